// round 1
// baseline (speedup 1.0000x reference)
#include <cuda_runtime.h>
#include <math_constants.h>

#define Bn 8
#define Cc 512
#define Nn 1024
#define NH 8
#define HD 64

// ---------------- scratch (device globals; no allocation) ----------------
__device__ float g_xn[Bn * Cc * Nn];        // 16 MB  group-normed x
__device__ float g_qkv[Bn * 3 * Cc * Nn];   // 48 MB  qkv activations
__device__ float g_att[Bn * Cc * Nn];       // 16 MB  attention output

// ---------------- GroupNorm ----------------
// one block per (b, group); 32 groups of 16 channels; 16384 elems per group
__global__ void gn_kernel(const float* __restrict__ x,
                          const float* __restrict__ gamma,
                          const float* __restrict__ beta) {
    int b = blockIdx.x >> 5;
    int g = blockIdx.x & 31;
    const float* xp = x + ((size_t)b * Cc + g * 16) * Nn;
    float* op = g_xn + ((size_t)b * Cc + g * 16) * Nn;

    float s = 0.f, s2 = 0.f;
    for (int i = threadIdx.x * 4; i < 16384; i += 1024) {
        float4 v = *(const float4*)(xp + i);
        s  += v.x + v.y + v.z + v.w;
        s2 += v.x * v.x + v.y * v.y + v.z * v.z + v.w * v.w;
    }
    for (int off = 16; off; off >>= 1) {
        s  += __shfl_xor_sync(0xffffffffu, s,  off);
        s2 += __shfl_xor_sync(0xffffffffu, s2, off);
    }
    __shared__ float sh[2][8];
    int w = threadIdx.x >> 5;
    if ((threadIdx.x & 31) == 0) { sh[0][w] = s; sh[1][w] = s2; }
    __syncthreads();
    if (threadIdx.x < 32) {
        s  = (threadIdx.x < 8) ? sh[0][threadIdx.x] : 0.f;
        s2 = (threadIdx.x < 8) ? sh[1][threadIdx.x] : 0.f;
        for (int off = 4; off; off >>= 1) {
            s  += __shfl_xor_sync(0xffffffffu, s,  off);
            s2 += __shfl_xor_sync(0xffffffffu, s2, off);
        }
        if (threadIdx.x == 0) { sh[0][0] = s; sh[1][0] = s2; }
    }
    __syncthreads();
    float mean = sh[0][0] * (1.f / 16384.f);
    float var  = sh[1][0] * (1.f / 16384.f) - mean * mean;
    float rstd = rsqrtf(var + 1e-5f);

    for (int i = threadIdx.x * 4; i < 16384; i += 1024) {
        float4 v = *(const float4*)(xp + i);
        int c = g * 16 + (i >> 10);
        float ga = gamma[c] * rstd;
        float be = beta[c] - mean * ga;
        v.x = v.x * ga + be; v.y = v.y * ga + be;
        v.z = v.z * ga + be; v.w = v.w * ga + be;
        *(float4*)(op + i) = v;
    }
}

// ---------------- 1x1 conv GEMM:  out[b,o,n] = bias[o] + sum_c W[o,c]*X[b,c,n] (+resid) ------
// 64x64 tile, BK=16, 256 threads, 4x4 per-thread blocking
__global__ void gemm1x1(const float* __restrict__ X, const float* __restrict__ W,
                        const float* __restrict__ bias, const float* __restrict__ resid,
                        float* __restrict__ out, int M) {
    const int K = Cc;
    int bn = blockIdx.x * 64;
    int bm = blockIdx.y * 64;
    int b  = blockIdx.z;

    __shared__ float Ws[16][65];   // Ws[c][o]  (pad 65 -> conflict-free transposed write)
    __shared__ float Xs[16][64];   // Xs[c][n]

    int tid = threadIdx.x;
    int tx = tid & 15, ty = tid >> 4;
    float acc[4][4] = {};

    const float* Xp = X + (size_t)b * K * Nn + bn;
    const float* Wp = W + (size_t)bm * K;

    for (int kk = 0; kk < K; kk += 16) {
        {   // W tile: 64 o x 16 c, float4 read, transposed scalar write
            int o  = tid >> 2;
            int c4 = (tid & 3) * 4;
            float4 wv = *(const float4*)(Wp + (size_t)o * K + kk + c4);
            Ws[c4 + 0][o] = wv.x; Ws[c4 + 1][o] = wv.y;
            Ws[c4 + 2][o] = wv.z; Ws[c4 + 3][o] = wv.w;
        }
        {   // X tile: 16 c x 64 n, direct float4
            int cr = tid >> 4;
            int n4 = (tid & 15) * 4;
            *(float4*)&Xs[cr][n4] = *(const float4*)(Xp + (size_t)(kk + cr) * Nn + n4);
        }
        __syncthreads();
        #pragma unroll
        for (int k = 0; k < 16; ++k) {
            float a0 = Ws[k][ty * 4 + 0], a1 = Ws[k][ty * 4 + 1];
            float a2 = Ws[k][ty * 4 + 2], a3 = Ws[k][ty * 4 + 3];
            float4 bv = *(const float4*)&Xs[k][tx * 4];
            acc[0][0] = fmaf(a0, bv.x, acc[0][0]); acc[0][1] = fmaf(a0, bv.y, acc[0][1]);
            acc[0][2] = fmaf(a0, bv.z, acc[0][2]); acc[0][3] = fmaf(a0, bv.w, acc[0][3]);
            acc[1][0] = fmaf(a1, bv.x, acc[1][0]); acc[1][1] = fmaf(a1, bv.y, acc[1][1]);
            acc[1][2] = fmaf(a1, bv.z, acc[1][2]); acc[1][3] = fmaf(a1, bv.w, acc[1][3]);
            acc[2][0] = fmaf(a2, bv.x, acc[2][0]); acc[2][1] = fmaf(a2, bv.y, acc[2][1]);
            acc[2][2] = fmaf(a2, bv.z, acc[2][2]); acc[2][3] = fmaf(a2, bv.w, acc[2][3]);
            acc[3][0] = fmaf(a3, bv.x, acc[3][0]); acc[3][1] = fmaf(a3, bv.y, acc[3][1]);
            acc[3][2] = fmaf(a3, bv.z, acc[3][2]); acc[3][3] = fmaf(a3, bv.w, acc[3][3]);
        }
        __syncthreads();
    }
    #pragma unroll
    for (int i = 0; i < 4; ++i) {
        int o = bm + ty * 4 + i;
        float bi = bias[o];
        size_t base = ((size_t)b * M + o) * Nn + bn + tx * 4;
        float4 r;
        r.x = acc[i][0] + bi; r.y = acc[i][1] + bi;
        r.z = acc[i][2] + bi; r.w = acc[i][3] + bi;
        if (resid) {
            float4 rv = *(const float4*)(resid + base);
            r.x += rv.x; r.y += rv.y; r.z += rv.z; r.w += rv.w;
        }
        *(float4*)(out + base) = r;
    }
}

// ---------------- flash attention, fp32, per (b, h, 64-query tile) ----------------
// q,k,v layout: g_qkv[b][o][n], o = {q:0..511, k:512..1023, v:1024..1535}, head h owns 64 dims
__global__ void attn_kernel() {
    const float* qp = g_qkv + ((size_t)blockIdx.z * 3 * Cc + blockIdx.y * HD) * Nn;
    const float* kp = qp + (size_t)Cc * Nn;
    const float* vp = qp + (size_t)2 * Cc * Nn;
    int qt = blockIdx.x * 64;

    extern __shared__ float sm[];
    float* Qs = sm;           // [64][64]  Qs[d][q]
    float* Ks = sm + 4096;    // [64][64]  Ks[d][m]
    float* Vs = sm + 8192;    // [64][64]  Vs[m][d]  (transposed)
    float* Ps = sm + 12288;   // [64][65]  Ps[q][m]  (pad -> conflict-free column read)

    int tid = threadIdx.x;
    int tx = tid & 15, ty = tid >> 4;

    // load Q tile (cooperative, coalesced)
    #pragma unroll
    for (int r = 0; r < 4; ++r) {
        int f = tid + r * 256;
        int d = f >> 4, c = (f & 15) * 4;
        *(float4*)&Qs[d * 64 + c] = *(const float4*)(qp + (size_t)d * Nn + qt + c);
    }

    float rmax[4], rsum[4], O[4][4];
    #pragma unroll
    for (int i = 0; i < 4; ++i) {
        rmax[i] = -CUDART_INF_F; rsum[i] = 0.f;
        #pragma unroll
        for (int j = 0; j < 4; ++j) O[i][j] = 0.f;
    }
    __syncthreads();

    for (int kt = 0; kt < Nn; kt += 64) {
        // load K tile [d][m] and V tile transposed [m][d]
        #pragma unroll
        for (int r = 0; r < 4; ++r) {
            int f = tid + r * 256;
            int d = f >> 4, m4 = (f & 15) * 4;
            *(float4*)&Ks[d * 64 + m4] = *(const float4*)(kp + (size_t)d * Nn + kt + m4);
            float4 v = *(const float4*)(vp + (size_t)d * Nn + kt + m4);
            Vs[(m4 + 0) * 64 + d] = v.x; Vs[(m4 + 1) * 64 + d] = v.y;
            Vs[(m4 + 2) * 64 + d] = v.z; Vs[(m4 + 3) * 64 + d] = v.w;
        }
        __syncthreads();

        // S tile = Q^T K (4x4 per thread)
        float s[4][4] = {};
        #pragma unroll
        for (int d = 0; d < 64; ++d) {
            float a0 = Qs[d * 64 + ty * 4 + 0], a1 = Qs[d * 64 + ty * 4 + 1];
            float a2 = Qs[d * 64 + ty * 4 + 2], a3 = Qs[d * 64 + ty * 4 + 3];
            float4 bv = *(const float4*)&Ks[d * 64 + tx * 4];
            s[0][0] = fmaf(a0, bv.x, s[0][0]); s[0][1] = fmaf(a0, bv.y, s[0][1]);
            s[0][2] = fmaf(a0, bv.z, s[0][2]); s[0][3] = fmaf(a0, bv.w, s[0][3]);
            s[1][0] = fmaf(a1, bv.x, s[1][0]); s[1][1] = fmaf(a1, bv.y, s[1][1]);
            s[1][2] = fmaf(a1, bv.z, s[1][2]); s[1][3] = fmaf(a1, bv.w, s[1][3]);
            s[2][0] = fmaf(a2, bv.x, s[2][0]); s[2][1] = fmaf(a2, bv.y, s[2][1]);
            s[2][2] = fmaf(a2, bv.z, s[2][2]); s[2][3] = fmaf(a2, bv.w, s[2][3]);
            s[3][0] = fmaf(a3, bv.x, s[3][0]); s[3][1] = fmaf(a3, bv.y, s[3][1]);
            s[3][2] = fmaf(a3, bv.z, s[3][2]); s[3][3] = fmaf(a3, bv.w, s[3][3]);
        }

        // online softmax update (row = query, reduce across tx within 16-lane group)
        #pragma unroll
        for (int i = 0; i < 4; ++i) {
            float tmax = -CUDART_INF_F;
            #pragma unroll
            for (int j = 0; j < 4; ++j) { s[i][j] *= 0.125f; tmax = fmaxf(tmax, s[i][j]); }
            #pragma unroll
            for (int off = 8; off; off >>= 1)
                tmax = fmaxf(tmax, __shfl_xor_sync(0xffffffffu, tmax, off));
            float newm = fmaxf(rmax[i], tmax);
            float corr = __expf(rmax[i] - newm);
            float tsum = 0.f;
            #pragma unroll
            for (int j = 0; j < 4; ++j) {
                s[i][j] = __expf(s[i][j] - newm);
                tsum += s[i][j];
            }
            #pragma unroll
            for (int off = 8; off; off >>= 1)
                tsum += __shfl_xor_sync(0xffffffffu, tsum, off);
            rsum[i] = rsum[i] * corr + tsum;
            rmax[i] = newm;
            #pragma unroll
            for (int j = 0; j < 4; ++j) O[i][j] *= corr;
            // stage P
            #pragma unroll
            for (int j = 0; j < 4; ++j)
                Ps[(ty * 4 + i) * 65 + tx * 4 + j] = s[i][j];
        }
        __syncthreads();

        // O[q][d] += P[q][m] * V[m][d]
        #pragma unroll
        for (int m = 0; m < 64; ++m) {
            float p0 = Ps[(ty * 4 + 0) * 65 + m];
            float p1 = Ps[(ty * 4 + 1) * 65 + m];
            float p2 = Ps[(ty * 4 + 2) * 65 + m];
            float p3 = Ps[(ty * 4 + 3) * 65 + m];
            float4 vv = *(const float4*)&Vs[m * 64 + tx * 4];
            O[0][0] = fmaf(p0, vv.x, O[0][0]); O[0][1] = fmaf(p0, vv.y, O[0][1]);
            O[0][2] = fmaf(p0, vv.z, O[0][2]); O[0][3] = fmaf(p0, vv.w, O[0][3]);
            O[1][0] = fmaf(p1, vv.x, O[1][0]); O[1][1] = fmaf(p1, vv.y, O[1][1]);
            O[1][2] = fmaf(p1, vv.z, O[1][2]); O[1][3] = fmaf(p1, vv.w, O[1][3]);
            O[2][0] = fmaf(p2, vv.x, O[2][0]); O[2][1] = fmaf(p2, vv.y, O[2][1]);
            O[2][2] = fmaf(p2, vv.z, O[2][2]); O[2][3] = fmaf(p2, vv.w, O[2][3]);
            O[3][0] = fmaf(p3, vv.x, O[3][0]); O[3][1] = fmaf(p3, vv.y, O[3][1]);
            O[3][2] = fmaf(p3, vv.z, O[3][2]); O[3][3] = fmaf(p3, vv.w, O[3][3]);
        }
        __syncthreads();   // protect K/V/P before next iteration overwrites
    }

    // normalize and stage transposed into Ks: Od[d][q], then coalesced store
    #pragma unroll
    for (int i = 0; i < 4; ++i) {
        float inv = 1.f / rsum[i];
        #pragma unroll
        for (int j = 0; j < 4; ++j)
            Ks[(tx * 4 + j) * 64 + ty * 4 + i] = O[i][j] * inv;
    }
    __syncthreads();
    float* ap = g_att + ((size_t)blockIdx.z * Cc + blockIdx.y * HD) * Nn + qt;
    #pragma unroll
    for (int r = 0; r < 4; ++r) {
        int f = tid + r * 256;
        int d = f >> 4, c = (f & 15) * 4;
        *(float4*)(ap + (size_t)d * Nn + c) = *(float4*)&Ks[d * 64 + c];
    }
}

// ---------------- launch ----------------
extern "C" void kernel_launch(void* const* d_in, const int* in_sizes, int n_in,
                              void* d_out, int out_size) {
    const float* x      = (const float*)d_in[0];
    const float* gamma  = (const float*)d_in[1];
    const float* beta   = (const float*)d_in[2];
    const float* w_qkv  = (const float*)d_in[3];
    const float* b_qkv  = (const float*)d_in[4];
    const float* w_proj = (const float*)d_in[5];
    const float* b_proj = (const float*)d_in[6];
    float* out = (float*)d_out;

    float *xn, *qkv, *att;
    cudaGetSymbolAddress((void**)&xn,  g_xn);
    cudaGetSymbolAddress((void**)&qkv, g_qkv);
    cudaGetSymbolAddress((void**)&att, g_att);

    const int attn_smem = (12288 + 64 * 65) * sizeof(float);   // 65792 B
    cudaFuncSetAttribute(attn_kernel, cudaFuncAttributeMaxDynamicSharedMemorySize, attn_smem);

    gn_kernel<<<256, 256>>>(x, gamma, beta);
    gemm1x1<<<dim3(16, 24, 8), 256>>>(xn, w_qkv, b_qkv, nullptr, qkv, 3 * Cc);
    attn_kernel<<<dim3(16, NH, Bn), 256, attn_smem>>>();
    gemm1x1<<<dim3(16, 8, 8), 256>>>(att, w_proj, b_proj, x, out, Cc);
}

// round 3
// speedup vs baseline: 1.0734x; 1.0734x over previous
#include <cuda_runtime.h>
#include <math_constants.h>
#include <cstdint>

#define Bn 8
#define Cc 512
#define Nn 1024
#define NH 8
#define HD 64

// ---------------- scratch (device globals; no allocation) ----------------
__device__ float g_xn[Bn * Cc * Nn];        // 16 MB  group-normed x  [b][c][n]
__device__ float g_qkv[Bn * 3 * Cc * Nn];   // 48 MB  qkv activations [b][o][n]
__device__ float g_att[Bn * Cc * Nn];       // 16 MB  attention out   [b][c][n]

// ---------------- helpers ----------------
__device__ __forceinline__ uint32_t f2tf32(float f) {
    uint32_t r;
    asm("cvt.rna.tf32.f32 %0, %1;" : "=r"(r) : "f"(f));
    return r;
}
__device__ __forceinline__ void mma_tf32(float* d, const uint32_t* a, const uint32_t* b) {
    asm volatile(
        "mma.sync.aligned.m16n8k8.row.col.f32.tf32.tf32.f32 "
        "{%0,%1,%2,%3}, {%4,%5,%6,%7}, {%8,%9}, {%0,%1,%2,%3};"
        : "+f"(d[0]), "+f"(d[1]), "+f"(d[2]), "+f"(d[3])
        : "r"(a[0]), "r"(a[1]), "r"(a[2]), "r"(a[3]), "r"(b[0]), "r"(b[1]));
}

// ---------------- GroupNorm (unchanged from round 1) ----------------
__global__ void gn_kernel(const float* __restrict__ x,
                          const float* __restrict__ gamma,
                          const float* __restrict__ beta) {
    int b = blockIdx.x >> 5;
    int g = blockIdx.x & 31;
    const float* xp = x + ((size_t)b * Cc + g * 16) * Nn;
    float* op = g_xn + ((size_t)b * Cc + g * 16) * Nn;

    float s = 0.f, s2 = 0.f;
    for (int i = threadIdx.x * 4; i < 16384; i += 1024) {
        float4 v = *(const float4*)(xp + i);
        s  += v.x + v.y + v.z + v.w;
        s2 += v.x * v.x + v.y * v.y + v.z * v.z + v.w * v.w;
    }
    for (int off = 16; off; off >>= 1) {
        s  += __shfl_xor_sync(0xffffffffu, s,  off);
        s2 += __shfl_xor_sync(0xffffffffu, s2, off);
    }
    __shared__ float sh[2][8];
    int w = threadIdx.x >> 5;
    if ((threadIdx.x & 31) == 0) { sh[0][w] = s; sh[1][w] = s2; }
    __syncthreads();
    if (threadIdx.x < 32) {
        s  = (threadIdx.x < 8) ? sh[0][threadIdx.x] : 0.f;
        s2 = (threadIdx.x < 8) ? sh[1][threadIdx.x] : 0.f;
        for (int off = 4; off; off >>= 1) {
            s  += __shfl_xor_sync(0xffffffffu, s,  off);
            s2 += __shfl_xor_sync(0xffffffffu, s2, off);
        }
        if (threadIdx.x == 0) { sh[0][0] = s; sh[1][0] = s2; }
    }
    __syncthreads();
    float mean = sh[0][0] * (1.f / 16384.f);
    float var  = sh[1][0] * (1.f / 16384.f) - mean * mean;
    float rstd = rsqrtf(var + 1e-5f);

    for (int i = threadIdx.x * 4; i < 16384; i += 1024) {
        float4 v = *(const float4*)(xp + i);
        int c = g * 16 + (i >> 10);
        float ga = gamma[c] * rstd;
        float be = beta[c] - mean * ga;
        v.x = v.x * ga + be; v.y = v.y * ga + be;
        v.z = v.z * ga + be; v.w = v.w * ga + be;
        *(float4*)(op + i) = v;
    }
}

// ---------------- tf32 mma.sync GEMM ----------------
// out[b,o,n] = bias[o] + sum_c W[o,c] * X[b,c,n]  (+resid)
// Block: 128(o) x 128(n), BK=32, 256 threads = 8 warps (4 m x 2 n), warp = 32x64.
// Smem staging is in FRAGMENT ORDER:
//  A-frag m16n8k8 tf32 (row):  a0=(r,c) a1=(r+8,c) a2=(r,c+4) a3=(r+8,c+4), r=lane>>2, c=lane&3
//  B-frag (col):               b0=(k,n) b1=(k+4,n),          k=lane&3,     n=lane>>2
// Smem (u32 units): A[buf] at buf*4096  ([4 kstep][8 mtile][32 lane][4 slot])
//                   B[buf] at 8192+buf*4096 ([4 kstep][16 ntile][32 lane][2 slot])
__global__ __launch_bounds__(256) void gemm_mma(
    const float* __restrict__ X, const float* __restrict__ W,
    const float* __restrict__ bias, const float* __restrict__ resid,
    float* __restrict__ out, int M)
{
    extern __shared__ uint32_t smemU[];
    const int tid = threadIdx.x;
    const int lane = tid & 31;
    const int wid = tid >> 5;
    const int wm = wid & 3;        // warp m index (0..3)
    const int wn = wid >> 2;       // warp n index (0..1)
    const int nb = blockIdx.x * 128;
    const int ob = blockIdx.y * 128;
    const int b  = blockIdx.z;

    const float* Wp = W + (size_t)ob * Cc;
    const float* Xp = X + (size_t)b * Cc * Nn + nb;

    float4 wreg[4], xreg[4];

    auto fetch = [&](int it) {
        int kk = it * 32;
        #pragma unroll
        for (int i = 0; i < 4; ++i) {
            int f = tid + i * 256;
            wreg[i] = *(const float4*)(Wp + (size_t)(f >> 3) * Cc + kk + (f & 7) * 4);
            xreg[i] = *(const float4*)(Xp + (size_t)(kk + (f >> 5)) * Nn + (f & 31) * 4);
        }
    };
    auto scatter = [&](int buf) {
        uint32_t* Afp = smemU + buf * 4096;
        uint32_t* Bfp = smemU + 8192 + buf * 4096;
        #pragma unroll
        for (int i = 0; i < 4; ++i) {
            int f = tid + i * 256;
            {   // W value (o_in, c_in = c4*4+j)
                int o_in = f >> 3, c4 = f & 7;
                int mtile = o_in >> 4, row_in = o_in & 15;
                int kstep = c4 >> 1;
                int slot  = (row_in >> 3) + (c4 & 1) * 2;
                int lbase = (row_in & 7) * 4;
                const float* wv = (const float*)&wreg[i];
                #pragma unroll
                for (int j = 0; j < 4; ++j)
                    Afp[((kstep * 8 + mtile) * 32 + lbase + j) * 4 + slot] = f2tf32(wv[j]);
            }
            {   // X value (c_in, n = n4*4+j)
                int c_in = f >> 5, n4 = f & 31;
                int kstep = c_in >> 3, c8 = c_in & 7;
                int ntile = n4 >> 1;
                int slot  = c8 >> 2;
                int ncol0 = (n4 & 1) * 4;
                const float* xv = (const float*)&xreg[i];
                #pragma unroll
                for (int j = 0; j < 4; ++j)
                    Bfp[((kstep * 16 + ntile) * 32 + (ncol0 + j) * 4 + (c8 & 3)) * 2 + slot]
                        = f2tf32(xv[j]);
            }
        }
    };

    float acc[2][8][4];
    #pragma unroll
    for (int mt = 0; mt < 2; ++mt)
        #pragma unroll
        for (int nt = 0; nt < 8; ++nt)
            #pragma unroll
            for (int r = 0; r < 4; ++r) acc[mt][nt][r] = 0.f;

    // pipeline prologue
    fetch(0); scatter(0); fetch(1);
    __syncthreads();

    const int NIT = Cc / 32;   // 16
    for (int it = 0; it < NIT; ++it) {
        int cur = it & 1;
        if (it + 1 < NIT) scatter(1 - cur);
        if (it + 2 < NIT) fetch(it + 2);

        const uint32_t* ab = smemU + cur * 4096;
        const uint32_t* bb = smemU + 8192 + cur * 4096;
        #pragma unroll
        for (int ks = 0; ks < 4; ++ks) {
            uint4 afr[2];
            uint2 bfr[8];
            #pragma unroll
            for (int mt = 0; mt < 2; ++mt)
                afr[mt] = *(const uint4*)(ab + ((ks * 8 + wm * 2 + mt) * 32 + lane) * 4);
            #pragma unroll
            for (int nt = 0; nt < 8; ++nt)
                bfr[nt] = *(const uint2*)(bb + ((ks * 16 + wn * 8 + nt) * 32 + lane) * 2);
            #pragma unroll
            for (int mt = 0; mt < 2; ++mt)
                #pragma unroll
                for (int nt = 0; nt < 8; ++nt)
                    mma_tf32(acc[mt][nt], (const uint32_t*)&afr[mt], (const uint32_t*)&bfr[nt]);
        }
        __syncthreads();
    }

    // epilogue: D frag c0=(r, c*2) c1=(r, c*2+1) c2=(r+8, c*2) c3=(r+8, c*2+1)
    #pragma unroll
    for (int mt = 0; mt < 2; ++mt) {
        int o = ob + wm * 32 + mt * 16 + (lane >> 2);
        float b0 = __ldg(bias + o);
        float b1 = __ldg(bias + o + 8);
        #pragma unroll
        for (int nt = 0; nt < 8; ++nt) {
            int n = nb + wn * 64 + nt * 8 + (lane & 3) * 2;
            size_t i0 = ((size_t)b * M + o) * Nn + n;
            size_t i1 = i0 + (size_t)8 * Nn;
            float2 v0 = make_float2(acc[mt][nt][0] + b0, acc[mt][nt][1] + b0);
            float2 v1 = make_float2(acc[mt][nt][2] + b1, acc[mt][nt][3] + b1);
            if (resid) {
                float2 r0 = *(const float2*)(resid + i0);
                float2 r1 = *(const float2*)(resid + i1);
                v0.x += r0.x; v0.y += r0.y;
                v1.x += r1.x; v1.y += r1.y;
            }
            *(float2*)(out + i0) = v0;
            *(float2*)(out + i1) = v1;
        }
    }
}

// ---------------- flash attention, fp32 SIMT (unchanged from round 1) ----------------
__global__ void attn_kernel() {
    const float* qp = g_qkv + ((size_t)blockIdx.z * 3 * Cc + blockIdx.y * HD) * Nn;
    const float* kp = qp + (size_t)Cc * Nn;
    const float* vp = qp + (size_t)2 * Cc * Nn;
    int qt = blockIdx.x * 64;

    extern __shared__ float sm[];
    float* Qs = sm;           // [64][64]  Qs[d][q]
    float* Ks = sm + 4096;    // [64][64]  Ks[d][m]
    float* Vs = sm + 8192;    // [64][64]  Vs[m][d]  (transposed)
    float* Ps = sm + 12288;   // [64][65]  Ps[q][m]

    int tid = threadIdx.x;
    int tx = tid & 15, ty = tid >> 4;

    #pragma unroll
    for (int r = 0; r < 4; ++r) {
        int f = tid + r * 256;
        int d = f >> 4, c = (f & 15) * 4;
        *(float4*)&Qs[d * 64 + c] = *(const float4*)(qp + (size_t)d * Nn + qt + c);
    }

    float rmax[4], rsum[4], O[4][4];
    #pragma unroll
    for (int i = 0; i < 4; ++i) {
        rmax[i] = -CUDART_INF_F; rsum[i] = 0.f;
        #pragma unroll
        for (int j = 0; j < 4; ++j) O[i][j] = 0.f;
    }
    __syncthreads();

    for (int kt = 0; kt < Nn; kt += 64) {
        #pragma unroll
        for (int r = 0; r < 4; ++r) {
            int f = tid + r * 256;
            int d = f >> 4, m4 = (f & 15) * 4;
            *(float4*)&Ks[d * 64 + m4] = *(const float4*)(kp + (size_t)d * Nn + kt + m4);
            float4 v = *(const float4*)(vp + (size_t)d * Nn + kt + m4);
            Vs[(m4 + 0) * 64 + d] = v.x; Vs[(m4 + 1) * 64 + d] = v.y;
            Vs[(m4 + 2) * 64 + d] = v.z; Vs[(m4 + 3) * 64 + d] = v.w;
        }
        __syncthreads();

        float s[4][4] = {};
        #pragma unroll
        for (int d = 0; d < 64; ++d) {
            float a0 = Qs[d * 64 + ty * 4 + 0], a1 = Qs[d * 64 + ty * 4 + 1];
            float a2 = Qs[d * 64 + ty * 4 + 2], a3 = Qs[d * 64 + ty * 4 + 3];
            float4 bv = *(const float4*)&Ks[d * 64 + tx * 4];
            s[0][0] = fmaf(a0, bv.x, s[0][0]); s[0][1] = fmaf(a0, bv.y, s[0][1]);
            s[0][2] = fmaf(a0, bv.z, s[0][2]); s[0][3] = fmaf(a0, bv.w, s[0][3]);
            s[1][0] = fmaf(a1, bv.x, s[1][0]); s[1][1] = fmaf(a1, bv.y, s[1][1]);
            s[1][2] = fmaf(a1, bv.z, s[1][2]); s[1][3] = fmaf(a1, bv.w, s[1][3]);
            s[2][0] = fmaf(a2, bv.x, s[2][0]); s[2][1] = fmaf(a2, bv.y, s[2][1]);
            s[2][2] = fmaf(a2, bv.z, s[2][2]); s[2][3] = fmaf(a2, bv.w, s[2][3]);
            s[3][0] = fmaf(a3, bv.x, s[3][0]); s[3][1] = fmaf(a3, bv.y, s[3][1]);
            s[3][2] = fmaf(a3, bv.z, s[3][2]); s[3][3] = fmaf(a3, bv.w, s[3][3]);
        }

        #pragma unroll
        for (int i = 0; i < 4; ++i) {
            float tmax = -CUDART_INF_F;
            #pragma unroll
            for (int j = 0; j < 4; ++j) { s[i][j] *= 0.125f; tmax = fmaxf(tmax, s[i][j]); }
            #pragma unroll
            for (int off = 8; off; off >>= 1)
                tmax = fmaxf(tmax, __shfl_xor_sync(0xffffffffu, tmax, off));
            float newm = fmaxf(rmax[i], tmax);
            float corr = __expf(rmax[i] - newm);
            float tsum = 0.f;
            #pragma unroll
            for (int j = 0; j < 4; ++j) {
                s[i][j] = __expf(s[i][j] - newm);
                tsum += s[i][j];
            }
            #pragma unroll
            for (int off = 8; off; off >>= 1)
                tsum += __shfl_xor_sync(0xffffffffu, tsum, off);
            rsum[i] = rsum[i] * corr + tsum;
            rmax[i] = newm;
            #pragma unroll
            for (int j = 0; j < 4; ++j) O[i][j] *= corr;
            #pragma unroll
            for (int j = 0; j < 4; ++j)
                Ps[(ty * 4 + i) * 65 + tx * 4 + j] = s[i][j];
        }
        __syncthreads();

        #pragma unroll
        for (int m = 0; m < 64; ++m) {
            float p0 = Ps[(ty * 4 + 0) * 65 + m];
            float p1 = Ps[(ty * 4 + 1) * 65 + m];
            float p2 = Ps[(ty * 4 + 2) * 65 + m];
            float p3 = Ps[(ty * 4 + 3) * 65 + m];
            float4 vv = *(const float4*)&Vs[m * 64 + tx * 4];
            O[0][0] = fmaf(p0, vv.x, O[0][0]); O[0][1] = fmaf(p0, vv.y, O[0][1]);
            O[0][2] = fmaf(p0, vv.z, O[0][2]); O[0][3] = fmaf(p0, vv.w, O[0][3]);
            O[1][0] = fmaf(p1, vv.x, O[1][0]); O[1][1] = fmaf(p1, vv.y, O[1][1]);
            O[1][2] = fmaf(p1, vv.z, O[1][2]); O[1][3] = fmaf(p1, vv.w, O[1][3]);
            O[2][0] = fmaf(p2, vv.x, O[2][0]); O[2][1] = fmaf(p2, vv.y, O[2][1]);
            O[2][2] = fmaf(p2, vv.z, O[2][2]); O[2][3] = fmaf(p2, vv.w, O[2][3]);
            O[3][0] = fmaf(p3, vv.x, O[3][0]); O[3][1] = fmaf(p3, vv.y, O[3][1]);
            O[3][2] = fmaf(p3, vv.z, O[3][2]); O[3][3] = fmaf(p3, vv.w, O[3][3]);
        }
        __syncthreads();
    }

    #pragma unroll
    for (int i = 0; i < 4; ++i) {
        float inv = 1.f / rsum[i];
        #pragma unroll
        for (int j = 0; j < 4; ++j)
            Ks[(tx * 4 + j) * 64 + ty * 4 + i] = O[i][j] * inv;
    }
    __syncthreads();
    float* ap = g_att + ((size_t)blockIdx.z * Cc + blockIdx.y * HD) * Nn + qt;
    #pragma unroll
    for (int r = 0; r < 4; ++r) {
        int f = tid + r * 256;
        int d = f >> 4, c = (f & 15) * 4;
        *(float4*)(ap + (size_t)d * Nn + c) = *(float4*)&Ks[d * 64 + c];
    }
}

// ---------------- launch ----------------
extern "C" void kernel_launch(void* const* d_in, const int* in_sizes, int n_in,
                              void* d_out, int out_size) {
    const float* x      = (const float*)d_in[0];
    const float* gamma  = (const float*)d_in[1];
    const float* beta   = (const float*)d_in[2];
    const float* w_qkv  = (const float*)d_in[3];
    const float* b_qkv  = (const float*)d_in[4];
    const float* w_proj = (const float*)d_in[5];
    const float* b_proj = (const float*)d_in[6];
    float* out = (float*)d_out;

    float *xn, *qkv, *att;
    cudaGetSymbolAddress((void**)&xn,  g_xn);
    cudaGetSymbolAddress((void**)&qkv, g_qkv);
    cudaGetSymbolAddress((void**)&att, g_att);

    const int gemm_smem = 64 * 1024;
    const int attn_smem = (12288 + 64 * 65) * sizeof(float);   // 65792 B
    cudaFuncSetAttribute(gemm_mma,    cudaFuncAttributeMaxDynamicSharedMemorySize, gemm_smem);
    cudaFuncSetAttribute(attn_kernel, cudaFuncAttributeMaxDynamicSharedMemorySize, attn_smem);

    gn_kernel<<<256, 256>>>(x, gamma, beta);
    gemm_mma<<<dim3(8, 12, 8), 256, gemm_smem>>>(xn, w_qkv, b_qkv, nullptr, qkv, 3 * Cc);
    attn_kernel<<<dim3(16, NH, Bn), 256, attn_smem>>>();
    gemm_mma<<<dim3(8, 4, 8), 256, gemm_smem>>>(att, w_proj, b_proj, x, out, Cc);
}

// round 4
// speedup vs baseline: 1.3650x; 1.2717x over previous
#include <cuda_runtime.h>
#include <math_constants.h>
#include <cstdint>

#define Bn 8
#define Cc 512
#define Nn 1024
#define NH 8
#define HD 64

// ---------------- scratch (device globals; no allocation) ----------------
__device__ float g_xn[Bn * Cc * Nn];        // 16 MB  group-normed x  [b][c][n]
__device__ float g_qkv[Bn * 3 * Cc * Nn];   // 48 MB  qkv activations [b][o][n]
__device__ float g_att[Bn * Cc * Nn];       // 16 MB  attention out   [b][c][n]

// ---------------- helpers ----------------
__device__ __forceinline__ uint32_t f2tf32(float f) {
    uint32_t r;
    asm("cvt.rna.tf32.f32 %0, %1;" : "=r"(r) : "f"(f));
    return r;
}
__device__ __forceinline__ void mma_tf32(float* d, const uint32_t* a, const uint32_t* b) {
    asm volatile(
        "mma.sync.aligned.m16n8k8.row.col.f32.tf32.tf32.f32 "
        "{%0,%1,%2,%3}, {%4,%5,%6,%7}, {%8,%9}, {%0,%1,%2,%3};"
        : "+f"(d[0]), "+f"(d[1]), "+f"(d[2]), "+f"(d[3])
        : "r"(a[0]), "r"(a[1]), "r"(a[2]), "r"(a[3]), "r"(b[0]), "r"(b[1]));
}

// fast 2^t, t <= ~1, pure FMA/ALU (no MUFU).  rel err ~2.4e-6
__device__ __forceinline__ float fexp2(float t) {
    t = fmaxf(t, -120.f);
    int ei = __float2int_rn(t);
    float f = t - (float)ei;                  // [-0.5, 0.5]
    float g = f * 0.6931471805599453f;        // ln2 * f
    float p = 8.3333337e-3f;                  // 1/120
    p = fmaf(p, g, 4.1666668e-2f);            // 1/24
    p = fmaf(p, g, 0.16666667f);              // 1/6
    p = fmaf(p, g, 0.5f);
    p = fmaf(p, g, 1.0f);
    p = fmaf(p, g, 1.0f);
    return p * __int_as_float((ei + 127) << 23);
}

// ---------------- GroupNorm (unchanged) ----------------
__global__ void gn_kernel(const float* __restrict__ x,
                          const float* __restrict__ gamma,
                          const float* __restrict__ beta) {
    int b = blockIdx.x >> 5;
    int g = blockIdx.x & 31;
    const float* xp = x + ((size_t)b * Cc + g * 16) * Nn;
    float* op = g_xn + ((size_t)b * Cc + g * 16) * Nn;

    float s = 0.f, s2 = 0.f;
    for (int i = threadIdx.x * 4; i < 16384; i += 1024) {
        float4 v = *(const float4*)(xp + i);
        s  += v.x + v.y + v.z + v.w;
        s2 += v.x * v.x + v.y * v.y + v.z * v.z + v.w * v.w;
    }
    for (int off = 16; off; off >>= 1) {
        s  += __shfl_xor_sync(0xffffffffu, s,  off);
        s2 += __shfl_xor_sync(0xffffffffu, s2, off);
    }
    __shared__ float sh[2][8];
    int w = threadIdx.x >> 5;
    if ((threadIdx.x & 31) == 0) { sh[0][w] = s; sh[1][w] = s2; }
    __syncthreads();
    if (threadIdx.x < 32) {
        s  = (threadIdx.x < 8) ? sh[0][threadIdx.x] : 0.f;
        s2 = (threadIdx.x < 8) ? sh[1][threadIdx.x] : 0.f;
        for (int off = 4; off; off >>= 1) {
            s  += __shfl_xor_sync(0xffffffffu, s,  off);
            s2 += __shfl_xor_sync(0xffffffffu, s2, off);
        }
        if (threadIdx.x == 0) { sh[0][0] = s; sh[1][0] = s2; }
    }
    __syncthreads();
    float mean = sh[0][0] * (1.f / 16384.f);
    float var  = sh[1][0] * (1.f / 16384.f) - mean * mean;
    float rstd = rsqrtf(var + 1e-5f);

    for (int i = threadIdx.x * 4; i < 16384; i += 1024) {
        float4 v = *(const float4*)(xp + i);
        int c = g * 16 + (i >> 10);
        float ga = gamma[c] * rstd;
        float be = beta[c] - mean * ga;
        v.x = v.x * ga + be; v.y = v.y * ga + be;
        v.z = v.z * ga + be; v.w = v.w * ga + be;
        *(float4*)(op + i) = v;
    }
}

// ---------------- tf32 mma.sync GEMM (STS.128 fragment staging) ----------------
// out[b,o,n] = bias[o] + sum_c W[o,c] * X[b,c,n]  (+resid)
// Block 128(o) x 128(n), BK=32, 8 warps (4m x 2n), warp = 32x64.
// A planes (u32): buf*4096 + ((kstep*8 + mtile)*4 + reg)*32 + lane
//   value (o,c): reg = (row>=8) | ((c8>=4)<<1), lane = (row&7)*4 + (c&3)
//   thread's 4 consecutive c -> 4 consecutive lanes -> STS.128
// B planes (u32): BB + buf*4608 + kstep*1152 + ntile*72 + reg*32 + k2*8 + n_in
//   ([k2][n] inside plane; thread's 4 consecutive n -> STS.128)
//   load perm: lane -> word (lane&3)*8 + (lane>>2)  (all banks distinct)
#define BB 8192
__global__ __launch_bounds__(256) void gemm_mma(
    const float* __restrict__ X, const float* __restrict__ W,
    const float* __restrict__ bias, const float* __restrict__ resid,
    float* __restrict__ out, int M)
{
    extern __shared__ uint32_t smemU[];
    const int tid = threadIdx.x;
    const int lane = tid & 31;
    const int wid = tid >> 5;
    const int wm = wid & 3;
    const int wn = wid >> 2;
    const int nb = blockIdx.x * 128;
    const int ob = blockIdx.y * 128;
    const int b  = blockIdx.z;

    const float* Wp = W + (size_t)ob * Cc;
    const float* Xp = X + (size_t)b * Cc * Nn + nb;

    float4 wreg[4], xreg[4];

    auto fetch = [&](int it) {
        int kk = it * 32;
        #pragma unroll
        for (int i = 0; i < 4; ++i) {
            int f = tid + i * 256;
            wreg[i] = *(const float4*)(Wp + (size_t)(f >> 3) * Cc + kk + (f & 7) * 4);
            xreg[i] = *(const float4*)(Xp + (size_t)(kk + (f >> 5)) * Nn + (f & 31) * 4);
        }
    };
    auto scatter = [&](int buf) {
        #pragma unroll
        for (int i = 0; i < 4; ++i) {
            int f = tid + i * 256;
            {   // A: W[o][c4*4 + 0..3]
                int o  = f >> 3, c4 = f & 7;
                int kstep = c4 >> 1;
                int mtile = o >> 4;
                int reg   = ((o >> 3) & 1) | ((c4 & 1) << 1);
                int addr  = buf * 4096 + ((kstep * 8 + mtile) * 4 + reg) * 32 + (o & 7) * 4;
                const float* wv = (const float*)&wreg[i];
                uint4 v = make_uint4(f2tf32(wv[0]), f2tf32(wv[1]), f2tf32(wv[2]), f2tf32(wv[3]));
                *(uint4*)(smemU + addr) = v;
            }
            {   // B: X[c_in][n4*4 + 0..3]
                int c_in = f >> 5, n4 = f & 31;
                int kstep = c_in >> 3, c8 = c_in & 7;
                int reg = c8 >> 2, k2 = c8 & 3;
                int ntile = n4 >> 1, n_in0 = (n4 & 1) * 4;
                int addr = BB + buf * 4608 + kstep * 1152 + ntile * 72 + reg * 32 + k2 * 8 + n_in0;
                const float* xv = (const float*)&xreg[i];
                uint4 v = make_uint4(f2tf32(xv[0]), f2tf32(xv[1]), f2tf32(xv[2]), f2tf32(xv[3]));
                *(uint4*)(smemU + addr) = v;
            }
        }
    };

    float acc[2][8][4];
    #pragma unroll
    for (int mt = 0; mt < 2; ++mt)
        #pragma unroll
        for (int nt = 0; nt < 8; ++nt)
            #pragma unroll
            for (int r = 0; r < 4; ++r) acc[mt][nt][r] = 0.f;

    fetch(0); scatter(0); fetch(1);
    __syncthreads();

    const int bperm = (lane & 3) * 8 + (lane >> 2);   // B load permutation
    const int NIT = Cc / 32;   // 16
    for (int it = 0; it < NIT; ++it) {
        int cur = it & 1;
        if (it + 1 < NIT) scatter(1 - cur);
        if (it + 2 < NIT) fetch(it + 2);

        const uint32_t* ab = smemU + cur * 4096;
        const uint32_t* bb = smemU + BB + cur * 4608;
        #pragma unroll
        for (int ks = 0; ks < 4; ++ks) {
            uint32_t afr[2][4];
            uint32_t bfr[8][2];
            #pragma unroll
            for (int mt = 0; mt < 2; ++mt)
                #pragma unroll
                for (int r = 0; r < 4; ++r)
                    afr[mt][r] = ab[((ks * 8 + wm * 2 + mt) * 4 + r) * 32 + lane];
            #pragma unroll
            for (int nt = 0; nt < 8; ++nt)
                #pragma unroll
                for (int r = 0; r < 2; ++r)
                    bfr[nt][r] = bb[ks * 1152 + (wn * 8 + nt) * 72 + r * 32 + bperm];
            #pragma unroll
            for (int mt = 0; mt < 2; ++mt)
                #pragma unroll
                for (int nt = 0; nt < 8; ++nt)
                    mma_tf32(acc[mt][nt], afr[mt], bfr[nt]);
        }
        __syncthreads();
    }

    // epilogue: D frag c0=(r, c*2) c1=(r, c*2+1) c2=(r+8, c*2) c3=(r+8, c*2+1)
    #pragma unroll
    for (int mt = 0; mt < 2; ++mt) {
        int o = ob + wm * 32 + mt * 16 + (lane >> 2);
        float b0 = __ldg(bias + o);
        float b1 = __ldg(bias + o + 8);
        #pragma unroll
        for (int nt = 0; nt < 8; ++nt) {
            int n = nb + wn * 64 + nt * 8 + (lane & 3) * 2;
            size_t i0 = ((size_t)b * M + o) * Nn + n;
            size_t i1 = i0 + (size_t)8 * Nn;
            float2 v0 = make_float2(acc[mt][nt][0] + b0, acc[mt][nt][1] + b0);
            float2 v1 = make_float2(acc[mt][nt][2] + b1, acc[mt][nt][3] + b1);
            if (resid) {
                float2 r0 = *(const float2*)(resid + i0);
                float2 r1 = *(const float2*)(resid + i1);
                v0.x += r0.x; v0.y += r0.y;
                v1.x += r1.x; v1.y += r1.y;
            }
            *(float2*)(out + i0) = v0;
            *(float2*)(out + i1) = v1;
        }
    }
}

// ---------------- flash attention, fp32 SIMT + FMA-exp (log2 domain) ----------------
__global__ void attn_kernel() {
    const float* qp = g_qkv + ((size_t)blockIdx.z * 3 * Cc + blockIdx.y * HD) * Nn;
    const float* kp = qp + (size_t)Cc * Nn;
    const float* vp = qp + (size_t)2 * Cc * Nn;
    int qt = blockIdx.x * 64;

    extern __shared__ float sm[];
    float* Qs = sm;           // [64][64]  Qs[d][q]
    float* Ks = sm + 4096;    // [64][64]  Ks[d][m]
    float* Vs = sm + 8192;    // [64][64]  Vs[m][d]  (transposed)
    float* Ps = sm + 12288;   // [64][65]  Ps[q][m]

    int tid = threadIdx.x;
    int tx = tid & 15, ty = tid >> 4;

    #pragma unroll
    for (int r = 0; r < 4; ++r) {
        int f = tid + r * 256;
        int d = f >> 4, c = (f & 15) * 4;
        *(float4*)&Qs[d * 64 + c] = *(const float4*)(qp + (size_t)d * Nn + qt + c);
    }

    float rmax[4], rsum[4], O[4][4];
    #pragma unroll
    for (int i = 0; i < 4; ++i) {
        rmax[i] = -CUDART_INF_F; rsum[i] = 0.f;
        #pragma unroll
        for (int j = 0; j < 4; ++j) O[i][j] = 0.f;
    }
    __syncthreads();

    // scale = (1/sqrt(64)) * log2(e): softmax tracked in base-2 domain
    const float SCL = 0.125f * 1.4426950408889634f;

    for (int kt = 0; kt < Nn; kt += 64) {
        #pragma unroll
        for (int r = 0; r < 4; ++r) {
            int f = tid + r * 256;
            int d = f >> 4, m4 = (f & 15) * 4;
            *(float4*)&Ks[d * 64 + m4] = *(const float4*)(kp + (size_t)d * Nn + kt + m4);
            float4 v = *(const float4*)(vp + (size_t)d * Nn + kt + m4);
            Vs[(m4 + 0) * 64 + d] = v.x; Vs[(m4 + 1) * 64 + d] = v.y;
            Vs[(m4 + 2) * 64 + d] = v.z; Vs[(m4 + 3) * 64 + d] = v.w;
        }
        __syncthreads();

        float s[4][4] = {};
        #pragma unroll
        for (int d = 0; d < 64; ++d) {
            float a0 = Qs[d * 64 + ty * 4 + 0], a1 = Qs[d * 64 + ty * 4 + 1];
            float a2 = Qs[d * 64 + ty * 4 + 2], a3 = Qs[d * 64 + ty * 4 + 3];
            float4 bv = *(const float4*)&Ks[d * 64 + tx * 4];
            s[0][0] = fmaf(a0, bv.x, s[0][0]); s[0][1] = fmaf(a0, bv.y, s[0][1]);
            s[0][2] = fmaf(a0, bv.z, s[0][2]); s[0][3] = fmaf(a0, bv.w, s[0][3]);
            s[1][0] = fmaf(a1, bv.x, s[1][0]); s[1][1] = fmaf(a1, bv.y, s[1][1]);
            s[1][2] = fmaf(a1, bv.z, s[1][2]); s[1][3] = fmaf(a1, bv.w, s[1][3]);
            s[2][0] = fmaf(a2, bv.x, s[2][0]); s[2][1] = fmaf(a2, bv.y, s[2][1]);
            s[2][2] = fmaf(a2, bv.z, s[2][2]); s[2][3] = fmaf(a2, bv.w, s[2][3]);
            s[3][0] = fmaf(a3, bv.x, s[3][0]); s[3][1] = fmaf(a3, bv.y, s[3][1]);
            s[3][2] = fmaf(a3, bv.z, s[3][2]); s[3][3] = fmaf(a3, bv.w, s[3][3]);
        }

        #pragma unroll
        for (int i = 0; i < 4; ++i) {
            float tmax = -CUDART_INF_F;
            #pragma unroll
            for (int j = 0; j < 4; ++j) { s[i][j] *= SCL; tmax = fmaxf(tmax, s[i][j]); }
            #pragma unroll
            for (int off = 8; off; off >>= 1)
                tmax = fmaxf(tmax, __shfl_xor_sync(0xffffffffu, tmax, off));
            float newm = fmaxf(rmax[i], tmax);
            float corr = fexp2(rmax[i] - newm);
            float tsum = 0.f;
            #pragma unroll
            for (int j = 0; j < 4; ++j) {
                s[i][j] = fexp2(s[i][j] - newm);
                tsum += s[i][j];
            }
            #pragma unroll
            for (int off = 8; off; off >>= 1)
                tsum += __shfl_xor_sync(0xffffffffu, tsum, off);
            rsum[i] = rsum[i] * corr + tsum;
            rmax[i] = newm;
            #pragma unroll
            for (int j = 0; j < 4; ++j) O[i][j] *= corr;
            #pragma unroll
            for (int j = 0; j < 4; ++j)
                Ps[(ty * 4 + i) * 65 + tx * 4 + j] = s[i][j];
        }
        __syncthreads();

        #pragma unroll
        for (int m = 0; m < 64; ++m) {
            float p0 = Ps[(ty * 4 + 0) * 65 + m];
            float p1 = Ps[(ty * 4 + 1) * 65 + m];
            float p2 = Ps[(ty * 4 + 2) * 65 + m];
            float p3 = Ps[(ty * 4 + 3) * 65 + m];
            float4 vv = *(const float4*)&Vs[m * 64 + tx * 4];
            O[0][0] = fmaf(p0, vv.x, O[0][0]); O[0][1] = fmaf(p0, vv.y, O[0][1]);
            O[0][2] = fmaf(p0, vv.z, O[0][2]); O[0][3] = fmaf(p0, vv.w, O[0][3]);
            O[1][0] = fmaf(p1, vv.x, O[1][0]); O[1][1] = fmaf(p1, vv.y, O[1][1]);
            O[1][2] = fmaf(p1, vv.z, O[1][2]); O[1][3] = fmaf(p1, vv.w, O[1][3]);
            O[2][0] = fmaf(p2, vv.x, O[2][0]); O[2][1] = fmaf(p2, vv.y, O[2][1]);
            O[2][2] = fmaf(p2, vv.z, O[2][2]); O[2][3] = fmaf(p2, vv.w, O[2][3]);
            O[3][0] = fmaf(p3, vv.x, O[3][0]); O[3][1] = fmaf(p3, vv.y, O[3][1]);
            O[3][2] = fmaf(p3, vv.z, O[3][2]); O[3][3] = fmaf(p3, vv.w, O[3][3]);
        }
        __syncthreads();
    }

    #pragma unroll
    for (int i = 0; i < 4; ++i) {
        float inv = 1.f / rsum[i];
        #pragma unroll
        for (int j = 0; j < 4; ++j)
            Ks[(tx * 4 + j) * 64 + ty * 4 + i] = O[i][j] * inv;
    }
    __syncthreads();
    float* ap = g_att + ((size_t)blockIdx.z * Cc + blockIdx.y * HD) * Nn + qt;
    #pragma unroll
    for (int r = 0; r < 4; ++r) {
        int f = tid + r * 256;
        int d = f >> 4, c = (f & 15) * 4;
        *(float4*)(ap + (size_t)d * Nn + c) = *(float4*)&Ks[d * 64 + c];
    }
}

// ---------------- launch ----------------
extern "C" void kernel_launch(void* const* d_in, const int* in_sizes, int n_in,
                              void* d_out, int out_size) {
    const float* x      = (const float*)d_in[0];
    const float* gamma  = (const float*)d_in[1];
    const float* beta   = (const float*)d_in[2];
    const float* w_qkv  = (const float*)d_in[3];
    const float* b_qkv  = (const float*)d_in[4];
    const float* w_proj = (const float*)d_in[5];
    const float* b_proj = (const float*)d_in[6];
    float* out = (float*)d_out;

    float *xn, *qkv, *att;
    cudaGetSymbolAddress((void**)&xn,  g_xn);
    cudaGetSymbolAddress((void**)&qkv, g_qkv);
    cudaGetSymbolAddress((void**)&att, g_att);

    const int gemm_smem = (8192 + 9216) * 4;                   // 69632 B
    const int attn_smem = (12288 + 64 * 65) * sizeof(float);   // 65792 B
    cudaFuncSetAttribute(gemm_mma,    cudaFuncAttributeMaxDynamicSharedMemorySize, gemm_smem);
    cudaFuncSetAttribute(attn_kernel, cudaFuncAttributeMaxDynamicSharedMemorySize, attn_smem);

    gn_kernel<<<256, 256>>>(x, gamma, beta);
    gemm_mma<<<dim3(8, 12, 8), 256, gemm_smem>>>(xn, w_qkv, b_qkv, nullptr, qkv, 3 * Cc);
    attn_kernel<<<dim3(16, NH, Bn), 256, attn_smem>>>();
    gemm_mma<<<dim3(8, 4, 8), 256, gemm_smem>>>(att, w_proj, b_proj, x, out, Cc);
}

// round 5
// speedup vs baseline: 2.4655x; 1.8063x over previous
#include <cuda_runtime.h>
#include <math_constants.h>
#include <cstdint>

#define Bn 8
#define Cc 512
#define Nn 1024
#define NH 8
#define HD 64

// ---------------- scratch (device globals; no allocation) ----------------
__device__ float g_xn[Bn * Cc * Nn];        // 16 MB  group-normed x  [b][c][n]
__device__ float g_qkv[Bn * 3 * Cc * Nn];   // 48 MB  qkv activations [b][o][n]
__device__ float g_att[Bn * Cc * Nn];       // 16 MB  attention out   [b][c][n]

// ---------------- helpers ----------------
__device__ __forceinline__ uint32_t f2tf32(float f) {
    uint32_t r;
    asm("cvt.rna.tf32.f32 %0, %1;" : "=r"(r) : "f"(f));
    return r;
}
__device__ __forceinline__ void mma_tf32(float* d, const uint32_t* a, const uint32_t* b) {
    asm volatile(
        "mma.sync.aligned.m16n8k8.row.col.f32.tf32.tf32.f32 "
        "{%0,%1,%2,%3}, {%4,%5,%6,%7}, {%8,%9}, {%0,%1,%2,%3};"
        : "+f"(d[0]), "+f"(d[1]), "+f"(d[2]), "+f"(d[3])
        : "r"(a[0]), "r"(a[1]), "r"(a[2]), "r"(a[3]), "r"(b[0]), "r"(b[1]));
}

// fast 2^t, pure FMA/ALU.  rel err ~2.4e-6
__device__ __forceinline__ float fexp2(float t) {
    t = fmaxf(t, -120.f);
    int ei = __float2int_rn(t);
    float f = t - (float)ei;
    float g = f * 0.6931471805599453f;
    float p = 8.3333337e-3f;
    p = fmaf(p, g, 4.1666668e-2f);
    p = fmaf(p, g, 0.16666667f);
    p = fmaf(p, g, 0.5f);
    p = fmaf(p, g, 1.0f);
    p = fmaf(p, g, 1.0f);
    return p * __int_as_float((ei + 127) << 23);
}

// swizzled [d][m] smem address for 64x64 tf32 tiles (conflict-free stage + b-frag load)
__device__ __forceinline__ int vaddr(int d, int m) {
    return d * 64 + (m ^ (((d & 3) << 3) + (((d >> 2) & 1) << 2)));
}

// ---------------- GroupNorm (unchanged) ----------------
__global__ void gn_kernel(const float* __restrict__ x,
                          const float* __restrict__ gamma,
                          const float* __restrict__ beta) {
    int b = blockIdx.x >> 5;
    int g = blockIdx.x & 31;
    const float* xp = x + ((size_t)b * Cc + g * 16) * Nn;
    float* op = g_xn + ((size_t)b * Cc + g * 16) * Nn;

    float s = 0.f, s2 = 0.f;
    for (int i = threadIdx.x * 4; i < 16384; i += 1024) {
        float4 v = *(const float4*)(xp + i);
        s  += v.x + v.y + v.z + v.w;
        s2 += v.x * v.x + v.y * v.y + v.z * v.z + v.w * v.w;
    }
    for (int off = 16; off; off >>= 1) {
        s  += __shfl_xor_sync(0xffffffffu, s,  off);
        s2 += __shfl_xor_sync(0xffffffffu, s2, off);
    }
    __shared__ float sh[2][8];
    int w = threadIdx.x >> 5;
    if ((threadIdx.x & 31) == 0) { sh[0][w] = s; sh[1][w] = s2; }
    __syncthreads();
    if (threadIdx.x < 32) {
        s  = (threadIdx.x < 8) ? sh[0][threadIdx.x] : 0.f;
        s2 = (threadIdx.x < 8) ? sh[1][threadIdx.x] : 0.f;
        for (int off = 4; off; off >>= 1) {
            s  += __shfl_xor_sync(0xffffffffu, s,  off);
            s2 += __shfl_xor_sync(0xffffffffu, s2, off);
        }
        if (threadIdx.x == 0) { sh[0][0] = s; sh[1][0] = s2; }
    }
    __syncthreads();
    float mean = sh[0][0] * (1.f / 16384.f);
    float var  = sh[1][0] * (1.f / 16384.f) - mean * mean;
    float rstd = rsqrtf(var + 1e-5f);

    for (int i = threadIdx.x * 4; i < 16384; i += 1024) {
        float4 v = *(const float4*)(xp + i);
        int c = g * 16 + (i >> 10);
        float ga = gamma[c] * rstd;
        float be = beta[c] - mean * ga;
        v.x = v.x * ga + be; v.y = v.y * ga + be;
        v.z = v.z * ga + be; v.w = v.w * ga + be;
        *(float4*)(op + i) = v;
    }
}

// ---------------- tf32 mma.sync GEMM (unchanged from round 4) ----------------
#define BB 8192
__global__ __launch_bounds__(256) void gemm_mma(
    const float* __restrict__ X, const float* __restrict__ W,
    const float* __restrict__ bias, const float* __restrict__ resid,
    float* __restrict__ out, int M)
{
    extern __shared__ uint32_t smemU[];
    const int tid = threadIdx.x;
    const int lane = tid & 31;
    const int wid = tid >> 5;
    const int wm = wid & 3;
    const int wn = wid >> 2;
    const int nb = blockIdx.x * 128;
    const int ob = blockIdx.y * 128;
    const int b  = blockIdx.z;

    const float* Wp = W + (size_t)ob * Cc;
    const float* Xp = X + (size_t)b * Cc * Nn + nb;

    float4 wreg[4], xreg[4];

    auto fetch = [&](int it) {
        int kk = it * 32;
        #pragma unroll
        for (int i = 0; i < 4; ++i) {
            int f = tid + i * 256;
            wreg[i] = *(const float4*)(Wp + (size_t)(f >> 3) * Cc + kk + (f & 7) * 4);
            xreg[i] = *(const float4*)(Xp + (size_t)(kk + (f >> 5)) * Nn + (f & 31) * 4);
        }
    };
    auto scatter = [&](int buf) {
        #pragma unroll
        for (int i = 0; i < 4; ++i) {
            int f = tid + i * 256;
            {
                int o  = f >> 3, c4 = f & 7;
                int kstep = c4 >> 1;
                int mtile = o >> 4;
                int reg   = ((o >> 3) & 1) | ((c4 & 1) << 1);
                int addr  = buf * 4096 + ((kstep * 8 + mtile) * 4 + reg) * 32 + (o & 7) * 4;
                const float* wv = (const float*)&wreg[i];
                uint4 v = make_uint4(f2tf32(wv[0]), f2tf32(wv[1]), f2tf32(wv[2]), f2tf32(wv[3]));
                *(uint4*)(smemU + addr) = v;
            }
            {
                int c_in = f >> 5, n4 = f & 31;
                int kstep = c_in >> 3, c8 = c_in & 7;
                int reg = c8 >> 2, k2 = c8 & 3;
                int ntile = n4 >> 1, n_in0 = (n4 & 1) * 4;
                int addr = BB + buf * 4608 + kstep * 1152 + ntile * 72 + reg * 32 + k2 * 8 + n_in0;
                const float* xv = (const float*)&xreg[i];
                uint4 v = make_uint4(f2tf32(xv[0]), f2tf32(xv[1]), f2tf32(xv[2]), f2tf32(xv[3]));
                *(uint4*)(smemU + addr) = v;
            }
        }
    };

    float acc[2][8][4];
    #pragma unroll
    for (int mt = 0; mt < 2; ++mt)
        #pragma unroll
        for (int nt = 0; nt < 8; ++nt)
            #pragma unroll
            for (int r = 0; r < 4; ++r) acc[mt][nt][r] = 0.f;

    fetch(0); scatter(0); fetch(1);
    __syncthreads();

    const int bperm = (lane & 3) * 8 + (lane >> 2);
    const int NIT = Cc / 32;
    for (int it = 0; it < NIT; ++it) {
        int cur = it & 1;
        if (it + 1 < NIT) scatter(1 - cur);
        if (it + 2 < NIT) fetch(it + 2);

        const uint32_t* ab = smemU + cur * 4096;
        const uint32_t* bb = smemU + BB + cur * 4608;
        #pragma unroll
        for (int ks = 0; ks < 4; ++ks) {
            uint32_t afr[2][4];
            uint32_t bfr[8][2];
            #pragma unroll
            for (int mt = 0; mt < 2; ++mt)
                #pragma unroll
                for (int r = 0; r < 4; ++r)
                    afr[mt][r] = ab[((ks * 8 + wm * 2 + mt) * 4 + r) * 32 + lane];
            #pragma unroll
            for (int nt = 0; nt < 8; ++nt)
                #pragma unroll
                for (int r = 0; r < 2; ++r)
                    bfr[nt][r] = bb[ks * 1152 + (wn * 8 + nt) * 72 + r * 32 + bperm];
            #pragma unroll
            for (int mt = 0; mt < 2; ++mt)
                #pragma unroll
                for (int nt = 0; nt < 8; ++nt)
                    mma_tf32(acc[mt][nt], afr[mt], bfr[nt]);
        }
        __syncthreads();
    }

    #pragma unroll
    for (int mt = 0; mt < 2; ++mt) {
        int o = ob + wm * 32 + mt * 16 + (lane >> 2);
        float b0 = __ldg(bias + o);
        float b1 = __ldg(bias + o + 8);
        #pragma unroll
        for (int nt = 0; nt < 8; ++nt) {
            int n = nb + wn * 64 + nt * 8 + (lane & 3) * 2;
            size_t i0 = ((size_t)b * M + o) * Nn + n;
            size_t i1 = i0 + (size_t)8 * Nn;
            float2 v0 = make_float2(acc[mt][nt][0] + b0, acc[mt][nt][1] + b0);
            float2 v1 = make_float2(acc[mt][nt][2] + b1, acc[mt][nt][3] + b1);
            if (resid) {
                float2 r0 = *(const float2*)(resid + i0);
                float2 r1 = *(const float2*)(resid + i1);
                v0.x += r0.x; v0.y += r0.y;
                v1.x += r1.x; v1.y += r1.y;
            }
            *(float2*)(out + i0) = v0;
            *(float2*)(out + i1) = v1;
        }
    }
}

// ---------------- flash attention with tf32 mma.sync ----------------
// block = (128 q, head, batch); 8 warps, warp owns 16 q rows x all m.
// S = Q K^T:  A = Q[q][d] row-major (k=d), B = K as [n=m][k=d] col-major -> native [d][m] smem
// O = P V  :  A = P[q][m] row-major (k=m), B = V as [n=d][k=m] col-major -> native [d][m] smem
__global__ __launch_bounds__(256) void attn_mma() {
    const int b = blockIdx.z, h = blockIdx.y;
    const float* qp = g_qkv + ((size_t)b * 3 * Cc + h * HD) * Nn;
    const float* kp = qp + (size_t)Cc * Nn;
    const float* vp = qp + (size_t)2 * Cc * Nn;
    const int qbase = blockIdx.x * 128;

    extern __shared__ uint32_t smu[];
    uint32_t* ks = smu;           // [64d][64m] swizzled, 4096 words
    uint32_t* vs = smu + 4096;    // [64d][64m] swizzled, 4096 words
    uint32_t* ps = smu + 8192;    // 8 warps x [16 q][68], 8704 words

    const int tid = threadIdx.x, lane = tid & 31, w = tid >> 5;
    const int r = lane >> 2, c = lane & 3;
    uint32_t* pw = ps + w * 1088;

    // preload Q a-frags (16 rows x 64 d per warp), tf32
    uint32_t aq[8][4];
    {
        int q0 = qbase + w * 16 + r;
        #pragma unroll
        for (int kt = 0; kt < 8; ++kt) {
            int d = kt * 8 + c;
            aq[kt][0] = f2tf32(__ldg(qp + (size_t)d * Nn + q0));
            aq[kt][1] = f2tf32(__ldg(qp + (size_t)d * Nn + q0 + 8));
            aq[kt][2] = f2tf32(__ldg(qp + (size_t)(d + 4) * Nn + q0));
            aq[kt][3] = f2tf32(__ldg(qp + (size_t)(d + 4) * Nn + q0 + 8));
        }
    }

    float oacc[8][4];
    #pragma unroll
    for (int j = 0; j < 8; ++j)
        #pragma unroll
        for (int i = 0; i < 4; ++i) oacc[j][i] = 0.f;
    float rm0 = -1e30f, rm1 = -1e30f, rs0 = 0.f, rs1 = 0.f;

    const float SCL = 0.125f * 1.4426950408889634f;   // hd^-0.5 * log2(e)

    for (int kt = 0; kt < 16; ++kt) {
        // stage K, V tiles (native [d][m], swizzled, tf32)
        #pragma unroll
        for (int rr = 0; rr < 4; ++rr) {
            int f = tid + rr * 256;
            int d = f >> 4, m0 = (f & 15) * 4;
            float4 kv = *(const float4*)(kp + (size_t)d * Nn + kt * 64 + m0);
            float4 vv = *(const float4*)(vp + (size_t)d * Nn + kt * 64 + m0);
            int sa = vaddr(d, m0);
            *(uint4*)(ks + sa) = make_uint4(f2tf32(kv.x), f2tf32(kv.y), f2tf32(kv.z), f2tf32(kv.w));
            *(uint4*)(vs + sa) = make_uint4(f2tf32(vv.x), f2tf32(vv.y), f2tf32(vv.z), f2tf32(vv.w));
        }
        __syncthreads();

        // S = Q K^T  (16q x 64m per warp)
        float sacc[8][4];
        #pragma unroll
        for (int j = 0; j < 8; ++j)
            #pragma unroll
            for (int i = 0; i < 4; ++i) sacc[j][i] = 0.f;
        #pragma unroll
        for (int k2 = 0; k2 < 8; ++k2) {
            int d = k2 * 8 + c;
            uint32_t bk[8][2];
            #pragma unroll
            for (int j = 0; j < 8; ++j) {
                int m = j * 8 + r;
                bk[j][0] = ks[vaddr(d, m)];
                bk[j][1] = ks[vaddr(d + 4, m)];
            }
            #pragma unroll
            for (int j = 0; j < 8; ++j) mma_tf32(sacc[j], aq[k2], bk[j]);
        }

        // online softmax (rows r and r+8; quad lanes share a row)
        float tm0 = -1e30f, tm1 = -1e30f;
        #pragma unroll
        for (int j = 0; j < 8; ++j) {
            sacc[j][0] *= SCL; sacc[j][1] *= SCL;
            sacc[j][2] *= SCL; sacc[j][3] *= SCL;
            tm0 = fmaxf(tm0, fmaxf(sacc[j][0], sacc[j][1]));
            tm1 = fmaxf(tm1, fmaxf(sacc[j][2], sacc[j][3]));
        }
        tm0 = fmaxf(tm0, __shfl_xor_sync(0xffffffffu, tm0, 1));
        tm0 = fmaxf(tm0, __shfl_xor_sync(0xffffffffu, tm0, 2));
        tm1 = fmaxf(tm1, __shfl_xor_sync(0xffffffffu, tm1, 1));
        tm1 = fmaxf(tm1, __shfl_xor_sync(0xffffffffu, tm1, 2));
        float nm0 = fmaxf(rm0, tm0), nm1 = fmaxf(rm1, tm1);
        float cr0 = fexp2(rm0 - nm0), cr1 = fexp2(rm1 - nm1);
        rm0 = nm0; rm1 = nm1;
        float ts0 = 0.f, ts1 = 0.f;
        #pragma unroll
        for (int j = 0; j < 8; ++j) {
            uint32_t p0 = f2tf32(fexp2(sacc[j][0] - nm0));
            uint32_t p1 = f2tf32(fexp2(sacc[j][1] - nm0));
            uint32_t p2 = f2tf32(fexp2(sacc[j][2] - nm1));
            uint32_t p3 = f2tf32(fexp2(sacc[j][3] - nm1));
            ts0 += __uint_as_float(p0) + __uint_as_float(p1);
            ts1 += __uint_as_float(p2) + __uint_as_float(p3);
            *(uint2*)(pw + r * 68 + j * 8 + 2 * c)       = make_uint2(p0, p1);
            *(uint2*)(pw + (r + 8) * 68 + j * 8 + 2 * c) = make_uint2(p2, p3);
            oacc[j][0] *= cr0; oacc[j][1] *= cr0;
            oacc[j][2] *= cr1; oacc[j][3] *= cr1;
        }
        ts0 += __shfl_xor_sync(0xffffffffu, ts0, 1);
        ts0 += __shfl_xor_sync(0xffffffffu, ts0, 2);
        ts1 += __shfl_xor_sync(0xffffffffu, ts1, 1);
        ts1 += __shfl_xor_sync(0xffffffffu, ts1, 2);
        rs0 = rs0 * cr0 + ts0;
        rs1 = rs1 * cr1 + ts1;
        __syncwarp();

        // O += P V  (16q x 64d per warp)
        #pragma unroll
        for (int ksq = 0; ksq < 8; ++ksq) {
            uint32_t ap4[4];
            ap4[0] = pw[r * 68 + ksq * 8 + c];
            ap4[1] = pw[(r + 8) * 68 + ksq * 8 + c];
            ap4[2] = pw[r * 68 + ksq * 8 + c + 4];
            ap4[3] = pw[(r + 8) * 68 + ksq * 8 + c + 4];
            int m = ksq * 8 + c;
            #pragma unroll
            for (int j = 0; j < 8; ++j) {
                int d = j * 8 + r;
                uint32_t bv[2];
                bv[0] = vs[vaddr(d, m)];
                bv[1] = vs[vaddr(d, m + 4)];
                mma_tf32(oacc[j], ap4, bv);
            }
        }
        __syncthreads();   // protect ks/vs before next tile staging
    }

    // normalize + transpose to [d][q] via smem, coalesced store
    float inv0 = 1.f / rs0, inv1 = 1.f / rs1;
    float* os = (float*)smu;    // 64 x 128 (reuses ks+vs area)
    int q0 = w * 16 + r;
    #pragma unroll
    for (int j = 0; j < 8; ++j) {
        int d = j * 8 + 2 * c;
        os[d * 128 + q0]           = oacc[j][0] * inv0;
        os[(d + 1) * 128 + q0]     = oacc[j][1] * inv0;
        os[d * 128 + q0 + 8]       = oacc[j][2] * inv1;
        os[(d + 1) * 128 + q0 + 8] = oacc[j][3] * inv1;
    }
    __syncthreads();
    float* ap = g_att + ((size_t)b * Cc + h * HD) * Nn + qbase;
    #pragma unroll
    for (int rr = 0; rr < 8; ++rr) {
        int f = tid + rr * 256;
        int d = f >> 5, q4 = (f & 31) * 4;
        *(float4*)(ap + (size_t)d * Nn + q4) = *(float4*)(os + d * 128 + q4);
    }
}

// ---------------- launch ----------------
extern "C" void kernel_launch(void* const* d_in, const int* in_sizes, int n_in,
                              void* d_out, int out_size) {
    const float* x      = (const float*)d_in[0];
    const float* gamma  = (const float*)d_in[1];
    const float* beta   = (const float*)d_in[2];
    const float* w_qkv  = (const float*)d_in[3];
    const float* b_qkv  = (const float*)d_in[4];
    const float* w_proj = (const float*)d_in[5];
    const float* b_proj = (const float*)d_in[6];
    float* out = (float*)d_out;

    float *xn, *qkv, *att;
    cudaGetSymbolAddress((void**)&xn,  g_xn);
    cudaGetSymbolAddress((void**)&qkv, g_qkv);
    cudaGetSymbolAddress((void**)&att, g_att);

    const int gemm_smem = (8192 + 9216) * 4;          // 69632 B
    const int attn_smem = (4096 + 4096 + 8704) * 4;   // 67584 B
    cudaFuncSetAttribute(gemm_mma, cudaFuncAttributeMaxDynamicSharedMemorySize, gemm_smem);
    cudaFuncSetAttribute(attn_mma, cudaFuncAttributeMaxDynamicSharedMemorySize, attn_smem);

    gn_kernel<<<256, 256>>>(x, gamma, beta);
    gemm_mma<<<dim3(8, 12, 8), 256, gemm_smem>>>(xn, w_qkv, b_qkv, nullptr, qkv, 3 * Cc);
    attn_mma<<<dim3(8, NH, Bn), 256, attn_smem>>>();
    gemm_mma<<<dim3(8, 4, 8), 256, gemm_smem>>>(att, w_proj, b_proj, x, out, Cc);
}

// round 7
// speedup vs baseline: 3.3229x; 1.3477x over previous
#include <cuda_runtime.h>
#include <math_constants.h>
#include <cstdint>

#define Bn 8
#define Cc 512
#define Nn 1024
#define NH 8
#define HD 64

// ---------------- scratch (device globals; no allocation) ----------------
__device__ float    g_qkv[Bn * 3 * Cc * Nn];        // 48 MB fp32 [b][o][n]
__device__ uint32_t g_xb  [Bn * 64 * Nn * 8];       // 16 MB tf32 b-frag layout (x_norm)
__device__ uint32_t g_atb [Bn * 64 * Nn * 8];       // 16 MB tf32 b-frag layout (attn out)
__device__ uint32_t g_wA  [96 * 64 * 32 * 4];       //  3 MB tf32 a-frag layout (w_qkv)
__device__ uint32_t g_wP  [32 * 64 * 32 * 4];       //  1 MB tf32 a-frag layout (w_proj)

// b-frag interleave: slot(c&7) = ((c&3)<<1) | ((c>>2)&1);  inv: c(j) = (j>>1) + ((j&1)<<2)

// ---------------- helpers ----------------
__device__ __forceinline__ uint32_t f2tf32(float f) {
    uint32_t r;
    asm("cvt.rna.tf32.f32 %0, %1;" : "=r"(r) : "f"(f));
    return r;
}
__device__ __forceinline__ void mma_tf32(float* d, const uint32_t* a, const uint32_t* b) {
    asm volatile(
        "mma.sync.aligned.m16n8k8.row.col.f32.tf32.tf32.f32 "
        "{%0,%1,%2,%3}, {%4,%5,%6,%7}, {%8,%9}, {%0,%1,%2,%3};"
        : "+f"(d[0]), "+f"(d[1]), "+f"(d[2]), "+f"(d[3])
        : "r"(a[0]), "r"(a[1]), "r"(a[2]), "r"(a[3]), "r"(b[0]), "r"(b[1]));
}
__device__ __forceinline__ float fexp2(float t) {
    t = fmaxf(t, -120.f);
    int ei = __float2int_rn(t);
    float f = t - (float)ei;
    float g = f * 0.6931471805599453f;
    float p = 8.3333337e-3f;
    p = fmaf(p, g, 4.1666668e-2f);
    p = fmaf(p, g, 0.16666667f);
    p = fmaf(p, g, 0.5f);
    p = fmaf(p, g, 1.0f);
    p = fmaf(p, g, 1.0f);
    return p * __int_as_float((ei + 127) << 23);
}
__device__ __forceinline__ int vaddr(int d, int m) {
    return d * 64 + (m ^ (((d & 3) << 3) + (((d >> 2) & 1) << 2)));
}

// ---------------- weight prep: W[M][512] -> a-frag layout tf32 ----------------
// dst[((mtile*64 + ks)*32 + lane)*4 + reg], lane=(o&7)*4+(c&3), reg=((o>>3)&1)|(((c>>2)&1)<<1)
__global__ void wprep(const float* __restrict__ W, uint32_t* __restrict__ dst) {
    int e = blockIdx.x * 256 + threadIdx.x;
    int o = e >> 9, c = e & 511;
    int mtile = o >> 4, ks = c >> 3;
    int lane = ((o & 7) << 2) | (c & 3);
    int reg  = ((o >> 3) & 1) | (((c >> 2) & 1) << 1);
    dst[(size_t)(mtile * 64 + ks) * 128 + lane * 4 + reg] = f2tf32(W[e]);
}

// ---------------- GroupNorm -> tf32 b-frag layout ----------------
__global__ void gn_kernel(const float* __restrict__ x,
                          const float* __restrict__ gamma,
                          const float* __restrict__ beta) {
    extern __shared__ float sx[];   // [16][1024]
    int b = blockIdx.x >> 5;
    int g = blockIdx.x & 31;
    const float* xp = x + ((size_t)b * Cc + g * 16) * Nn;
    int tid = threadIdx.x;

    float s = 0.f, s2 = 0.f;
    for (int i = tid * 4; i < 16384; i += 1024) {
        float4 v = *(const float4*)(xp + i);
        *(float4*)(sx + i) = v;
        s  += v.x + v.y + v.z + v.w;
        s2 += v.x * v.x + v.y * v.y + v.z * v.z + v.w * v.w;
    }
    for (int off = 16; off; off >>= 1) {
        s  += __shfl_xor_sync(0xffffffffu, s,  off);
        s2 += __shfl_xor_sync(0xffffffffu, s2, off);
    }
    __shared__ float sh[2][8];
    int w = tid >> 5;
    if ((tid & 31) == 0) { sh[0][w] = s; sh[1][w] = s2; }
    __syncthreads();
    if (tid < 32) {
        s  = (tid < 8) ? sh[0][tid] : 0.f;
        s2 = (tid < 8) ? sh[1][tid] : 0.f;
        for (int off = 4; off; off >>= 1) {
            s  += __shfl_xor_sync(0xffffffffu, s,  off);
            s2 += __shfl_xor_sync(0xffffffffu, s2, off);
        }
        if (tid == 0) { sh[0][0] = s; sh[1][0] = s2; }
    }
    __syncthreads();
    float mean = sh[0][0] * (1.f / 16384.f);
    float var  = sh[1][0] * (1.f / 16384.f) - mean * mean;
    float rstd = rsqrtf(var + 1e-5f);

    float ga[16], be[16];
    #pragma unroll
    for (int c = 0; c < 16; ++c) {
        float gg = __ldg(gamma + g * 16 + c) * rstd;
        ga[c] = gg;
        be[c] = __ldg(beta + g * 16 + c) - mean * gg;
    }

    uint32_t* op = g_xb + ((size_t)b * 64 + g * 2) * 8192;
    #pragma unroll
    for (int r = 0; r < 16; ++r) {
        int f = (tid + r * 256) * 4;     // word idx 0..16383
        int cgl = f >> 13, rem = f & 8191;
        int n = rem >> 3, j0 = rem & 7;  // j0 in {0,4}
        uint32_t vv[4];
        #pragma unroll
        for (int i = 0; i < 4; ++i) {
            int j = j0 + i;
            int cl = cgl * 8 + ((j >> 1) + ((j & 1) << 2));
            vv[i] = f2tf32(sx[cl * 1024 + n] * ga[cl] + be[cl]);
        }
        *(uint4*)(op + (size_t)cgl * 8192 + rem) = make_uint4(vv[0], vv[1], vv[2], vv[3]);
    }
}

// ---------------- tf32 mma GEMM, fragment-direct (no smem, no syncs) ----------------
// out[b,o,n] = bias[o] + sum_c A[o,c]*B[b,c,n] (+resid)
// A: a-frag layout; B: b-frag layout. Block 128o x 128n, 8 warps (4m x 2n).
__global__ __launch_bounds__(256) void gemm_mma(
    const uint32_t* __restrict__ Amat, const uint32_t* __restrict__ Bmat,
    const float* __restrict__ bias, const float* __restrict__ resid,
    float* __restrict__ out, int M)
{
    const int tid = threadIdx.x;
    const int lane = tid & 31;
    const int wid = tid >> 5;
    const int wm = wid & 3;
    const int wn = wid >> 2;
    const int nb = blockIdx.x * 128;
    const int ob = blockIdx.y * 128;
    const int b  = blockIdx.z;

    const uint32_t* Aw0 = Amat + (size_t)((ob >> 4) + wm * 2)     * 8192 + lane * 4;
    const uint32_t* Aw1 = Amat + (size_t)((ob >> 4) + wm * 2 + 1) * 8192 + lane * 4;
    const uint32_t* Bw  = Bmat + (size_t)b * 524288
                        + (size_t)(nb + wn * 64 + (lane >> 2)) * 8 + ((lane & 3) << 1);

    float acc[2][8][4];
    #pragma unroll
    for (int mt = 0; mt < 2; ++mt)
        #pragma unroll
        for (int nt = 0; nt < 8; ++nt)
            #pragma unroll
            for (int r = 0; r < 4; ++r) acc[mt][nt][r] = 0.f;

    uint4 afr[2][2];
    uint2 bfr[2][8];

    auto ld = [&](int ks, int p) {
        afr[p][0] = *(const uint4*)(Aw0 + ks * 128);
        afr[p][1] = *(const uint4*)(Aw1 + ks * 128);
        #pragma unroll
        for (int nt = 0; nt < 8; ++nt)
            bfr[p][nt] = *(const uint2*)(Bw + ks * 8192 + nt * 64);
    };
    auto domma = [&](int p) {
        #pragma unroll
        for (int mt = 0; mt < 2; ++mt)
            #pragma unroll
            for (int nt = 0; nt < 8; ++nt)
                mma_tf32(acc[mt][nt], (const uint32_t*)&afr[p][mt], (const uint32_t*)&bfr[p][nt]);
    };

    ld(0, 0);
    #pragma unroll 4
    for (int ks = 0; ks < 64; ks += 2) {
        ld(ks + 1, 1);
        domma(0);
        if (ks + 2 < 64) ld(ks + 2, 0);
        domma(1);
    }

    #pragma unroll
    for (int mt = 0; mt < 2; ++mt) {
        int o = ob + wm * 32 + mt * 16 + (lane >> 2);
        float b0 = __ldg(bias + o);
        float b1 = __ldg(bias + o + 8);
        #pragma unroll
        for (int nt = 0; nt < 8; ++nt) {
            int n = nb + wn * 64 + nt * 8 + (lane & 3) * 2;
            size_t i0 = ((size_t)b * M + o) * Nn + n;
            size_t i1 = i0 + (size_t)8 * Nn;
            float2 v0 = make_float2(acc[mt][nt][0] + b0, acc[mt][nt][1] + b0);
            float2 v1 = make_float2(acc[mt][nt][2] + b1, acc[mt][nt][3] + b1);
            if (resid) {
                float2 r0 = *(const float2*)(resid + i0);
                float2 r1 = *(const float2*)(resid + i1);
                v0.x += r0.x; v0.y += r0.y;
                v1.x += r1.x; v1.y += r1.y;
            }
            *(float2*)(out + i0) = v0;
            *(float2*)(out + i1) = v1;
        }
    }
}

// ---------------- flash attention with tf32 mma.sync ----------------
__global__ __launch_bounds__(256) void attn_mma() {
    const int b = blockIdx.z, h = blockIdx.y;
    const float* qp = g_qkv + ((size_t)b * 3 * Cc + h * HD) * Nn;
    const float* kp = qp + (size_t)Cc * Nn;
    const float* vp = qp + (size_t)2 * Cc * Nn;
    const int qbase = blockIdx.x * 128;

    extern __shared__ uint32_t smu[];
    uint32_t* ks = smu;           // [64d][64m] swizzled
    uint32_t* vs = smu + 4096;
    uint32_t* ps = smu + 8192;    // 8 warps x [16 q][68]

    const int tid = threadIdx.x, lane = tid & 31, w = tid >> 5;
    const int r = lane >> 2, c = lane & 3;
    uint32_t* pw = ps + w * 1088;

    uint32_t aq[8][4];
    {
        int q0 = qbase + w * 16 + r;
        #pragma unroll
        for (int kt = 0; kt < 8; ++kt) {
            int d = kt * 8 + c;
            aq[kt][0] = f2tf32(__ldg(qp + (size_t)d * Nn + q0));
            aq[kt][1] = f2tf32(__ldg(qp + (size_t)d * Nn + q0 + 8));
            aq[kt][2] = f2tf32(__ldg(qp + (size_t)(d + 4) * Nn + q0));
            aq[kt][3] = f2tf32(__ldg(qp + (size_t)(d + 4) * Nn + q0 + 8));
        }
    }

    float oacc[8][4];
    #pragma unroll
    for (int j = 0; j < 8; ++j)
        #pragma unroll
        for (int i = 0; i < 4; ++i) oacc[j][i] = 0.f;
    float rm0 = -1e30f, rm1 = -1e30f, rs0 = 0.f, rs1 = 0.f;

    const float SCL = 0.125f * 1.4426950408889634f;

    for (int kt = 0; kt < 16; ++kt) {
        #pragma unroll
        for (int rr = 0; rr < 4; ++rr) {
            int f = tid + rr * 256;
            int d = f >> 4, m0 = (f & 15) * 4;
            float4 kv = *(const float4*)(kp + (size_t)d * Nn + kt * 64 + m0);
            float4 vv = *(const float4*)(vp + (size_t)d * Nn + kt * 64 + m0);
            int sa = vaddr(d, m0);
            *(uint4*)(ks + sa) = make_uint4(f2tf32(kv.x), f2tf32(kv.y), f2tf32(kv.z), f2tf32(kv.w));
            *(uint4*)(vs + sa) = make_uint4(f2tf32(vv.x), f2tf32(vv.y), f2tf32(vv.z), f2tf32(vv.w));
        }
        __syncthreads();

        float sacc[8][4];
        #pragma unroll
        for (int j = 0; j < 8; ++j)
            #pragma unroll
            for (int i = 0; i < 4; ++i) sacc[j][i] = 0.f;
        #pragma unroll
        for (int k2 = 0; k2 < 8; ++k2) {
            int d = k2 * 8 + c;
            uint32_t bk[8][2];
            #pragma unroll
            for (int j = 0; j < 8; ++j) {
                int m = j * 8 + r;
                bk[j][0] = ks[vaddr(d, m)];
                bk[j][1] = ks[vaddr(d + 4, m)];
            }
            #pragma unroll
            for (int j = 0; j < 8; ++j) mma_tf32(sacc[j], aq[k2], bk[j]);
        }

        float tm0 = -1e30f, tm1 = -1e30f;
        #pragma unroll
        for (int j = 0; j < 8; ++j) {
            sacc[j][0] *= SCL; sacc[j][1] *= SCL;
            sacc[j][2] *= SCL; sacc[j][3] *= SCL;
            tm0 = fmaxf(tm0, fmaxf(sacc[j][0], sacc[j][1]));
            tm1 = fmaxf(tm1, fmaxf(sacc[j][2], sacc[j][3]));
        }
        tm0 = fmaxf(tm0, __shfl_xor_sync(0xffffffffu, tm0, 1));
        tm0 = fmaxf(tm0, __shfl_xor_sync(0xffffffffu, tm0, 2));
        tm1 = fmaxf(tm1, __shfl_xor_sync(0xffffffffu, tm1, 1));
        tm1 = fmaxf(tm1, __shfl_xor_sync(0xffffffffu, tm1, 2));
        float nm0 = fmaxf(rm0, tm0), nm1 = fmaxf(rm1, tm1);
        float cr0 = fexp2(rm0 - nm0), cr1 = fexp2(rm1 - nm1);
        rm0 = nm0; rm1 = nm1;
        float ts0 = 0.f, ts1 = 0.f;
        #pragma unroll
        for (int j = 0; j < 8; ++j) {
            uint32_t p0 = f2tf32(fexp2(sacc[j][0] - nm0));
            uint32_t p1 = f2tf32(fexp2(sacc[j][1] - nm0));
            uint32_t p2 = f2tf32(fexp2(sacc[j][2] - nm1));
            uint32_t p3 = f2tf32(fexp2(sacc[j][3] - nm1));
            ts0 += __uint_as_float(p0) + __uint_as_float(p1);
            ts1 += __uint_as_float(p2) + __uint_as_float(p3);
            *(uint2*)(pw + r * 68 + j * 8 + 2 * c)       = make_uint2(p0, p1);
            *(uint2*)(pw + (r + 8) * 68 + j * 8 + 2 * c) = make_uint2(p2, p3);
            oacc[j][0] *= cr0; oacc[j][1] *= cr0;
            oacc[j][2] *= cr1; oacc[j][3] *= cr1;
        }
        ts0 += __shfl_xor_sync(0xffffffffu, ts0, 1);
        ts0 += __shfl_xor_sync(0xffffffffu, ts0, 2);
        ts1 += __shfl_xor_sync(0xffffffffu, ts1, 1);
        ts1 += __shfl_xor_sync(0xffffffffu, ts1, 2);
        rs0 = rs0 * cr0 + ts0;
        rs1 = rs1 * cr1 + ts1;
        __syncwarp();

        #pragma unroll
        for (int ksq = 0; ksq < 8; ++ksq) {
            uint32_t ap4[4];
            ap4[0] = pw[r * 68 + ksq * 8 + c];
            ap4[1] = pw[(r + 8) * 68 + ksq * 8 + c];
            ap4[2] = pw[r * 68 + ksq * 8 + c + 4];
            ap4[3] = pw[(r + 8) * 68 + ksq * 8 + c + 4];
            int m = ksq * 8 + c;
            #pragma unroll
            for (int j = 0; j < 8; ++j) {
                int d = j * 8 + r;
                uint32_t bv[2];
                bv[0] = vs[vaddr(d, m)];
                bv[1] = vs[vaddr(d, m + 4)];
                mma_tf32(oacc[j], ap4, bv);
            }
        }
        __syncthreads();
    }

    // normalize, transpose to [d][128q] in smem, then write tf32 b-frag layout
    float inv0 = 1.f / rs0, inv1 = 1.f / rs1;
    float* os = (float*)smu;    // 64 x 128
    int q0 = w * 16 + r;
    #pragma unroll
    for (int j = 0; j < 8; ++j) {
        int d = j * 8 + 2 * c;
        os[d * 128 + q0]           = oacc[j][0] * inv0;
        os[(d + 1) * 128 + q0]     = oacc[j][1] * inv0;
        os[d * 128 + q0 + 8]       = oacc[j][2] * inv1;
        os[(d + 1) * 128 + q0 + 8] = oacc[j][3] * inv1;
    }
    __syncthreads();
    uint32_t* op = g_atb + ((size_t)b * 64 + h * 8) * 8192 + (size_t)qbase * 8;
    #pragma unroll
    for (int rr = 0; rr < 8; ++rr) {
        int f = (tid + rr * 256) * 4;    // 0..8191
        int cg = f >> 10, rem = f & 1023;
        int n = rem >> 3, j0 = rem & 7;
        uint32_t vv[4];
        #pragma unroll
        for (int i = 0; i < 4; ++i) {
            int j = j0 + i;
            int dl = cg * 8 + ((j >> 1) + ((j & 1) << 2));
            vv[i] = f2tf32(os[dl * 128 + n]);
        }
        *(uint4*)(op + (size_t)cg * 8192 + rem) = make_uint4(vv[0], vv[1], vv[2], vv[3]);
    }
}

// ---------------- launch ----------------
extern "C" void kernel_launch(void* const* d_in, const int* in_sizes, int n_in,
                              void* d_out, int out_size) {
    const float* x      = (const float*)d_in[0];
    const float* gamma  = (const float*)d_in[1];
    const float* beta   = (const float*)d_in[2];
    const float* w_qkv  = (const float*)d_in[3];
    const float* b_qkv  = (const float*)d_in[4];
    const float* w_proj = (const float*)d_in[5];
    const float* b_proj = (const float*)d_in[6];
    float* out = (float*)d_out;

    float* qkv;
    uint32_t *xb, *atb, *wA, *wP;
    cudaGetSymbolAddress((void**)&qkv, g_qkv);
    cudaGetSymbolAddress((void**)&xb,  g_xb);
    cudaGetSymbolAddress((void**)&atb, g_atb);
    cudaGetSymbolAddress((void**)&wA,  g_wA);
    cudaGetSymbolAddress((void**)&wP,  g_wP);

    const int gn_smem   = 16 * 1024 * sizeof(float);          // 64 KB
    const int attn_smem = (4096 + 4096 + 8704) * 4;           // 67584 B
    cudaFuncSetAttribute(gn_kernel, cudaFuncAttributeMaxDynamicSharedMemorySize, gn_smem);
    cudaFuncSetAttribute(attn_mma,  cudaFuncAttributeMaxDynamicSharedMemorySize, attn_smem);

    wprep<<<3072, 256>>>(w_qkv, wA);
    wprep<<<1024, 256>>>(w_proj, wP);   // FIX: 262144 elements = 1024 blocks x 256
    gn_kernel<<<256, 256, gn_smem>>>(x, gamma, beta);
    gemm_mma<<<dim3(8, 12, 8), 256>>>(wA, xb, b_qkv, nullptr, qkv, 3 * Cc);
    attn_mma<<<dim3(8, NH, Bn), 256, attn_smem>>>();
    gemm_mma<<<dim3(8, 4, 8), 256>>>(wP, atb, b_proj, x, out, Cc);
}

// round 8
// speedup vs baseline: 3.9739x; 1.1959x over previous
#include <cuda_runtime.h>
#include <math_constants.h>
#include <cstdint>

#define Bn 8
#define Cc 512
#define Nn 1024
#define NH 8
#define HD 64

// ---------------- scratch (device globals; no allocation) ----------------
__device__ uint32_t g_xb [Bn * 64 * Nn * 8];        // 16 MB tf32 b-frag (x_norm)
__device__ uint32_t g_atb[Bn * 64 * Nn * 8];        // 16 MB tf32 b-frag (attn out)
__device__ uint32_t g_wA [96 * 64 * 32 * 4];        //  3 MB tf32 a-frag (w_qkv)
__device__ uint32_t g_wP [32 * 64 * 32 * 4];        //  1 MB tf32 a-frag (w_proj)
__device__ uint32_t g_qa [Bn * NH * 64 * 8 * 128];  // 16 MB Q a-frag  [b][h][qt16][kd][128]
__device__ uint32_t g_kb [Bn * NH * 16 * 8 * 512];  // 16 MB K b-frag  [b][h][kt][k2][m*8+slot]
__device__ uint32_t g_vb [Bn * NH * 16 * 8 * 512];  // 16 MB V b-frag  [b][h][kt][k2v][d*8+slot]

// ---------------- helpers ----------------
__device__ __forceinline__ uint32_t f2tf32(float f) {
    uint32_t r;
    asm("cvt.rna.tf32.f32 %0, %1;" : "=r"(r) : "f"(f));
    return r;
}
__device__ __forceinline__ void mma_tf32(float* d, const uint32_t* a, const uint32_t* b) {
    asm volatile(
        "mma.sync.aligned.m16n8k8.row.col.f32.tf32.tf32.f32 "
        "{%0,%1,%2,%3}, {%4,%5,%6,%7}, {%8,%9}, {%0,%1,%2,%3};"
        : "+f"(d[0]), "+f"(d[1]), "+f"(d[2]), "+f"(d[3])
        : "r"(a[0]), "r"(a[1]), "r"(a[2]), "r"(a[3]), "r"(b[0]), "r"(b[1]));
}
__device__ __forceinline__ float fexp2(float t) {
    t = fmaxf(t, -120.f);
    int ei = __float2int_rn(t);
    float f = t - (float)ei;
    float g = f * 0.6931471805599453f;
    float p = 8.3333337e-3f;
    p = fmaf(p, g, 4.1666668e-2f);
    p = fmaf(p, g, 0.16666667f);
    p = fmaf(p, g, 0.5f);
    p = fmaf(p, g, 1.0f);
    p = fmaf(p, g, 1.0f);
    return p * __int_as_float((ei + 127) << 23);
}
__device__ __forceinline__ uint32_t smem_u32(const void* p) {
    uint32_t a;
    asm("{ .reg .u64 t; cvta.to.shared.u64 t, %1; cvt.u32.u64 %0, t; }" : "=r"(a) : "l"(p));
    return a;
}
__device__ __forceinline__ void cp16(uint32_t saddr, const void* g) {
    asm volatile("cp.async.cg.shared.global [%0], [%1], 16;" :: "r"(saddr), "l"(g));
}
#define CP_COMMIT() asm volatile("cp.async.commit_group;")
#define CP_WAIT0()  asm volatile("cp.async.wait_group 0;")

// scatter one QKV value (bias already added, tf32 bits) to Q/K/V fragment buffers
__device__ __forceinline__ void qkv_store(int b, int o, int n, uint32_t v) {
    if (o < 512) {                       // Q a-frag
        int h = o >> 6, d = o & 63, q = n;
        size_t base = (((size_t)(b * 8 + h) * 64 + (q >> 4)) * 8 + (d >> 3)) * 128;
        int lane2 = ((q & 7) << 2) | (d & 3);
        int reg = ((q >> 3) & 1) | (((d >> 2) & 1) << 1);
        g_qa[base + lane2 * 4 + reg] = v;
    } else if (o < 1024) {               // K b-frag (pairs d, d+4)
        int h = (o >> 6) & 7, d = o & 63, m = n;
        size_t base = (((size_t)(b * 8 + h) * 16 + (m >> 6)) * 8 + (d >> 3)) * 512;
        int slot = ((d & 3) << 1) | ((d >> 2) & 1);
        g_kb[base + (m & 63) * 8 + slot] = v;
    } else {                             // V b-frag (pairs m, m+4)
        int h = (o >> 6) & 7, d = o & 63, m = n;
        size_t base = (((size_t)(b * 8 + h) * 16 + (m >> 6)) * 8 + ((m & 63) >> 3)) * 512;
        int slot = ((m & 3) << 1) | ((m >> 2) & 1);
        g_vb[base + d * 8 + slot] = v;
    }
}

// ---------------- weight prep: W[M][512] -> a-frag layout tf32 ----------------
__global__ void wprep(const float* __restrict__ W, uint32_t* __restrict__ dst) {
    int e = blockIdx.x * 256 + threadIdx.x;
    int o = e >> 9, c = e & 511;
    int mtile = o >> 4, ks = c >> 3;
    int lane = ((o & 7) << 2) | (c & 3);
    int reg  = ((o >> 3) & 1) | (((c >> 2) & 1) << 1);
    dst[(size_t)(mtile * 64 + ks) * 128 + lane * 4 + reg] = f2tf32(W[e]);
}

// ---------------- GroupNorm -> tf32 b-frag layout ----------------
__global__ void gn_kernel(const float* __restrict__ x,
                          const float* __restrict__ gamma,
                          const float* __restrict__ beta) {
    extern __shared__ float sx[];   // [16][1024]
    int b = blockIdx.x >> 5;
    int g = blockIdx.x & 31;
    const float* xp = x + ((size_t)b * Cc + g * 16) * Nn;
    int tid = threadIdx.x;

    float s = 0.f, s2 = 0.f;
    for (int i = tid * 4; i < 16384; i += 1024) {
        float4 v = *(const float4*)(xp + i);
        *(float4*)(sx + i) = v;
        s  += v.x + v.y + v.z + v.w;
        s2 += v.x * v.x + v.y * v.y + v.z * v.z + v.w * v.w;
    }
    for (int off = 16; off; off >>= 1) {
        s  += __shfl_xor_sync(0xffffffffu, s,  off);
        s2 += __shfl_xor_sync(0xffffffffu, s2, off);
    }
    __shared__ float sh[2][8];
    int w = tid >> 5;
    if ((tid & 31) == 0) { sh[0][w] = s; sh[1][w] = s2; }
    __syncthreads();
    if (tid < 32) {
        s  = (tid < 8) ? sh[0][tid] : 0.f;
        s2 = (tid < 8) ? sh[1][tid] : 0.f;
        for (int off = 4; off; off >>= 1) {
            s  += __shfl_xor_sync(0xffffffffu, s,  off);
            s2 += __shfl_xor_sync(0xffffffffu, s2, off);
        }
        if (tid == 0) { sh[0][0] = s; sh[1][0] = s2; }
    }
    __syncthreads();
    float mean = sh[0][0] * (1.f / 16384.f);
    float var  = sh[1][0] * (1.f / 16384.f) - mean * mean;
    float rstd = rsqrtf(var + 1e-5f);

    float ga[16], be[16];
    #pragma unroll
    for (int c = 0; c < 16; ++c) {
        float gg = __ldg(gamma + g * 16 + c) * rstd;
        ga[c] = gg;
        be[c] = __ldg(beta + g * 16 + c) - mean * gg;
    }

    uint32_t* op = g_xb + ((size_t)b * 64 + g * 2) * 8192;
    #pragma unroll
    for (int r = 0; r < 16; ++r) {
        int f = (tid + r * 256) * 4;
        int cgl = f >> 13, rem = f & 8191;
        int n = rem >> 3, j0 = rem & 7;
        uint32_t vv[4];
        #pragma unroll
        for (int i = 0; i < 4; ++i) {
            int j = j0 + i;
            int cl = cgl * 8 + ((j >> 1) + ((j & 1) << 2));
            vv[i] = f2tf32(sx[cl * 1024 + n] * ga[cl] + be[cl]);
        }
        *(uint4*)(op + (size_t)cgl * 8192 + rem) = make_uint4(vv[0], vv[1], vv[2], vv[3]);
    }
}

// ---------------- tf32 mma GEMM, fragment-direct ----------------
// qkvmode=1: scatter outputs to g_qa/g_kb/g_vb (tf32 bits, bias added)
// qkvmode=0: out[b,o,n] = bias + acc (+resid), fp32
__global__ __launch_bounds__(256) void gemm_mma(
    const uint32_t* __restrict__ Amat, const uint32_t* __restrict__ Bmat,
    const float* __restrict__ bias, const float* __restrict__ resid,
    float* __restrict__ out, int M, int qkvmode)
{
    const int tid = threadIdx.x;
    const int lane = tid & 31;
    const int wid = tid >> 5;
    const int wm = wid & 3;
    const int wn = wid >> 2;
    const int nb = blockIdx.x * 128;
    const int ob = blockIdx.y * 128;
    const int b  = blockIdx.z;

    const uint32_t* Aw0 = Amat + (size_t)((ob >> 4) + wm * 2)     * 8192 + lane * 4;
    const uint32_t* Aw1 = Amat + (size_t)((ob >> 4) + wm * 2 + 1) * 8192 + lane * 4;
    const uint32_t* Bw  = Bmat + (size_t)b * 524288
                        + (size_t)(nb + wn * 64 + (lane >> 2)) * 8 + ((lane & 3) << 1);

    float acc[2][8][4];
    #pragma unroll
    for (int mt = 0; mt < 2; ++mt)
        #pragma unroll
        for (int nt = 0; nt < 8; ++nt)
            #pragma unroll
            for (int r = 0; r < 4; ++r) acc[mt][nt][r] = 0.f;

    uint4 afr[2][2];
    uint2 bfr[2][8];

    auto ld = [&](int ks, int p) {
        afr[p][0] = *(const uint4*)(Aw0 + ks * 128);
        afr[p][1] = *(const uint4*)(Aw1 + ks * 128);
        #pragma unroll
        for (int nt = 0; nt < 8; ++nt)
            bfr[p][nt] = *(const uint2*)(Bw + ks * 8192 + nt * 64);
    };
    auto domma = [&](int p) {
        #pragma unroll
        for (int mt = 0; mt < 2; ++mt)
            #pragma unroll
            for (int nt = 0; nt < 8; ++nt)
                mma_tf32(acc[mt][nt], (const uint32_t*)&afr[p][mt], (const uint32_t*)&bfr[p][nt]);
    };

    ld(0, 0);
    #pragma unroll 4
    for (int ks = 0; ks < 64; ks += 2) {
        ld(ks + 1, 1);
        domma(0);
        if (ks + 2 < 64) ld(ks + 2, 0);
        domma(1);
    }

    if (qkvmode) {
        #pragma unroll
        for (int mt = 0; mt < 2; ++mt) {
            int o = ob + wm * 32 + mt * 16 + (lane >> 2);
            float b0 = __ldg(bias + o);
            float b1 = __ldg(bias + o + 8);
            #pragma unroll
            for (int nt = 0; nt < 8; ++nt) {
                int n = nb + wn * 64 + nt * 8 + (lane & 3) * 2;
                qkv_store(b, o,     n,     f2tf32(acc[mt][nt][0] + b0));
                qkv_store(b, o,     n + 1, f2tf32(acc[mt][nt][1] + b0));
                qkv_store(b, o + 8, n,     f2tf32(acc[mt][nt][2] + b1));
                qkv_store(b, o + 8, n + 1, f2tf32(acc[mt][nt][3] + b1));
            }
        }
    } else {
        #pragma unroll
        for (int mt = 0; mt < 2; ++mt) {
            int o = ob + wm * 32 + mt * 16 + (lane >> 2);
            float b0 = __ldg(bias + o);
            float b1 = __ldg(bias + o + 8);
            #pragma unroll
            for (int nt = 0; nt < 8; ++nt) {
                int n = nb + wn * 64 + nt * 8 + (lane & 3) * 2;
                size_t i0 = ((size_t)b * M + o) * Nn + n;
                size_t i1 = i0 + (size_t)8 * Nn;
                float2 v0 = make_float2(acc[mt][nt][0] + b0, acc[mt][nt][1] + b0);
                float2 v1 = make_float2(acc[mt][nt][2] + b1, acc[mt][nt][3] + b1);
                if (resid) {
                    float2 r0 = *(const float2*)(resid + i0);
                    float2 r1 = *(const float2*)(resid + i1);
                    v0.x += r0.x; v0.y += r0.y;
                    v1.x += r1.x; v1.y += r1.y;
                }
                *(float2*)(out + i0) = v0;
                *(float2*)(out + i1) = v1;
            }
        }
    }
}

// ---------------- flash attention: fragment-direct, cp.async double-buffered ----------------
// smem words: kbuf[2] @0/@4096, vbuf[2] @8192/@12288, ps @16384 (8 warps x 1088)
__global__ __launch_bounds__(256) void attn_mma() {
    const int b = blockIdx.z, h = blockIdx.y;
    const uint32_t* qa = g_qa + (size_t)(b * 8 + h) * 65536;
    const uint32_t* kb = g_kb + (size_t)(b * 8 + h) * 65536;
    const uint32_t* vb = g_vb + (size_t)(b * 8 + h) * 65536;

    extern __shared__ uint32_t smu[];
    const int tid = threadIdx.x, lane = tid & 31, w = tid >> 5;
    const int r = lane >> 2, c = lane & 3;
    uint32_t* pw = smu + 16384 + w * 1088;
    const uint32_t sbase = smem_u32(smu);

    // Q a-frags: one LDG.128 per k-tile
    uint4 aq[8];
    {
        const uint32_t* qp = qa + (size_t)(blockIdx.x * 8 + w) * 1024 + lane * 4;
        #pragma unroll
        for (int kd = 0; kd < 8; ++kd) aq[kd] = *(const uint4*)(qp + kd * 128);
    }

    auto stage = [&](int kt, int buf) {
        const uint32_t* kg = kb + (size_t)kt * 4096 + tid * 4;
        const uint32_t* vg = vb + (size_t)kt * 4096 + tid * 4;
        uint32_t ksm = sbase + (buf * 4096 + tid * 4) * 4;
        uint32_t vsm = sbase + (8192 + buf * 4096 + tid * 4) * 4;
        #pragma unroll
        for (int i = 0; i < 4; ++i) {
            cp16(ksm + i * 4096, kg + i * 1024);
            cp16(vsm + i * 4096, vg + i * 1024);
        }
        CP_COMMIT();
    };

    float oacc[8][4];
    #pragma unroll
    for (int j = 0; j < 8; ++j)
        #pragma unroll
        for (int i = 0; i < 4; ++i) oacc[j][i] = 0.f;
    float rm0 = -1e30f, rm1 = -1e30f, rs0 = 0.f, rs1 = 0.f;
    const float SCL = 0.125f * 1.4426950408889634f;

    stage(0, 0);
    CP_WAIT0();
    __syncthreads();

    for (int kt = 0; kt < 16; ++kt) {
        int cur = kt & 1;
        if (kt + 1 < 16) stage(kt + 1, cur ^ 1);

        const uint32_t* ksb = smu + cur * 4096;
        const uint32_t* vsb = smu + 8192 + cur * 4096;

        // S = Q K^T
        float sacc[8][4];
        #pragma unroll
        for (int j = 0; j < 8; ++j)
            #pragma unroll
            for (int i = 0; i < 4; ++i) sacc[j][i] = 0.f;
        #pragma unroll
        for (int k2 = 0; k2 < 8; ++k2) {
            uint2 bk[8];
            #pragma unroll
            for (int j = 0; j < 8; ++j)
                bk[j] = *(const uint2*)(ksb + k2 * 512 + (j * 8 + r) * 8 + 2 * c);
            #pragma unroll
            for (int j = 0; j < 8; ++j)
                mma_tf32(sacc[j], (const uint32_t*)&aq[k2], (const uint32_t*)&bk[j]);
        }

        // online softmax (rows r, r+8)
        float tm0 = -1e30f, tm1 = -1e30f;
        #pragma unroll
        for (int j = 0; j < 8; ++j) {
            sacc[j][0] *= SCL; sacc[j][1] *= SCL;
            sacc[j][2] *= SCL; sacc[j][3] *= SCL;
            tm0 = fmaxf(tm0, fmaxf(sacc[j][0], sacc[j][1]));
            tm1 = fmaxf(tm1, fmaxf(sacc[j][2], sacc[j][3]));
        }
        tm0 = fmaxf(tm0, __shfl_xor_sync(0xffffffffu, tm0, 1));
        tm0 = fmaxf(tm0, __shfl_xor_sync(0xffffffffu, tm0, 2));
        tm1 = fmaxf(tm1, __shfl_xor_sync(0xffffffffu, tm1, 1));
        tm1 = fmaxf(tm1, __shfl_xor_sync(0xffffffffu, tm1, 2));
        float nm0 = fmaxf(rm0, tm0), nm1 = fmaxf(rm1, tm1);
        float cr0 = fexp2(rm0 - nm0), cr1 = fexp2(rm1 - nm1);
        rm0 = nm0; rm1 = nm1;
        float ts0 = 0.f, ts1 = 0.f;
        #pragma unroll
        for (int j = 0; j < 8; ++j) {
            uint32_t p0 = f2tf32(fexp2(sacc[j][0] - nm0));
            uint32_t p1 = f2tf32(fexp2(sacc[j][1] - nm0));
            uint32_t p2 = f2tf32(fexp2(sacc[j][2] - nm1));
            uint32_t p3 = f2tf32(fexp2(sacc[j][3] - nm1));
            ts0 += __uint_as_float(p0) + __uint_as_float(p1);
            ts1 += __uint_as_float(p2) + __uint_as_float(p3);
            *(uint2*)(pw + r * 68 + j * 8 + 2 * c)       = make_uint2(p0, p1);
            *(uint2*)(pw + (r + 8) * 68 + j * 8 + 2 * c) = make_uint2(p2, p3);
            oacc[j][0] *= cr0; oacc[j][1] *= cr0;
            oacc[j][2] *= cr1; oacc[j][3] *= cr1;
        }
        ts0 += __shfl_xor_sync(0xffffffffu, ts0, 1);
        ts0 += __shfl_xor_sync(0xffffffffu, ts0, 2);
        ts1 += __shfl_xor_sync(0xffffffffu, ts1, 1);
        ts1 += __shfl_xor_sync(0xffffffffu, ts1, 2);
        rs0 = rs0 * cr0 + ts0;
        rs1 = rs1 * cr1 + ts1;
        __syncwarp();

        // O += P V
        #pragma unroll
        for (int ksq = 0; ksq < 8; ++ksq) {
            uint32_t ap4[4];
            ap4[0] = pw[r * 68 + ksq * 8 + c];
            ap4[1] = pw[(r + 8) * 68 + ksq * 8 + c];
            ap4[2] = pw[r * 68 + ksq * 8 + c + 4];
            ap4[3] = pw[(r + 8) * 68 + ksq * 8 + c + 4];
            #pragma unroll
            for (int j = 0; j < 8; ++j) {
                uint2 bv = *(const uint2*)(vsb + ksq * 512 + (j * 8 + r) * 8 + 2 * c);
                mma_tf32(oacc[j], ap4, (const uint32_t*)&bv);
            }
        }

        if (kt + 1 < 16) CP_WAIT0();
        __syncthreads();
    }

    // normalize, transpose to [d][128q], write b-frag layout for proj
    float inv0 = 1.f / rs0, inv1 = 1.f / rs1;
    float* os = (float*)smu;   // 64 x 128, reuses k/v buffers
    int q0 = w * 16 + r;
    #pragma unroll
    for (int j = 0; j < 8; ++j) {
        int d = j * 8 + 2 * c;
        os[d * 128 + q0]           = oacc[j][0] * inv0;
        os[(d + 1) * 128 + q0]     = oacc[j][1] * inv0;
        os[d * 128 + q0 + 8]       = oacc[j][2] * inv1;
        os[(d + 1) * 128 + q0 + 8] = oacc[j][3] * inv1;
    }
    __syncthreads();
    uint32_t* op = g_atb + ((size_t)b * 64 + h * 8) * 8192 + (size_t)(blockIdx.x * 128) * 8;
    #pragma unroll
    for (int rr = 0; rr < 8; ++rr) {
        int f = (tid + rr * 256) * 4;
        int cg = f >> 10, rem = f & 1023;
        int n = rem >> 3, j0 = rem & 7;
        uint32_t vv[4];
        #pragma unroll
        for (int i = 0; i < 4; ++i) {
            int j = j0 + i;
            int dl = cg * 8 + ((j >> 1) + ((j & 1) << 2));
            vv[i] = f2tf32(os[dl * 128 + n]);
        }
        *(uint4*)(op + (size_t)cg * 8192 + rem) = make_uint4(vv[0], vv[1], vv[2], vv[3]);
    }
}

// ---------------- launch ----------------
extern "C" void kernel_launch(void* const* d_in, const int* in_sizes, int n_in,
                              void* d_out, int out_size) {
    const float* x      = (const float*)d_in[0];
    const float* gamma  = (const float*)d_in[1];
    const float* beta   = (const float*)d_in[2];
    const float* w_qkv  = (const float*)d_in[3];
    const float* b_qkv  = (const float*)d_in[4];
    const float* w_proj = (const float*)d_in[5];
    const float* b_proj = (const float*)d_in[6];
    float* out = (float*)d_out;

    uint32_t *xb, *atb, *wA, *wP;
    cudaGetSymbolAddress((void**)&xb,  g_xb);
    cudaGetSymbolAddress((void**)&atb, g_atb);
    cudaGetSymbolAddress((void**)&wA,  g_wA);
    cudaGetSymbolAddress((void**)&wP,  g_wP);

    const int gn_smem   = 16 * 1024 * sizeof(float);          // 64 KB
    const int attn_smem = (16384 + 8704) * 4;                 // 100352 B
    cudaFuncSetAttribute(gn_kernel, cudaFuncAttributeMaxDynamicSharedMemorySize, gn_smem);
    cudaFuncSetAttribute(attn_mma,  cudaFuncAttributeMaxDynamicSharedMemorySize, attn_smem);

    wprep<<<3072, 256>>>(w_qkv, wA);
    wprep<<<1024, 256>>>(w_proj, wP);
    gn_kernel<<<256, 256, gn_smem>>>(x, gamma, beta);
    gemm_mma<<<dim3(8, 12, 8), 256>>>(wA, xb, b_qkv, nullptr, nullptr, 0, 1);
    attn_mma<<<dim3(8, NH, Bn), 256, attn_smem>>>();
    gemm_mma<<<dim3(8, 4, 8), 256>>>(wP, atb, b_proj, x, out, Cc, 0);
}

// round 9
// speedup vs baseline: 5.7598x; 1.4494x over previous
#include <cuda_runtime.h>
#include <math_constants.h>
#include <cstdint>

#define Bn 8
#define Cc 512
#define Nn 1024
#define NH 8
#define HD 64

// ---------------- scratch (device globals; no allocation) ----------------
// bf16x2 word layouts for mma.sync m16n8k16:
//  B-frag (X / atb): per b: [ks 32][n 1024][t 4] uint2 {b0 = {c0,c0+1}, b1 = {c0+8,c0+9}}, c0 = ks*16+2t
//  A-frag (W):       [mtile][ks 32][lane 32][reg 4], word = {W[o][c0], W[o][c0+1]}
//  Q a-frag:  per (b,h): [qtile 64][ksd 4][lane 32][reg 4]
//  K b-frag:  per (b,h): [kt 16][ksd 4][m 64][t 4][reg 2]
//  V b-frag:  per (b,h): [kt 16][ksm 4][d 64][t 4][reg 2]
__device__ uint32_t g_xb [Bn * 262144];      // 8 MB
__device__ uint32_t g_atb[Bn * 262144];      // 8 MB
__device__ uint32_t g_wA [96 * 32 * 128];    // 1.5 MB
__device__ uint32_t g_wP [32 * 32 * 128];    // 0.5 MB
__device__ uint32_t g_qa [Bn * NH * 32768];  // 8 MB
__device__ uint32_t g_kb [Bn * NH * 32768];  // 8 MB
__device__ uint32_t g_vb [Bn * NH * 32768];  // 8 MB

// ---------------- helpers ----------------
__device__ __forceinline__ uint32_t pack2(float lo, float hi) {
    uint32_t r;
    asm("cvt.rn.bf16x2.f32 %0, %1, %2;" : "=r"(r) : "f"(hi), "f"(lo));
    return r;
}
__device__ __forceinline__ void mma_bf16(float* d, const uint32_t* a, const uint32_t* b) {
    asm volatile(
        "mma.sync.aligned.m16n8k16.row.col.f32.bf16.bf16.f32 "
        "{%0,%1,%2,%3}, {%4,%5,%6,%7}, {%8,%9}, {%0,%1,%2,%3};"
        : "+f"(d[0]), "+f"(d[1]), "+f"(d[2]), "+f"(d[3])
        : "r"(a[0]), "r"(a[1]), "r"(a[2]), "r"(a[3]), "r"(b[0]), "r"(b[1]));
}
__device__ __forceinline__ float fexp2(float t) {
    t = fmaxf(t, -120.f);
    int ei = __float2int_rn(t);
    float f = t - (float)ei;
    float g = f * 0.6931471805599453f;
    float p = 8.3333337e-3f;
    p = fmaf(p, g, 4.1666668e-2f);
    p = fmaf(p, g, 0.16666667f);
    p = fmaf(p, g, 0.5f);
    p = fmaf(p, g, 1.0f);
    p = fmaf(p, g, 1.0f);
    return p * __int_as_float((ei + 127) << 23);
}
__device__ __forceinline__ uint32_t smem_u32(const void* p) {
    uint32_t a;
    asm("{ .reg .u64 t; cvta.to.shared.u64 t, %1; cvt.u32.u64 %0, t; }" : "=r"(a) : "l"(p));
    return a;
}
__device__ __forceinline__ void cp16(uint32_t saddr, const void* g) {
    asm volatile("cp.async.cg.shared.global [%0], [%1], 16;" :: "r"(saddr), "l"(g));
}
#define CP_COMMIT() asm volatile("cp.async.commit_group;")
#define CP_WAIT0()  asm volatile("cp.async.wait_group 0;")

// ---------------- weight prep: W[M][512] -> bf16 a-frag words ----------------
__global__ void wprep(const float* __restrict__ W, uint32_t* __restrict__ dst) {
    int e = blockIdx.x * 256 + threadIdx.x;     // word index
    int reg = e & 3, lane = (e >> 2) & 31, ks = (e >> 7) & 31, mtile = e >> 12;
    int r = lane >> 2, t = lane & 3;
    int o  = mtile * 16 + r + (reg & 1) * 8;
    int c0 = ks * 16 + 2 * t + (reg & 2) * 4;
    dst[e] = pack2(W[o * 512 + c0], W[o * 512 + c0 + 1]);
}

// ---------------- GroupNorm -> bf16 b-frag layout ----------------
__global__ void gn_kernel(const float* __restrict__ x,
                          const float* __restrict__ gamma,
                          const float* __restrict__ beta) {
    extern __shared__ float sx[];   // [16][1024]
    int b = blockIdx.x >> 5;
    int g = blockIdx.x & 31;        // group == ks (16 channels)
    const float* xp = x + ((size_t)b * Cc + g * 16) * Nn;
    int tid = threadIdx.x;

    float s = 0.f, s2 = 0.f;
    for (int i = tid * 4; i < 16384; i += 1024) {
        float4 v = *(const float4*)(xp + i);
        *(float4*)(sx + i) = v;
        s  += v.x + v.y + v.z + v.w;
        s2 += v.x * v.x + v.y * v.y + v.z * v.z + v.w * v.w;
    }
    for (int off = 16; off; off >>= 1) {
        s  += __shfl_xor_sync(0xffffffffu, s,  off);
        s2 += __shfl_xor_sync(0xffffffffu, s2, off);
    }
    __shared__ float sh[2][8];
    int w = tid >> 5;
    if ((tid & 31) == 0) { sh[0][w] = s; sh[1][w] = s2; }
    __syncthreads();
    if (tid < 32) {
        s  = (tid < 8) ? sh[0][tid] : 0.f;
        s2 = (tid < 8) ? sh[1][tid] : 0.f;
        for (int off = 4; off; off >>= 1) {
            s  += __shfl_xor_sync(0xffffffffu, s,  off);
            s2 += __shfl_xor_sync(0xffffffffu, s2, off);
        }
        if (tid == 0) { sh[0][0] = s; sh[1][0] = s2; }
    }
    __syncthreads();
    float mean = sh[0][0] * (1.f / 16384.f);
    float var  = sh[1][0] * (1.f / 16384.f) - mean * mean;
    float rstd = rsqrtf(var + 1e-5f);

    float ga[16], be[16];
    #pragma unroll
    for (int c = 0; c < 16; ++c) {
        float gg = __ldg(gamma + g * 16 + c) * rstd;
        ga[c] = gg;
        be[c] = __ldg(beta + g * 16 + c) - mean * gg;
    }

    uint32_t* op = g_xb + ((size_t)b * 32 + g) * 8192;
    #pragma unroll
    for (int rr = 0; rr < 4; ++rr) {
        int n = tid + rr * 256;
        float v[16];
        #pragma unroll
        for (int lc = 0; lc < 16; ++lc) v[lc] = sx[lc * 1024 + n] * ga[lc] + be[lc];
        uint4 A = make_uint4(pack2(v[0], v[1]), pack2(v[8],  v[9]),
                             pack2(v[2], v[3]), pack2(v[10], v[11]));
        uint4 B = make_uint4(pack2(v[4], v[5]), pack2(v[12], v[13]),
                             pack2(v[6], v[7]), pack2(v[14], v[15]));
        *(uint4*)(op + (size_t)n * 8)     = A;
        *(uint4*)(op + (size_t)n * 8 + 4) = B;
    }
}

// ---------------- bf16 mma GEMM, fragment-direct ----------------
// qkvmode=1: scatter outputs (bias added, bf16) to g_qa/g_kb/g_vb
// qkvmode=0: out[b,o,n] = bias + acc (+resid), fp32
__global__ __launch_bounds__(256, 2) void gemm_mma(
    const uint32_t* __restrict__ Amat, const uint32_t* __restrict__ Bmat,
    const float* __restrict__ bias, const float* __restrict__ resid,
    float* __restrict__ out, int M, int qkvmode)
{
    const int tid = threadIdx.x;
    const int lane = tid & 31;
    const int wid = tid >> 5;
    const int wm = wid & 3;
    const int wn = wid >> 2;
    const int nb = blockIdx.x * 128;
    const int ob = blockIdx.y * 128;
    const int b  = blockIdx.z;
    const int r = lane >> 2, c = lane & 3;

    const uint32_t* Aw0 = Amat + (size_t)((ob >> 4) + wm * 2)     * 4096 + lane * 4;
    const uint32_t* Aw1 = Amat + (size_t)((ob >> 4) + wm * 2 + 1) * 4096 + lane * 4;
    const uint32_t* Bw  = Bmat + (size_t)b * 262144
                        + (size_t)(nb + wn * 64 + r) * 8 + c * 2;

    float acc[2][8][4];
    #pragma unroll
    for (int mt = 0; mt < 2; ++mt)
        #pragma unroll
        for (int nt = 0; nt < 8; ++nt)
            #pragma unroll
            for (int q = 0; q < 4; ++q) acc[mt][nt][q] = 0.f;

    uint4 afr[2][2];
    uint2 bfr[2][8];

    auto ld = [&](int ks, int p) {
        afr[p][0] = *(const uint4*)(Aw0 + ks * 128);
        afr[p][1] = *(const uint4*)(Aw1 + ks * 128);
        #pragma unroll
        for (int nt = 0; nt < 8; ++nt)
            bfr[p][nt] = *(const uint2*)(Bw + ks * 8192 + nt * 64);
    };
    auto domma = [&](int p) {
        #pragma unroll
        for (int mt = 0; mt < 2; ++mt)
            #pragma unroll
            for (int nt = 0; nt < 8; ++nt)
                mma_bf16(acc[mt][nt], (const uint32_t*)&afr[p][mt], (const uint32_t*)&bfr[p][nt]);
    };

    ld(0, 0);
    #pragma unroll 4
    for (int ks = 0; ks < 32; ks += 2) {
        ld(ks + 1, 1);
        domma(0);
        if (ks + 2 < 32) ld(ks + 2, 0);
        domma(1);
    }

    if (qkvmode) {
        #pragma unroll
        for (int mt = 0; mt < 2; ++mt) {
            int o0 = ob + wm * 32 + mt * 16 + r;
            float b0 = __ldg(bias + o0);
            float b1 = __ldg(bias + o0 + 8);
            #pragma unroll
            for (int nt = 0; nt < 8; ++nt) {
                int n = nb + wn * 64 + nt * 8 + 2 * c;
                float v0 = acc[mt][nt][0] + b0, v1 = acc[mt][nt][1] + b0;
                float v2 = acc[mt][nt][2] + b1, v3 = acc[mt][nt][3] + b1;
                if (o0 < 1024) {   // Q or K: bf16 pairs run along d -> butterfly with r^1
                    float u0 = __shfl_xor_sync(0xffffffffu, v0, 4);
                    float u1 = __shfl_xor_sync(0xffffffffu, v1, 4);
                    float u2 = __shfl_xor_sync(0xffffffffu, v2, 4);
                    float u3 = __shfl_xor_sync(0xffffffffu, v3, 4);
                    if (!(r & 1)) {
                        uint32_t w0 = pack2(v0, u0), w1 = pack2(v1, u1);
                        uint32_t w2 = pack2(v2, u2), w3 = pack2(v3, u3);
                        if (o0 < 512) {        // Q a-frag
                            int h = o0 >> 6, d0 = o0 & 63, q = n;
                            int qt = q >> 4, q_in = q & 15;
                            int ksd = d0 >> 4, tp = (d0 & 15) >> 1;
                            int lane0 = (q_in & 7) * 4 + tp;
                            int rb = (q_in >> 3) & 1;
                            uint32_t* dst = g_qa
                                + ((size_t)((b * 8 + h) * 64 + qt) * 4 + ksd) * 128;
                            dst[lane0 * 4 + rb]           = w0;
                            dst[(lane0 + 4) * 4 + rb]     = w1;
                            dst[lane0 * 4 + rb + 2]       = w2;
                            dst[(lane0 + 4) * 4 + rb + 2] = w3;
                        } else {               // K b-frag
                            int oh = o0 - 512;
                            int h = oh >> 6, d0 = oh & 63, m = n;
                            int kt = m >> 6, m_in = m & 63;
                            int ksd = d0 >> 4, t = (d0 & 15) >> 1;
                            uint32_t* dst = g_kb
                                + ((size_t)((b * 8 + h) * 16 + kt) * 4 + ksd) * 512;
                            dst[m_in * 8 + t * 2]           = w0;
                            dst[(m_in + 1) * 8 + t * 2]     = w1;
                            dst[m_in * 8 + t * 2 + 1]       = w2;
                            dst[(m_in + 1) * 8 + t * 2 + 1] = w3;
                        }
                    }
                } else {           // V: bf16 pairs along m -> in-thread
                    int oh = o0 - 1024;
                    int h = oh >> 6, d = oh & 63, m = n;
                    int kt = m >> 6;
                    int ksm = nt >> 1;
                    int tr = c * 2 + (nt & 1);
                    uint32_t w0 = pack2(v0, v1);
                    uint32_t w1 = pack2(v2, v3);
                    uint32_t* dst = g_vb
                        + ((size_t)((b * 8 + h) * 16 + kt) * 4 + ksm) * 512;
                    dst[d * 8 + tr]       = w0;
                    dst[(d + 8) * 8 + tr] = w1;
                }
            }
        }
    } else {
        #pragma unroll
        for (int mt = 0; mt < 2; ++mt) {
            int o = ob + wm * 32 + mt * 16 + r;
            float b0 = __ldg(bias + o);
            float b1 = __ldg(bias + o + 8);
            #pragma unroll
            for (int nt = 0; nt < 8; ++nt) {
                int n = nb + wn * 64 + nt * 8 + 2 * c;
                size_t i0 = ((size_t)b * M + o) * Nn + n;
                size_t i1 = i0 + (size_t)8 * Nn;
                float2 v0 = make_float2(acc[mt][nt][0] + b0, acc[mt][nt][1] + b0);
                float2 v1 = make_float2(acc[mt][nt][2] + b1, acc[mt][nt][3] + b1);
                if (resid) {
                    float2 r0 = *(const float2*)(resid + i0);
                    float2 r1 = *(const float2*)(resid + i1);
                    v0.x += r0.x; v0.y += r0.y;
                    v1.x += r1.x; v1.y += r1.y;
                }
                *(float2*)(out + i0) = v0;
                *(float2*)(out + i1) = v1;
            }
        }
    }
}

// ---------------- flash attention, bf16 m16n8k16, cp.async double-buffered ----------------
// smem words: kbuf[2] @0/@2048, vbuf[2] @4096/@6144, ps @8192 (8 warps x 512) = 12288 words
__global__ __launch_bounds__(256) void attn_mma() {
    const int b = blockIdx.z, h = blockIdx.y;
    const uint32_t* qa = g_qa + (size_t)(b * 8 + h) * 32768;
    const uint32_t* kb = g_kb + (size_t)(b * 8 + h) * 32768;
    const uint32_t* vb = g_vb + (size_t)(b * 8 + h) * 32768;

    extern __shared__ uint32_t smu[];
    const int tid = threadIdx.x, lane = tid & 31, w = tid >> 5;
    const int r = lane >> 2, c = lane & 3;
    uint32_t* pw = smu + 8192 + w * 512;
    const uint32_t sbase = smem_u32(smu);

    // Q a-frags: 4 x LDG.128 per warp
    uint4 aq[4];
    {
        const uint32_t* qp = qa + (size_t)(blockIdx.x * 8 + w) * 512 + lane * 4;
        #pragma unroll
        for (int ks = 0; ks < 4; ++ks) aq[ks] = *(const uint4*)(qp + ks * 128);
    }

    auto stage = [&](int kt, int buf) {
        const uint32_t* kg = kb + (size_t)kt * 2048 + tid * 8;
        const uint32_t* vg = vb + (size_t)kt * 2048 + tid * 8;
        uint32_t ksm = sbase + (buf * 2048 + tid * 8) * 4;
        uint32_t vsm = sbase + (4096 + buf * 2048 + tid * 8) * 4;
        cp16(ksm,      kg);
        cp16(ksm + 16, kg + 4);
        cp16(vsm,      vg);
        cp16(vsm + 16, vg + 4);
        CP_COMMIT();
    };

    float oacc[8][4];
    #pragma unroll
    for (int j = 0; j < 8; ++j)
        #pragma unroll
        for (int i = 0; i < 4; ++i) oacc[j][i] = 0.f;
    float rm0 = -1e30f, rm1 = -1e30f, rs0 = 0.f, rs1 = 0.f;
    const float SCL = 0.125f * 1.4426950408889634f;

    stage(0, 0);
    CP_WAIT0();
    __syncthreads();

    for (int kt = 0; kt < 16; ++kt) {
        int cur = kt & 1;
        if (kt + 1 < 16) stage(kt + 1, cur ^ 1);

        const uint32_t* ksb = smu + cur * 2048;
        const uint32_t* vsb = smu + 4096 + cur * 2048;

        // S = Q K^T  (4 k16-steps)
        float sacc[8][4];
        #pragma unroll
        for (int j = 0; j < 8; ++j)
            #pragma unroll
            for (int i = 0; i < 4; ++i) sacc[j][i] = 0.f;
        #pragma unroll
        for (int ks = 0; ks < 4; ++ks) {
            uint2 bk[8];
            #pragma unroll
            for (int j = 0; j < 8; ++j)
                bk[j] = *(const uint2*)(ksb + ks * 512 + (j * 8 + r) * 8 + c * 2);
            #pragma unroll
            for (int j = 0; j < 8; ++j)
                mma_bf16(sacc[j], (const uint32_t*)&aq[ks], (const uint32_t*)&bk[j]);
        }

        // online softmax (rows r, r+8)
        float tm0 = -1e30f, tm1 = -1e30f;
        #pragma unroll
        for (int j = 0; j < 8; ++j) {
            sacc[j][0] *= SCL; sacc[j][1] *= SCL;
            sacc[j][2] *= SCL; sacc[j][3] *= SCL;
            tm0 = fmaxf(tm0, fmaxf(sacc[j][0], sacc[j][1]));
            tm1 = fmaxf(tm1, fmaxf(sacc[j][2], sacc[j][3]));
        }
        tm0 = fmaxf(tm0, __shfl_xor_sync(0xffffffffu, tm0, 1));
        tm0 = fmaxf(tm0, __shfl_xor_sync(0xffffffffu, tm0, 2));
        tm1 = fmaxf(tm1, __shfl_xor_sync(0xffffffffu, tm1, 1));
        tm1 = fmaxf(tm1, __shfl_xor_sync(0xffffffffu, tm1, 2));
        float nm0 = fmaxf(rm0, tm0), nm1 = fmaxf(rm1, tm1);
        float cr0 = fexp2(rm0 - nm0), cr1 = fexp2(rm1 - nm1);
        rm0 = nm0; rm1 = nm1;
        float ts0 = 0.f, ts1 = 0.f;
        #pragma unroll
        for (int j = 0; j < 8; ++j) {
            float e0 = fexp2(sacc[j][0] - nm0);
            float e1 = fexp2(sacc[j][1] - nm0);
            float e2 = fexp2(sacc[j][2] - nm1);
            float e3 = fexp2(sacc[j][3] - nm1);
            ts0 += e0 + e1;
            ts1 += e2 + e3;
            // P a-frag: pairs along m are in-thread; store uint2 {reg (j&1)*2, +1}
            uint2 pword = make_uint2(pack2(e0, e1), pack2(e2, e3));
            *(uint2*)(pw + (((j >> 1) * 32 + lane) * 4 + (j & 1) * 2)) = pword;
            oacc[j][0] *= cr0; oacc[j][1] *= cr0;
            oacc[j][2] *= cr1; oacc[j][3] *= cr1;
        }
        ts0 += __shfl_xor_sync(0xffffffffu, ts0, 1);
        ts0 += __shfl_xor_sync(0xffffffffu, ts0, 2);
        ts1 += __shfl_xor_sync(0xffffffffu, ts1, 1);
        ts1 += __shfl_xor_sync(0xffffffffu, ts1, 2);
        rs0 = rs0 * cr0 + ts0;
        rs1 = rs1 * cr1 + ts1;
        __syncwarp();

        // O += P V  (4 k16-steps, P a-frag = one LDS.128)
        #pragma unroll
        for (int ks = 0; ks < 4; ++ks) {
            uint4 ap = *(const uint4*)(pw + (ks * 32 + lane) * 4);
            #pragma unroll
            for (int j = 0; j < 8; ++j) {
                uint2 bv = *(const uint2*)(vsb + ks * 512 + (j * 8 + r) * 8 + c * 2);
                mma_bf16(oacc[j], (const uint32_t*)&ap, (const uint32_t*)&bv);
            }
        }

        if (kt + 1 < 16) CP_WAIT0();
        __syncthreads();
    }

    // normalize, transpose via smem (stride 132), write bf16 b-frag for proj
    float inv0 = 1.f / rs0, inv1 = 1.f / rs1;
    float* os = (float*)smu;   // 64 x 132 floats = 8448 words
    int q0 = w * 16 + r;
    #pragma unroll
    for (int j = 0; j < 8; ++j) {
        int d = j * 8 + 2 * c;
        os[d * 132 + q0]           = oacc[j][0] * inv0;
        os[(d + 1) * 132 + q0]     = oacc[j][1] * inv0;
        os[d * 132 + q0 + 8]       = oacc[j][2] * inv1;
        os[(d + 1) * 132 + q0 + 8] = oacc[j][3] * inv1;
    }
    __syncthreads();
    const int qbase = blockIdx.x * 128;
    #pragma unroll
    for (int rr = 0; rr < 8; ++rr) {
        int f = tid + rr * 256;                 // 2048 uint2 words total
        int t = f & 3, nl = (f >> 2) & 127, ksl = f >> 9;
        int c0 = ksl * 16 + 2 * t;
        uint2 wv;
        wv.x = pack2(os[c0 * 132 + nl],       os[(c0 + 1) * 132 + nl]);
        wv.y = pack2(os[(c0 + 8) * 132 + nl], os[(c0 + 9) * 132 + nl]);
        *(uint2*)(g_atb + ((size_t)b * 32 + h * 4 + ksl) * 8192
                  + (size_t)(qbase + nl) * 8 + t * 2) = wv;
    }
}

// ---------------- launch ----------------
extern "C" void kernel_launch(void* const* d_in, const int* in_sizes, int n_in,
                              void* d_out, int out_size) {
    const float* x      = (const float*)d_in[0];
    const float* gamma  = (const float*)d_in[1];
    const float* beta   = (const float*)d_in[2];
    const float* w_qkv  = (const float*)d_in[3];
    const float* b_qkv  = (const float*)d_in[4];
    const float* w_proj = (const float*)d_in[5];
    const float* b_proj = (const float*)d_in[6];
    float* out = (float*)d_out;

    uint32_t *xb, *atb, *wA, *wP;
    cudaGetSymbolAddress((void**)&xb,  g_xb);
    cudaGetSymbolAddress((void**)&atb, g_atb);
    cudaGetSymbolAddress((void**)&wA,  g_wA);
    cudaGetSymbolAddress((void**)&wP,  g_wP);

    const int gn_smem   = 16 * 1024 * sizeof(float);   // 64 KB
    const int attn_smem = 12288 * 4;                   // 49152 B
    cudaFuncSetAttribute(gn_kernel, cudaFuncAttributeMaxDynamicSharedMemorySize, gn_smem);
    cudaFuncSetAttribute(attn_mma,  cudaFuncAttributeMaxDynamicSharedMemorySize, attn_smem);

    wprep<<<1536, 256>>>(w_qkv, wA);    // 96 mtiles * 32 ks * 128 = 393216 words
    wprep<<<512,  256>>>(w_proj, wP);   // 32 * 32 * 128 = 131072 words
    gn_kernel<<<256, 256, gn_smem>>>(x, gamma, beta);
    gemm_mma<<<dim3(8, 12, 8), 256>>>(wA, xb, b_qkv, nullptr, nullptr, 0, 1);
    attn_mma<<<dim3(8, NH, Bn), 256, attn_smem>>>();
    gemm_mma<<<dim3(8, 4, 8), 256>>>(wP, atb, b_proj, x, out, Cc, 0);
}

// round 10
// speedup vs baseline: 7.3405x; 1.2744x over previous
#include <cuda_runtime.h>
#include <math_constants.h>
#include <cstdint>

#define Bn 8
#define Cc 512
#define Nn 1024
#define NH 8
#define HD 64

// ---------------- scratch (device globals; no allocation) ----------------
// bf16x2 word layouts for mma.sync m16n8k16 (same as round 9):
//  B-frag (X / atb): per b: [ks 32][n 1024][t 4] uint2
//  A-frag (W):       [mtile][ks 32][lane 32][reg 4]
//  Q a-frag:  per (b,h): [qtile 64][ksd 4][lane 32][reg 4]   (pre-scaled by hd^-.5*log2e)
//  K b-frag:  per (b,h): [kt 16][ksd 4][m 64][t 4][reg 2]
//  V b-frag:  per (b,h): [kt 16][ksm 4][d 64][t 4][reg 2]
__device__ uint32_t g_xb [Bn * 262144];      // 8 MB
__device__ uint32_t g_atb[Bn * 262144];      // 8 MB
__device__ uint32_t g_wA [96 * 32 * 128];    // 1.5 MB
__device__ uint32_t g_wP [32 * 32 * 128];    // 0.5 MB
__device__ uint32_t g_qa [Bn * NH * 32768];  // 8 MB
__device__ uint32_t g_kb [Bn * NH * 32768];  // 8 MB
__device__ uint32_t g_vb [Bn * NH * 32768];  // 8 MB

// ---------------- helpers ----------------
__device__ __forceinline__ uint32_t pack2(float lo, float hi) {
    uint32_t r;
    asm("cvt.rn.bf16x2.f32 %0, %1, %2;" : "=r"(r) : "f"(hi), "f"(lo));
    return r;
}
__device__ __forceinline__ void mma_bf16(float* d, const uint32_t* a, const uint32_t* b) {
    asm volatile(
        "mma.sync.aligned.m16n8k16.row.col.f32.bf16.bf16.f32 "
        "{%0,%1,%2,%3}, {%4,%5,%6,%7}, {%8,%9}, {%0,%1,%2,%3};"
        : "+f"(d[0]), "+f"(d[1]), "+f"(d[2]), "+f"(d[3])
        : "r"(a[0]), "r"(a[1]), "r"(a[2]), "r"(a[3]), "r"(b[0]), "r"(b[1]));
}
// MUFU exp2 — 1 issue slot, off the FMA pipe
__device__ __forceinline__ float fexp2(float t) {
    float r;
    asm("ex2.approx.ftz.f32 %0, %1;" : "=f"(r) : "f"(t));
    return r;
}
__device__ __forceinline__ uint32_t smem_u32(const void* p) {
    uint32_t a;
    asm("{ .reg .u64 t; cvta.to.shared.u64 t, %1; cvt.u32.u64 %0, t; }" : "=r"(a) : "l"(p));
    return a;
}
__device__ __forceinline__ void cp16(uint32_t saddr, const void* g) {
    asm volatile("cp.async.cg.shared.global [%0], [%1], 16;" :: "r"(saddr), "l"(g));
}
#define CP_COMMIT() asm volatile("cp.async.commit_group;")
#define CP_WAIT(n)  asm volatile("cp.async.wait_group %0;" :: "n"(n))

#define QSCL 0.1803368801111204f   /* 0.125 * log2(e) */

// ---------------- weight prep: W[M][512] -> bf16 a-frag words ----------------
__global__ void wprep(const float* __restrict__ W, uint32_t* __restrict__ dst) {
    int e = blockIdx.x * 256 + threadIdx.x;     // word index
    int reg = e & 3, lane = (e >> 2) & 31, ks = (e >> 7) & 31, mtile = e >> 12;
    int r = lane >> 2, t = lane & 3;
    int o  = mtile * 16 + r + (reg & 1) * 8;
    int c0 = ks * 16 + 2 * t + (reg & 2) * 4;
    dst[e] = pack2(W[o * 512 + c0], W[o * 512 + c0 + 1]);
}

// ---------------- GroupNorm -> bf16 b-frag layout ----------------
__global__ void gn_kernel(const float* __restrict__ x,
                          const float* __restrict__ gamma,
                          const float* __restrict__ beta) {
    extern __shared__ float sx[];   // [16][1024]
    int b = blockIdx.x >> 5;
    int g = blockIdx.x & 31;        // group == ks (16 channels)
    const float* xp = x + ((size_t)b * Cc + g * 16) * Nn;
    int tid = threadIdx.x;

    float s = 0.f, s2 = 0.f;
    for (int i = tid * 4; i < 16384; i += 1024) {
        float4 v = *(const float4*)(xp + i);
        *(float4*)(sx + i) = v;
        s  += v.x + v.y + v.z + v.w;
        s2 += v.x * v.x + v.y * v.y + v.z * v.z + v.w * v.w;
    }
    for (int off = 16; off; off >>= 1) {
        s  += __shfl_xor_sync(0xffffffffu, s,  off);
        s2 += __shfl_xor_sync(0xffffffffu, s2, off);
    }
    __shared__ float sh[2][8];
    int w = tid >> 5;
    if ((tid & 31) == 0) { sh[0][w] = s; sh[1][w] = s2; }
    __syncthreads();
    if (tid < 32) {
        s  = (tid < 8) ? sh[0][tid] : 0.f;
        s2 = (tid < 8) ? sh[1][tid] : 0.f;
        for (int off = 4; off; off >>= 1) {
            s  += __shfl_xor_sync(0xffffffffu, s,  off);
            s2 += __shfl_xor_sync(0xffffffffu, s2, off);
        }
        if (tid == 0) { sh[0][0] = s; sh[1][0] = s2; }
    }
    __syncthreads();
    float mean = sh[0][0] * (1.f / 16384.f);
    float var  = sh[1][0] * (1.f / 16384.f) - mean * mean;
    float rstd = rsqrtf(var + 1e-5f);

    float ga[16], be[16];
    #pragma unroll
    for (int c = 0; c < 16; ++c) {
        float gg = __ldg(gamma + g * 16 + c) * rstd;
        ga[c] = gg;
        be[c] = __ldg(beta + g * 16 + c) - mean * gg;
    }

    uint32_t* op = g_xb + ((size_t)b * 32 + g) * 8192;
    #pragma unroll
    for (int rr = 0; rr < 4; ++rr) {
        int n = tid + rr * 256;
        float v[16];
        #pragma unroll
        for (int lc = 0; lc < 16; ++lc) v[lc] = sx[lc * 1024 + n] * ga[lc] + be[lc];
        uint4 A = make_uint4(pack2(v[0], v[1]), pack2(v[8],  v[9]),
                             pack2(v[2], v[3]), pack2(v[10], v[11]));
        uint4 B = make_uint4(pack2(v[4], v[5]), pack2(v[12], v[13]),
                             pack2(v[6], v[7]), pack2(v[14], v[15]));
        *(uint4*)(op + (size_t)n * 8)     = A;
        *(uint4*)(op + (size_t)n * 8 + 4) = B;
    }
}

// ---------------- bf16 mma GEMM: A reg-prefetch x4, B cp.async 4-stage smem ----------------
// qkvmode=1: scatter outputs (bias added, bf16, Q pre-scaled) to g_qa/g_kb/g_vb
// qkvmode=0: out[b,o,n] = bias + acc (+resid), fp32
__global__ __launch_bounds__(256, 2) void gemm_mma(
    const uint32_t* __restrict__ Amat, const uint32_t* __restrict__ Bmat,
    const float* __restrict__ bias, const float* __restrict__ resid,
    float* __restrict__ out, int M, int qkvmode)
{
    extern __shared__ uint32_t bsm[];   // 4 stages x 1024 words = 16 KB
    const int tid = threadIdx.x;
    const int lane = tid & 31;
    const int wid = tid >> 5;
    const int wm = wid & 3;
    const int wn = wid >> 2;
    const int nb = blockIdx.x * 128;
    const int ob = blockIdx.y * 128;
    const int b  = blockIdx.z;
    const int r = lane >> 2, c = lane & 3;

    const uint32_t* Aw = Amat + (size_t)((ob >> 4) + wm * 2) * 4096 + lane * 4;
    const uint32_t* Bg = Bmat + (size_t)b * 262144 + (size_t)nb * 8 + tid * 4;
    const uint32_t sb = smem_u32(bsm);
    const uint32_t* bwarp = bsm + wn * 512 + r * 8 + c * 2;

    float acc[2][8][4];
    #pragma unroll
    for (int mt = 0; mt < 2; ++mt)
        #pragma unroll
        for (int nt = 0; nt < 8; ++nt)
            #pragma unroll
            for (int q = 0; q < 4; ++q) acc[mt][nt][q] = 0.f;

    uint4 afr[4][2];
    auto lda = [&](int ks, int slot) {
        afr[slot][0] = *(const uint4*)(Aw + ks * 128);
        afr[slot][1] = *(const uint4*)(Aw + 4096 + ks * 128);
    };
    auto bstage = [&](int ks) {
        cp16(sb + (((ks & 3) << 10) + tid * 4) * 4, Bg + (size_t)ks * 8192);
    };

    // prologue: 3 B stages in flight, 3 A slots loaded
    bstage(0); CP_COMMIT();
    bstage(1); CP_COMMIT();
    bstage(2); CP_COMMIT();
    lda(0, 0); lda(1, 1); lda(2, 2);
    CP_WAIT(2);
    __syncthreads();

    #pragma unroll 4
    for (int ks = 0; ks < 32; ++ks) {
        const int slot = ks & 3;
        // stage ks is ready+visible (prev iteration's wait+barrier)
        uint2 bfr[8];
        #pragma unroll
        for (int nt = 0; nt < 8; ++nt)
            bfr[nt] = *(const uint2*)(bwarp + (slot << 10) + nt * 64);
        // refill slot (ks-1)%4: all warps finished it before last barrier
        if (ks + 3 < 32) bstage(ks + 3);
        CP_COMMIT();
        #pragma unroll
        for (int mt = 0; mt < 2; ++mt)
            #pragma unroll
            for (int nt = 0; nt < 8; ++nt)
                mma_bf16(acc[mt][nt], (const uint32_t*)&afr[slot][mt],
                         (const uint32_t*)&bfr[nt]);
        if (ks + 3 < 32) lda(ks + 3, (ks + 3) & 3);
        CP_WAIT(2);        // stage ks+1 done
        __syncthreads();   // visible to all warps; reads of stage ks finished
    }

    if (qkvmode) {
        #pragma unroll
        for (int mt = 0; mt < 2; ++mt) {
            int o0 = ob + wm * 32 + mt * 16 + r;
            float b0 = __ldg(bias + o0);
            float b1 = __ldg(bias + o0 + 8);
            #pragma unroll
            for (int nt = 0; nt < 8; ++nt) {
                int n = nb + wn * 64 + nt * 8 + 2 * c;
                float v0 = acc[mt][nt][0] + b0, v1 = acc[mt][nt][1] + b0;
                float v2 = acc[mt][nt][2] + b1, v3 = acc[mt][nt][3] + b1;
                if (o0 < 1024) {   // Q or K: pairs along d -> butterfly
                    if (o0 < 512) { v0 *= QSCL; v1 *= QSCL; v2 *= QSCL; v3 *= QSCL; }
                    float u0 = __shfl_xor_sync(0xffffffffu, v0, 4);
                    float u1 = __shfl_xor_sync(0xffffffffu, v1, 4);
                    float u2 = __shfl_xor_sync(0xffffffffu, v2, 4);
                    float u3 = __shfl_xor_sync(0xffffffffu, v3, 4);
                    if (!(r & 1)) {
                        uint32_t w0 = pack2(v0, u0), w1 = pack2(v1, u1);
                        uint32_t w2 = pack2(v2, u2), w3 = pack2(v3, u3);
                        if (o0 < 512) {        // Q a-frag
                            int h = o0 >> 6, d0 = o0 & 63, q = n;
                            int qt = q >> 4, q_in = q & 15;
                            int ksd = d0 >> 4, tp = (d0 & 15) >> 1;
                            int lane0 = (q_in & 7) * 4 + tp;
                            int rb = (q_in >> 3) & 1;
                            uint32_t* dst = g_qa
                                + ((size_t)((b * 8 + h) * 64 + qt) * 4 + ksd) * 128;
                            dst[lane0 * 4 + rb]           = w0;
                            dst[(lane0 + 4) * 4 + rb]     = w1;
                            dst[lane0 * 4 + rb + 2]       = w2;
                            dst[(lane0 + 4) * 4 + rb + 2] = w3;
                        } else {               // K b-frag
                            int oh = o0 - 512;
                            int h = oh >> 6, d0 = oh & 63, m = n;
                            int kt = m >> 6, m_in = m & 63;
                            int ksd = d0 >> 4, t = (d0 & 15) >> 1;
                            uint32_t* dst = g_kb
                                + ((size_t)((b * 8 + h) * 16 + kt) * 4 + ksd) * 512;
                            dst[m_in * 8 + t * 2]           = w0;
                            dst[(m_in + 1) * 8 + t * 2]     = w1;
                            dst[m_in * 8 + t * 2 + 1]       = w2;
                            dst[(m_in + 1) * 8 + t * 2 + 1] = w3;
                        }
                    }
                } else {           // V: pairs along m -> in-thread
                    int oh = o0 - 1024;
                    int h = oh >> 6, d = oh & 63, m = n;
                    int kt = m >> 6;
                    int ksm = nt >> 1;
                    int tr = c * 2 + (nt & 1);
                    uint32_t w0 = pack2(v0, v1);
                    uint32_t w1 = pack2(v2, v3);
                    uint32_t* dst = g_vb
                        + ((size_t)((b * 8 + h) * 16 + kt) * 4 + ksm) * 512;
                    dst[d * 8 + tr]       = w0;
                    dst[(d + 8) * 8 + tr] = w1;
                }
            }
        }
    } else {
        #pragma unroll
        for (int mt = 0; mt < 2; ++mt) {
            int o = ob + wm * 32 + mt * 16 + r;
            float b0 = __ldg(bias + o);
            float b1 = __ldg(bias + o + 8);
            #pragma unroll
            for (int nt = 0; nt < 8; ++nt) {
                int n = nb + wn * 64 + nt * 8 + 2 * c;
                size_t i0 = ((size_t)b * M + o) * Nn + n;
                size_t i1 = i0 + (size_t)8 * Nn;
                float2 v0 = make_float2(acc[mt][nt][0] + b0, acc[mt][nt][1] + b0);
                float2 v1 = make_float2(acc[mt][nt][2] + b1, acc[mt][nt][3] + b1);
                if (resid) {
                    float2 r0 = *(const float2*)(resid + i0);
                    float2 r1 = *(const float2*)(resid + i1);
                    v0.x += r0.x; v0.y += r0.y;
                    v1.x += r1.x; v1.y += r1.y;
                }
                *(float2*)(out + i0) = v0;
                *(float2*)(out + i1) = v1;
            }
        }
    }
}

// ---------------- flash attention, bf16 m16n8k16, cp.async double-buffered ----------------
// smem words: kbuf[2] @0/@2048, vbuf[2] @4096/@6144, ps @8192 (8 warps x 512) = 12288 words
__global__ __launch_bounds__(256) void attn_mma() {
    const int b = blockIdx.z, h = blockIdx.y;
    const uint32_t* qa = g_qa + (size_t)(b * 8 + h) * 32768;
    const uint32_t* kb = g_kb + (size_t)(b * 8 + h) * 32768;
    const uint32_t* vb = g_vb + (size_t)(b * 8 + h) * 32768;

    extern __shared__ uint32_t smu[];
    const int tid = threadIdx.x, lane = tid & 31, w = tid >> 5;
    const int r = lane >> 2, c = lane & 3;
    uint32_t* pw = smu + 8192 + w * 512;
    const uint32_t sbase = smem_u32(smu);

    // Q a-frags: 4 x LDG.128 per warp (pre-scaled by QSCL in QKV epilogue)
    uint4 aq[4];
    {
        const uint32_t* qp = qa + (size_t)(blockIdx.x * 8 + w) * 512 + lane * 4;
        #pragma unroll
        for (int ks = 0; ks < 4; ++ks) aq[ks] = *(const uint4*)(qp + ks * 128);
    }

    auto stage = [&](int kt, int buf) {
        const uint32_t* kg = kb + (size_t)kt * 2048 + tid * 8;
        const uint32_t* vg = vb + (size_t)kt * 2048 + tid * 8;
        uint32_t ksm = sbase + (buf * 2048 + tid * 8) * 4;
        uint32_t vsm = sbase + (4096 + buf * 2048 + tid * 8) * 4;
        cp16(ksm,      kg);
        cp16(ksm + 16, kg + 4);
        cp16(vsm,      vg);
        cp16(vsm + 16, vg + 4);
        CP_COMMIT();
    };

    float oacc[8][4];
    #pragma unroll
    for (int j = 0; j < 8; ++j)
        #pragma unroll
        for (int i = 0; i < 4; ++i) oacc[j][i] = 0.f;
    float rm0 = -1e30f, rm1 = -1e30f, rs0 = 0.f, rs1 = 0.f;

    stage(0, 0);
    CP_WAIT(0);
    __syncthreads();

    for (int kt = 0; kt < 16; ++kt) {
        int cur = kt & 1;
        if (kt + 1 < 16) stage(kt + 1, cur ^ 1);

        const uint32_t* ksb = smu + cur * 2048;
        const uint32_t* vsb = smu + 4096 + cur * 2048;

        // S = Q K^T  (4 k16-steps) — already scaled via Q
        float sacc[8][4];
        #pragma unroll
        for (int j = 0; j < 8; ++j)
            #pragma unroll
            for (int i = 0; i < 4; ++i) sacc[j][i] = 0.f;
        #pragma unroll
        for (int ks = 0; ks < 4; ++ks) {
            uint2 bk[8];
            #pragma unroll
            for (int j = 0; j < 8; ++j)
                bk[j] = *(const uint2*)(ksb + ks * 512 + (j * 8 + r) * 8 + c * 2);
            #pragma unroll
            for (int j = 0; j < 8; ++j)
                mma_bf16(sacc[j], (const uint32_t*)&aq[ks], (const uint32_t*)&bk[j]);
        }

        // online softmax (rows r, r+8) — MUFU exp2
        float tm0 = -1e30f, tm1 = -1e30f;
        #pragma unroll
        for (int j = 0; j < 8; ++j) {
            tm0 = fmaxf(tm0, fmaxf(sacc[j][0], sacc[j][1]));
            tm1 = fmaxf(tm1, fmaxf(sacc[j][2], sacc[j][3]));
        }
        tm0 = fmaxf(tm0, __shfl_xor_sync(0xffffffffu, tm0, 1));
        tm0 = fmaxf(tm0, __shfl_xor_sync(0xffffffffu, tm0, 2));
        tm1 = fmaxf(tm1, __shfl_xor_sync(0xffffffffu, tm1, 1));
        tm1 = fmaxf(tm1, __shfl_xor_sync(0xffffffffu, tm1, 2));
        float nm0 = fmaxf(rm0, tm0), nm1 = fmaxf(rm1, tm1);
        float cr0 = fexp2(rm0 - nm0), cr1 = fexp2(rm1 - nm1);
        rm0 = nm0; rm1 = nm1;
        float ts0 = 0.f, ts1 = 0.f;
        #pragma unroll
        for (int j = 0; j < 8; ++j) {
            float e0 = fexp2(sacc[j][0] - nm0);
            float e1 = fexp2(sacc[j][1] - nm0);
            float e2 = fexp2(sacc[j][2] - nm1);
            float e3 = fexp2(sacc[j][3] - nm1);
            ts0 += e0 + e1;
            ts1 += e2 + e3;
            uint2 pword = make_uint2(pack2(e0, e1), pack2(e2, e3));
            *(uint2*)(pw + (((j >> 1) * 32 + lane) * 4 + (j & 1) * 2)) = pword;
            oacc[j][0] *= cr0; oacc[j][1] *= cr0;
            oacc[j][2] *= cr1; oacc[j][3] *= cr1;
        }
        ts0 += __shfl_xor_sync(0xffffffffu, ts0, 1);
        ts0 += __shfl_xor_sync(0xffffffffu, ts0, 2);
        ts1 += __shfl_xor_sync(0xffffffffu, ts1, 1);
        ts1 += __shfl_xor_sync(0xffffffffu, ts1, 2);
        rs0 = rs0 * cr0 + ts0;
        rs1 = rs1 * cr1 + ts1;
        __syncwarp();

        // O += P V  (4 k16-steps, P a-frag = one LDS.128)
        #pragma unroll
        for (int ks = 0; ks < 4; ++ks) {
            uint4 ap = *(const uint4*)(pw + (ks * 32 + lane) * 4);
            #pragma unroll
            for (int j = 0; j < 8; ++j) {
                uint2 bv = *(const uint2*)(vsb + ks * 512 + (j * 8 + r) * 8 + c * 2);
                mma_bf16(oacc[j], (const uint32_t*)&ap, (const uint32_t*)&bv);
            }
        }

        if (kt + 1 < 16) CP_WAIT(0);
        __syncthreads();
    }

    // normalize, transpose via smem (stride 132), write bf16 b-frag for proj
    float inv0 = 1.f / rs0, inv1 = 1.f / rs1;
    float* os = (float*)smu;   // 64 x 132 floats
    int q0 = w * 16 + r;
    #pragma unroll
    for (int j = 0; j < 8; ++j) {
        int d = j * 8 + 2 * c;
        os[d * 132 + q0]           = oacc[j][0] * inv0;
        os[(d + 1) * 132 + q0]     = oacc[j][1] * inv0;
        os[d * 132 + q0 + 8]       = oacc[j][2] * inv1;
        os[(d + 1) * 132 + q0 + 8] = oacc[j][3] * inv1;
    }
    __syncthreads();
    const int qbase = blockIdx.x * 128;
    #pragma unroll
    for (int rr = 0; rr < 8; ++rr) {
        int f = tid + rr * 256;
        int t = f & 3, nl = (f >> 2) & 127, ksl = f >> 9;
        int c0 = ksl * 16 + 2 * t;
        uint2 wv;
        wv.x = pack2(os[c0 * 132 + nl],       os[(c0 + 1) * 132 + nl]);
        wv.y = pack2(os[(c0 + 8) * 132 + nl], os[(c0 + 9) * 132 + nl]);
        *(uint2*)(g_atb + ((size_t)b * 32 + h * 4 + ksl) * 8192
                  + (size_t)(qbase + nl) * 8 + t * 2) = wv;
    }
}

// ---------------- launch ----------------
extern "C" void kernel_launch(void* const* d_in, const int* in_sizes, int n_in,
                              void* d_out, int out_size) {
    const float* x      = (const float*)d_in[0];
    const float* gamma  = (const float*)d_in[1];
    const float* beta   = (const float*)d_in[2];
    const float* w_qkv  = (const float*)d_in[3];
    const float* b_qkv  = (const float*)d_in[4];
    const float* w_proj = (const float*)d_in[5];
    const float* b_proj = (const float*)d_in[6];
    float* out = (float*)d_out;

    uint32_t *xb, *atb, *wA, *wP;
    cudaGetSymbolAddress((void**)&xb,  g_xb);
    cudaGetSymbolAddress((void**)&atb, g_atb);
    cudaGetSymbolAddress((void**)&wA,  g_wA);
    cudaGetSymbolAddress((void**)&wP,  g_wP);

    const int gn_smem   = 16 * 1024 * sizeof(float);   // 64 KB
    const int gemm_smem = 16384;                       // 4-stage B pipeline
    const int attn_smem = 12288 * 4;                   // 49152 B
    cudaFuncSetAttribute(gn_kernel, cudaFuncAttributeMaxDynamicSharedMemorySize, gn_smem);
    cudaFuncSetAttribute(attn_mma,  cudaFuncAttributeMaxDynamicSharedMemorySize, attn_smem);

    wprep<<<1536, 256>>>(w_qkv, wA);
    wprep<<<512,  256>>>(w_proj, wP);
    gn_kernel<<<256, 256, gn_smem>>>(x, gamma, beta);
    gemm_mma<<<dim3(8, 12, 8), 256, gemm_smem>>>(wA, xb, b_qkv, nullptr, nullptr, 0, 1);
    attn_mma<<<dim3(8, NH, Bn), 256, attn_smem>>>();
    gemm_mma<<<dim3(8, 4, 8), 256, gemm_smem>>>(wP, atb, b_proj, x, out, Cc, 0);
}

// round 11
// speedup vs baseline: 7.7613x; 1.0573x over previous
#include <cuda_runtime.h>
#include <math_constants.h>
#include <cstdint>

#define Bn 8
#define Cc 512
#define Nn 1024
#define NH 8
#define HD 64

// ---------------- scratch (device globals; no allocation) ----------------
__device__ uint32_t g_xb [Bn * 262144];      // 8 MB  bf16 b-frag (x_norm)
__device__ uint32_t g_atb[Bn * 262144];      // 8 MB  bf16 b-frag (attn out)
__device__ uint32_t g_wA [96 * 32 * 128];    // 1.5 MB a-frag (w_qkv)
__device__ uint32_t g_wP [32 * 32 * 128];    // 0.5 MB a-frag (w_proj)
__device__ uint32_t g_qa [Bn * NH * 32768];  // 8 MB Q a-frag (pre-scaled)
__device__ uint32_t g_kb [Bn * NH * 32768];  // 8 MB K b-frag
__device__ uint32_t g_vb [Bn * NH * 32768];  // 8 MB V b-frag

// ---------------- helpers ----------------
__device__ __forceinline__ uint32_t pack2(float lo, float hi) {
    uint32_t r;
    asm("cvt.rn.bf16x2.f32 %0, %1, %2;" : "=r"(r) : "f"(hi), "f"(lo));
    return r;
}
__device__ __forceinline__ void mma_bf16(float* d, const uint32_t* a, const uint32_t* b) {
    asm volatile(
        "mma.sync.aligned.m16n8k16.row.col.f32.bf16.bf16.f32 "
        "{%0,%1,%2,%3}, {%4,%5,%6,%7}, {%8,%9}, {%0,%1,%2,%3};"
        : "+f"(d[0]), "+f"(d[1]), "+f"(d[2]), "+f"(d[3])
        : "r"(a[0]), "r"(a[1]), "r"(a[2]), "r"(a[3]), "r"(b[0]), "r"(b[1]));
}
__device__ __forceinline__ float fexp2(float t) {
    float r;
    asm("ex2.approx.ftz.f32 %0, %1;" : "=f"(r) : "f"(t));
    return r;
}
__device__ __forceinline__ uint32_t smem_u32(const void* p) {
    uint32_t a;
    asm("{ .reg .u64 t; cvta.to.shared.u64 t, %1; cvt.u32.u64 %0, t; }" : "=r"(a) : "l"(p));
    return a;
}
__device__ __forceinline__ void cp16(uint32_t saddr, const void* g) {
    asm volatile("cp.async.cg.shared.global [%0], [%1], 16;" :: "r"(saddr), "l"(g));
}
#define CP_COMMIT() asm volatile("cp.async.commit_group;")
#define CP_WAIT(n)  asm volatile("cp.async.wait_group %0;" :: "n"(n))

#define QSCL 0.1803368801111204f   /* 0.125 * log2(e) */

// ---------------- weight prep: W[M][512] -> bf16 a-frag words ----------------
__global__ void wprep(const float* __restrict__ W, uint32_t* __restrict__ dst) {
    int e = blockIdx.x * 256 + threadIdx.x;
    int reg = e & 3, lane = (e >> 2) & 31, ks = (e >> 7) & 31, mtile = e >> 12;
    int r = lane >> 2, t = lane & 3;
    int o  = mtile * 16 + r + (reg & 1) * 8;
    int c0 = ks * 16 + 2 * t + (reg & 2) * 4;
    dst[e] = pack2(W[o * 512 + c0], W[o * 512 + c0 + 1]);
}

// ---------------- GroupNorm -> bf16 b-frag layout ----------------
__global__ void gn_kernel(const float* __restrict__ x,
                          const float* __restrict__ gamma,
                          const float* __restrict__ beta) {
    extern __shared__ float sx[];   // [16][1024]
    int b = blockIdx.x >> 5;
    int g = blockIdx.x & 31;
    const float* xp = x + ((size_t)b * Cc + g * 16) * Nn;
    int tid = threadIdx.x;

    float s = 0.f, s2 = 0.f;
    for (int i = tid * 4; i < 16384; i += 1024) {
        float4 v = *(const float4*)(xp + i);
        *(float4*)(sx + i) = v;
        s  += v.x + v.y + v.z + v.w;
        s2 += v.x * v.x + v.y * v.y + v.z * v.z + v.w * v.w;
    }
    for (int off = 16; off; off >>= 1) {
        s  += __shfl_xor_sync(0xffffffffu, s,  off);
        s2 += __shfl_xor_sync(0xffffffffu, s2, off);
    }
    __shared__ float sh[2][8];
    int w = tid >> 5;
    if ((tid & 31) == 0) { sh[0][w] = s; sh[1][w] = s2; }
    __syncthreads();
    if (tid < 32) {
        s  = (tid < 8) ? sh[0][tid] : 0.f;
        s2 = (tid < 8) ? sh[1][tid] : 0.f;
        for (int off = 4; off; off >>= 1) {
            s  += __shfl_xor_sync(0xffffffffu, s,  off);
            s2 += __shfl_xor_sync(0xffffffffu, s2, off);
        }
        if (tid == 0) { sh[0][0] = s; sh[1][0] = s2; }
    }
    __syncthreads();
    float mean = sh[0][0] * (1.f / 16384.f);
    float var  = sh[1][0] * (1.f / 16384.f) - mean * mean;
    float rstd = rsqrtf(var + 1e-5f);

    float ga[16], be[16];
    #pragma unroll
    for (int c = 0; c < 16; ++c) {
        float gg = __ldg(gamma + g * 16 + c) * rstd;
        ga[c] = gg;
        be[c] = __ldg(beta + g * 16 + c) - mean * gg;
    }

    uint32_t* op = g_xb + ((size_t)b * 32 + g) * 8192;
    #pragma unroll
    for (int rr = 0; rr < 4; ++rr) {
        int n = tid + rr * 256;
        float v[16];
        #pragma unroll
        for (int lc = 0; lc < 16; ++lc) v[lc] = sx[lc * 1024 + n] * ga[lc] + be[lc];
        uint4 A = make_uint4(pack2(v[0], v[1]), pack2(v[8],  v[9]),
                             pack2(v[2], v[3]), pack2(v[10], v[11]));
        uint4 B = make_uint4(pack2(v[4], v[5]), pack2(v[12], v[13]),
                             pack2(v[6], v[7]), pack2(v[14], v[15]));
        *(uint4*)(op + (size_t)n * 8)     = A;
        *(uint4*)(op + (size_t)n * 8 + 4) = B;
    }
}

// ---------------- bf16 mma GEMM: 4-stage x 2-kstep cp.async pipeline ----------------
__global__ __launch_bounds__(256, 2) void gemm_mma(
    const uint32_t* __restrict__ Amat, const uint32_t* __restrict__ Bmat,
    const float* __restrict__ bias, const float* __restrict__ resid,
    float* __restrict__ out, int M, int qkvmode)
{
    extern __shared__ uint32_t bsm[];   // 4 stages x 2048 words = 32 KB
    const int tid = threadIdx.x;
    const int lane = tid & 31;
    const int wid = tid >> 5;
    const int wm = wid & 3;
    const int wn = wid >> 2;
    const int nb = blockIdx.x * 128;
    const int ob = blockIdx.y * 128;
    const int b  = blockIdx.z;
    const int r = lane >> 2, c = lane & 3;

    const uint32_t* Aw = Amat + (size_t)((ob >> 4) + wm * 2) * 4096 + lane * 4;
    const uint32_t* Bg = Bmat + (size_t)b * 262144 + (size_t)nb * 8 + tid * 4;
    const uint32_t sb = smem_u32(bsm);
    const uint32_t* bwarp = bsm + wn * 512 + r * 8 + c * 2;

    float acc[2][8][4];
    #pragma unroll
    for (int mt = 0; mt < 2; ++mt)
        #pragma unroll
        for (int nt = 0; nt < 8; ++nt)
            #pragma unroll
            for (int q = 0; q < 4; ++q) acc[mt][nt][q] = 0.f;

    uint4 afr[4][2];
    auto lda = [&](int ks) {
        afr[ks & 3][0] = *(const uint4*)(Aw + ks * 128);
        afr[ks & 3][1] = *(const uint4*)(Aw + 4096 + ks * 128);
    };
    auto bstage = [&](int s) {   // stage s covers k-steps 2s, 2s+1
        uint32_t dst = sb + (((s & 3) << 11) + tid * 4) * 4;
        cp16(dst,                Bg + (size_t)(2 * s) * 8192);
        cp16(dst + 4096,         Bg + (size_t)(2 * s + 1) * 8192);
        CP_COMMIT();
    };

    // prologue: 3 stages in flight, 4 A k-steps loaded
    bstage(0); bstage(1); bstage(2);
    lda(0); lda(1); lda(2); lda(3);
    CP_WAIT(2);
    __syncthreads();

    #pragma unroll 2
    for (int s = 0; s < 16; ++s) {
        #pragma unroll
        for (int kk = 0; kk < 2; ++kk) {
            const int ks = 2 * s + kk;
            uint2 bfr[8];
            #pragma unroll
            for (int nt = 0; nt < 8; ++nt)
                bfr[nt] = *(const uint2*)(bwarp + ((s & 3) << 11) + (kk << 10) + nt * 64);
            #pragma unroll
            for (int mt = 0; mt < 2; ++mt)
                #pragma unroll
                for (int nt = 0; nt < 8; ++nt)
                    mma_bf16(acc[mt][nt], (const uint32_t*)&afr[ks & 3][mt],
                             (const uint32_t*)&bfr[nt]);
            if (s + 2 < 16) lda(2 * s + 4 + kk);
        }
        if (s + 3 < 16) bstage(s + 3);
        else CP_COMMIT();
        CP_WAIT(2);
        __syncthreads();
    }

    if (qkvmode) {
        #pragma unroll
        for (int mt = 0; mt < 2; ++mt) {
            int o0 = ob + wm * 32 + mt * 16 + r;
            float b0 = __ldg(bias + o0);
            float b1 = __ldg(bias + o0 + 8);
            #pragma unroll
            for (int nt = 0; nt < 8; ++nt) {
                int n = nb + wn * 64 + nt * 8 + 2 * c;
                float v0 = acc[mt][nt][0] + b0, v1 = acc[mt][nt][1] + b0;
                float v2 = acc[mt][nt][2] + b1, v3 = acc[mt][nt][3] + b1;
                if (o0 < 1024) {   // Q or K: pairs along d -> butterfly
                    if (o0 < 512) { v0 *= QSCL; v1 *= QSCL; v2 *= QSCL; v3 *= QSCL; }
                    float u0 = __shfl_xor_sync(0xffffffffu, v0, 4);
                    float u1 = __shfl_xor_sync(0xffffffffu, v1, 4);
                    float u2 = __shfl_xor_sync(0xffffffffu, v2, 4);
                    float u3 = __shfl_xor_sync(0xffffffffu, v3, 4);
                    if (!(r & 1)) {
                        uint32_t w0 = pack2(v0, u0), w1 = pack2(v1, u1);
                        uint32_t w2 = pack2(v2, u2), w3 = pack2(v3, u3);
                        if (o0 < 512) {        // Q a-frag
                            int h = o0 >> 6, d0 = o0 & 63, q = n;
                            int qt = q >> 4, q_in = q & 15;
                            int ksd = d0 >> 4, tp = (d0 & 15) >> 1;
                            int lane0 = (q_in & 7) * 4 + tp;
                            int rb = (q_in >> 3) & 1;
                            uint32_t* dst = g_qa
                                + ((size_t)((b * 8 + h) * 64 + qt) * 4 + ksd) * 128;
                            dst[lane0 * 4 + rb]           = w0;
                            dst[(lane0 + 4) * 4 + rb]     = w1;
                            dst[lane0 * 4 + rb + 2]       = w2;
                            dst[(lane0 + 4) * 4 + rb + 2] = w3;
                        } else {               // K b-frag
                            int oh = o0 - 512;
                            int h = oh >> 6, d0 = oh & 63, m = n;
                            int kt = m >> 6, m_in = m & 63;
                            int ksd = d0 >> 4, t = (d0 & 15) >> 1;
                            uint32_t* dst = g_kb
                                + ((size_t)((b * 8 + h) * 16 + kt) * 4 + ksd) * 512;
                            dst[m_in * 8 + t * 2]           = w0;
                            dst[(m_in + 1) * 8 + t * 2]     = w1;
                            dst[m_in * 8 + t * 2 + 1]       = w2;
                            dst[(m_in + 1) * 8 + t * 2 + 1] = w3;
                        }
                    }
                } else {           // V: pairs along m -> in-thread
                    int oh = o0 - 1024;
                    int h = oh >> 6, d = oh & 63, m = n;
                    int kt = m >> 6;
                    int ksm = nt >> 1;
                    int tr = c * 2 + (nt & 1);
                    uint32_t w0 = pack2(v0, v1);
                    uint32_t w1 = pack2(v2, v3);
                    uint32_t* dst = g_vb
                        + ((size_t)((b * 8 + h) * 16 + kt) * 4 + ksm) * 512;
                    dst[d * 8 + tr]       = w0;
                    dst[(d + 8) * 8 + tr] = w1;
                }
            }
        }
    } else {
        #pragma unroll
        for (int mt = 0; mt < 2; ++mt) {
            int o = ob + wm * 32 + mt * 16 + r;
            float b0 = __ldg(bias + o);
            float b1 = __ldg(bias + o + 8);
            #pragma unroll
            for (int nt = 0; nt < 8; ++nt) {
                int n = nb + wn * 64 + nt * 8 + 2 * c;
                size_t i0 = ((size_t)b * M + o) * Nn + n;
                size_t i1 = i0 + (size_t)8 * Nn;
                float2 v0 = make_float2(acc[mt][nt][0] + b0, acc[mt][nt][1] + b0);
                float2 v1 = make_float2(acc[mt][nt][2] + b1, acc[mt][nt][3] + b1);
                if (resid) {
                    float2 r0 = *(const float2*)(resid + i0);
                    float2 r1 = *(const float2*)(resid + i1);
                    v0.x += r0.x; v0.y += r0.y;
                    v1.x += r1.x; v1.y += r1.y;
                }
                *(float2*)(out + i0) = v0;
                *(float2*)(out + i1) = v1;
            }
        }
    }
}

// ---------------- flash attention: P stays in registers, cp.async double-buffered ----------------
// smem words: kbuf[2] @0/@2048, vbuf[2] @4096/@6144; epilogue reuses as 64x132 floats
__global__ __launch_bounds__(256) void attn_mma() {
    const int b = blockIdx.z, h = blockIdx.y;
    const uint32_t* qa = g_qa + (size_t)(b * 8 + h) * 32768;
    const uint32_t* kb = g_kb + (size_t)(b * 8 + h) * 32768;
    const uint32_t* vb = g_vb + (size_t)(b * 8 + h) * 32768;

    extern __shared__ uint32_t smu[];
    const int tid = threadIdx.x, lane = tid & 31, w = tid >> 5;
    const int r = lane >> 2, c = lane & 3;
    const uint32_t sbase = smem_u32(smu);

    uint4 aq[4];
    {
        const uint32_t* qp = qa + (size_t)(blockIdx.x * 8 + w) * 512 + lane * 4;
        #pragma unroll
        for (int ks = 0; ks < 4; ++ks) aq[ks] = *(const uint4*)(qp + ks * 128);
    }

    auto stage = [&](int kt, int buf) {
        const uint32_t* kg = kb + (size_t)kt * 2048 + tid * 8;
        const uint32_t* vg = vb + (size_t)kt * 2048 + tid * 8;
        uint32_t ksm = sbase + (buf * 2048 + tid * 8) * 4;
        uint32_t vsm = sbase + (4096 + buf * 2048 + tid * 8) * 4;
        cp16(ksm,      kg);
        cp16(ksm + 16, kg + 4);
        cp16(vsm,      vg);
        cp16(vsm + 16, vg + 4);
        CP_COMMIT();
    };

    float oacc[8][4];
    #pragma unroll
    for (int j = 0; j < 8; ++j)
        #pragma unroll
        for (int i = 0; i < 4; ++i) oacc[j][i] = 0.f;
    float rm0 = -1e30f, rm1 = -1e30f, rs0 = 0.f, rs1 = 0.f;

    stage(0, 0);
    CP_WAIT(0);
    __syncthreads();

    for (int kt = 0; kt < 16; ++kt) {
        int cur = kt & 1;
        if (kt + 1 < 16) stage(kt + 1, cur ^ 1);

        const uint32_t* ksb = smu + cur * 2048;
        const uint32_t* vsb = smu + 4096 + cur * 2048;

        // S = Q K^T
        float sacc[8][4];
        #pragma unroll
        for (int j = 0; j < 8; ++j)
            #pragma unroll
            for (int i = 0; i < 4; ++i) sacc[j][i] = 0.f;
        #pragma unroll
        for (int ks = 0; ks < 4; ++ks) {
            uint2 bk[8];
            #pragma unroll
            for (int j = 0; j < 8; ++j)
                bk[j] = *(const uint2*)(ksb + ks * 512 + (j * 8 + r) * 8 + c * 2);
            #pragma unroll
            for (int j = 0; j < 8; ++j)
                mma_bf16(sacc[j], (const uint32_t*)&aq[ks], (const uint32_t*)&bk[j]);
        }

        // online softmax (rows r, r+8) — P packed directly into registers
        float tm0 = -1e30f, tm1 = -1e30f;
        #pragma unroll
        for (int j = 0; j < 8; ++j) {
            tm0 = fmaxf(tm0, fmaxf(sacc[j][0], sacc[j][1]));
            tm1 = fmaxf(tm1, fmaxf(sacc[j][2], sacc[j][3]));
        }
        tm0 = fmaxf(tm0, __shfl_xor_sync(0xffffffffu, tm0, 1));
        tm0 = fmaxf(tm0, __shfl_xor_sync(0xffffffffu, tm0, 2));
        tm1 = fmaxf(tm1, __shfl_xor_sync(0xffffffffu, tm1, 1));
        tm1 = fmaxf(tm1, __shfl_xor_sync(0xffffffffu, tm1, 2));
        float nm0 = fmaxf(rm0, tm0), nm1 = fmaxf(rm1, tm1);
        float cr0 = fexp2(rm0 - nm0), cr1 = fexp2(rm1 - nm1);
        rm0 = nm0; rm1 = nm1;
        float ts0 = 0.f, ts1 = 0.f;
        uint4 pa[4];
        #pragma unroll
        for (int t = 0; t < 4; ++t) {
            float e0 = fexp2(sacc[2*t][0] - nm0);
            float e1 = fexp2(sacc[2*t][1] - nm0);
            float e2 = fexp2(sacc[2*t][2] - nm1);
            float e3 = fexp2(sacc[2*t][3] - nm1);
            float f0 = fexp2(sacc[2*t+1][0] - nm0);
            float f1 = fexp2(sacc[2*t+1][1] - nm0);
            float f2 = fexp2(sacc[2*t+1][2] - nm1);
            float f3 = fexp2(sacc[2*t+1][3] - nm1);
            ts0 += e0 + e1 + f0 + f1;
            ts1 += e2 + e3 + f2 + f3;
            pa[t] = make_uint4(pack2(e0, e1), pack2(e2, e3),
                               pack2(f0, f1), pack2(f2, f3));
        }
        #pragma unroll
        for (int j = 0; j < 8; ++j) {
            oacc[j][0] *= cr0; oacc[j][1] *= cr0;
            oacc[j][2] *= cr1; oacc[j][3] *= cr1;
        }
        ts0 += __shfl_xor_sync(0xffffffffu, ts0, 1);
        ts0 += __shfl_xor_sync(0xffffffffu, ts0, 2);
        ts1 += __shfl_xor_sync(0xffffffffu, ts1, 1);
        ts1 += __shfl_xor_sync(0xffffffffu, ts1, 2);
        rs0 = rs0 * cr0 + ts0;
        rs1 = rs1 * cr1 + ts1;

        // O += P V
        #pragma unroll
        for (int ks = 0; ks < 4; ++ks) {
            #pragma unroll
            for (int j = 0; j < 8; ++j) {
                uint2 bv = *(const uint2*)(vsb + ks * 512 + (j * 8 + r) * 8 + c * 2);
                mma_bf16(oacc[j], (const uint32_t*)&pa[ks], (const uint32_t*)&bv);
            }
        }

        if (kt + 1 < 16) CP_WAIT(0);
        __syncthreads();
    }

    // normalize, transpose via smem (stride 132), write bf16 b-frag for proj
    float inv0 = 1.f / rs0, inv1 = 1.f / rs1;
    float* os = (float*)smu;   // 64 x 132 floats = 8448 words
    int q0 = w * 16 + r;
    #pragma unroll
    for (int j = 0; j < 8; ++j) {
        int d = j * 8 + 2 * c;
        os[d * 132 + q0]           = oacc[j][0] * inv0;
        os[(d + 1) * 132 + q0]     = oacc[j][1] * inv0;
        os[d * 132 + q0 + 8]       = oacc[j][2] * inv1;
        os[(d + 1) * 132 + q0 + 8] = oacc[j][3] * inv1;
    }
    __syncthreads();
    const int qbase = blockIdx.x * 128;
    #pragma unroll
    for (int rr = 0; rr < 8; ++rr) {
        int f = tid + rr * 256;
        int t = f & 3, nl = (f >> 2) & 127, ksl = f >> 9;
        int c0 = ksl * 16 + 2 * t;
        uint2 wv;
        wv.x = pack2(os[c0 * 132 + nl],       os[(c0 + 1) * 132 + nl]);
        wv.y = pack2(os[(c0 + 8) * 132 + nl], os[(c0 + 9) * 132 + nl]);
        *(uint2*)(g_atb + ((size_t)b * 32 + h * 4 + ksl) * 8192
                  + (size_t)(qbase + nl) * 8 + t * 2) = wv;
    }
}

// ---------------- launch ----------------
extern "C" void kernel_launch(void* const* d_in, const int* in_sizes, int n_in,
                              void* d_out, int out_size) {
    const float* x      = (const float*)d_in[0];
    const float* gamma  = (const float*)d_in[1];
    const float* beta   = (const float*)d_in[2];
    const float* w_qkv  = (const float*)d_in[3];
    const float* b_qkv  = (const float*)d_in[4];
    const float* w_proj = (const float*)d_in[5];
    const float* b_proj = (const float*)d_in[6];
    float* out = (float*)d_out;

    uint32_t *xb, *atb, *wA, *wP;
    cudaGetSymbolAddress((void**)&xb,  g_xb);
    cudaGetSymbolAddress((void**)&atb, g_atb);
    cudaGetSymbolAddress((void**)&wA,  g_wA);
    cudaGetSymbolAddress((void**)&wP,  g_wP);

    const int gn_smem   = 16 * 1024 * sizeof(float);   // 64 KB
    const int gemm_smem = 32768;                       // 4 stages x 8 KB
    const int attn_smem = 8448 * 4;                    // 33792 B (epilogue transpose)
    cudaFuncSetAttribute(gn_kernel, cudaFuncAttributeMaxDynamicSharedMemorySize, gn_smem);
    cudaFuncSetAttribute(gemm_mma,  cudaFuncAttributeMaxDynamicSharedMemorySize, gemm_smem);
    cudaFuncSetAttribute(attn_mma,  cudaFuncAttributeMaxDynamicSharedMemorySize, attn_smem);

    wprep<<<1536, 256>>>(w_qkv, wA);
    wprep<<<512,  256>>>(w_proj, wP);
    gn_kernel<<<256, 256, gn_smem>>>(x, gamma, beta);
    gemm_mma<<<dim3(8, 12, 8), 256, gemm_smem>>>(wA, xb, b_qkv, nullptr, nullptr, 0, 1);
    attn_mma<<<dim3(8, NH, Bn), 256, attn_smem>>>();
    gemm_mma<<<dim3(8, 4, 8), 256, gemm_smem>>>(wP, atb, b_proj, x, out, Cc, 0);
}

// round 12
// speedup vs baseline: 7.7815x; 1.0026x over previous
#include <cuda_runtime.h>
#include <math_constants.h>
#include <cstdint>

#define Bn 8
#define Cc 512
#define Nn 1024
#define NH 8
#define HD 64

// ---------------- scratch (device globals; no allocation) ----------------
__device__ uint32_t g_xb [Bn * 262144];      // 8 MB  bf16 b-frag (x_norm)
__device__ uint32_t g_atb[Bn * 262144];      // 8 MB  bf16 b-frag (attn out)
__device__ uint32_t g_wA [96 * 32 * 128];    // 1.5 MB a-frag (w_qkv)
__device__ uint32_t g_wP [32 * 32 * 128];    // 0.5 MB a-frag (w_proj)
__device__ uint32_t g_qa [Bn * NH * 32768];  // 8 MB Q a-frag (pre-scaled)
__device__ uint32_t g_kb [Bn * NH * 32768];  // 8 MB K b-frag
__device__ uint32_t g_vb [Bn * NH * 32768];  // 8 MB V b-frag

// ---------------- helpers ----------------
__device__ __forceinline__ uint32_t pack2(float lo, float hi) {
    uint32_t r;
    asm("cvt.rn.bf16x2.f32 %0, %1, %2;" : "=r"(r) : "f"(hi), "f"(lo));
    return r;
}
__device__ __forceinline__ void mma_bf16(float* d, const uint32_t* a, const uint32_t* b) {
    asm volatile(
        "mma.sync.aligned.m16n8k16.row.col.f32.bf16.bf16.f32 "
        "{%0,%1,%2,%3}, {%4,%5,%6,%7}, {%8,%9}, {%0,%1,%2,%3};"
        : "+f"(d[0]), "+f"(d[1]), "+f"(d[2]), "+f"(d[3])
        : "r"(a[0]), "r"(a[1]), "r"(a[2]), "r"(a[3]), "r"(b[0]), "r"(b[1]));
}
__device__ __forceinline__ float fexp2(float t) {
    float r;
    asm("ex2.approx.ftz.f32 %0, %1;" : "=f"(r) : "f"(t));
    return r;
}
__device__ __forceinline__ uint32_t smem_u32(const void* p) {
    uint32_t a;
    asm("{ .reg .u64 t; cvta.to.shared.u64 t, %1; cvt.u32.u64 %0, t; }" : "=r"(a) : "l"(p));
    return a;
}
__device__ __forceinline__ void cp16(uint32_t saddr, const void* g) {
    asm volatile("cp.async.cg.shared.global [%0], [%1], 16;" :: "r"(saddr), "l"(g));
}
#define CP_COMMIT() asm volatile("cp.async.commit_group;")
#define CP_WAIT(n)  asm volatile("cp.async.wait_group %0;" :: "n"(n))

#define QSCL 0.1803368801111204f   /* 0.125 * log2(e) */

// ---------------- merged prep: wprep(w_qkv) + wprep(w_proj) + GroupNorm ----------------
__device__ __forceinline__ void wprep_body(const float* __restrict__ W,
                                           uint32_t* __restrict__ dst, int e) {
    int reg = e & 3, lane = (e >> 2) & 31, ks = (e >> 7) & 31, mtile = e >> 12;
    int r = lane >> 2, t = lane & 3;
    int o  = mtile * 16 + r + (reg & 1) * 8;
    int c0 = ks * 16 + 2 * t + (reg & 2) * 4;
    dst[e] = pack2(W[o * 512 + c0], W[o * 512 + c0 + 1]);
}

__global__ void prep_kernel(const float* __restrict__ w_qkv,
                            const float* __restrict__ w_proj,
                            const float* __restrict__ x,
                            const float* __restrict__ gamma,
                            const float* __restrict__ beta) {
    int blk = blockIdx.x;
    int tid = threadIdx.x;
    if (blk < 1536) { wprep_body(w_qkv, g_wA, blk * 256 + tid); return; }
    if (blk < 2048) { wprep_body(w_proj, g_wP, (blk - 1536) * 256 + tid); return; }

    // ---- GroupNorm block ----
    extern __shared__ float sx[];   // [16][1024]
    int gi = blk - 2048;
    int b = gi >> 5;
    int g = gi & 31;
    const float* xp = x + ((size_t)b * Cc + g * 16) * Nn;

    float s = 0.f, s2 = 0.f;
    for (int i = tid * 4; i < 16384; i += 1024) {
        float4 v = *(const float4*)(xp + i);
        *(float4*)(sx + i) = v;
        s  += v.x + v.y + v.z + v.w;
        s2 += v.x * v.x + v.y * v.y + v.z * v.z + v.w * v.w;
    }
    for (int off = 16; off; off >>= 1) {
        s  += __shfl_xor_sync(0xffffffffu, s,  off);
        s2 += __shfl_xor_sync(0xffffffffu, s2, off);
    }
    __shared__ float sh[2][8];
    int w = tid >> 5;
    if ((tid & 31) == 0) { sh[0][w] = s; sh[1][w] = s2; }
    __syncthreads();
    if (tid < 32) {
        s  = (tid < 8) ? sh[0][tid] : 0.f;
        s2 = (tid < 8) ? sh[1][tid] : 0.f;
        for (int off = 4; off; off >>= 1) {
            s  += __shfl_xor_sync(0xffffffffu, s,  off);
            s2 += __shfl_xor_sync(0xffffffffu, s2, off);
        }
        if (tid == 0) { sh[0][0] = s; sh[1][0] = s2; }
    }
    __syncthreads();
    float mean = sh[0][0] * (1.f / 16384.f);
    float var  = sh[1][0] * (1.f / 16384.f) - mean * mean;
    float rstd = rsqrtf(var + 1e-5f);

    float ga[16], be[16];
    #pragma unroll
    for (int c = 0; c < 16; ++c) {
        float gg = __ldg(gamma + g * 16 + c) * rstd;
        ga[c] = gg;
        be[c] = __ldg(beta + g * 16 + c) - mean * gg;
    }

    uint32_t* op = g_xb + ((size_t)b * 32 + g) * 8192;
    #pragma unroll
    for (int rr = 0; rr < 4; ++rr) {
        int n = tid + rr * 256;
        float v[16];
        #pragma unroll
        for (int lc = 0; lc < 16; ++lc) v[lc] = sx[lc * 1024 + n] * ga[lc] + be[lc];
        uint4 A = make_uint4(pack2(v[0], v[1]), pack2(v[8],  v[9]),
                             pack2(v[2], v[3]), pack2(v[10], v[11]));
        uint4 B = make_uint4(pack2(v[4], v[5]), pack2(v[12], v[13]),
                             pack2(v[6], v[7]), pack2(v[14], v[15]));
        *(uint4*)(op + (size_t)n * 8)     = A;
        *(uint4*)(op + (size_t)n * 8 + 4) = B;
    }
}

// ---------------- bf16 mma GEMM: 4-stage x 2-kstep cp.async pipeline ----------------
__global__ __launch_bounds__(256, 2) void gemm_mma(
    const uint32_t* __restrict__ Amat, const uint32_t* __restrict__ Bmat,
    const float* __restrict__ bias, const float* __restrict__ resid,
    float* __restrict__ out, int M, int qkvmode)
{
    extern __shared__ uint32_t bsm[];   // 4 stages x 2048 words = 32 KB
    const int tid = threadIdx.x;
    const int lane = tid & 31;
    const int wid = tid >> 5;
    const int wm = wid & 3;
    const int wn = wid >> 2;
    const int nb = blockIdx.x * 128;
    const int ob = blockIdx.y * 128;
    const int b  = blockIdx.z;
    const int r = lane >> 2, c = lane & 3;

    const uint32_t* Aw = Amat + (size_t)((ob >> 4) + wm * 2) * 4096 + lane * 4;
    const uint32_t* Bg = Bmat + (size_t)b * 262144 + (size_t)nb * 8 + tid * 4;
    const uint32_t sb = smem_u32(bsm);
    const uint32_t* bwarp = bsm + wn * 512 + r * 8 + c * 2;

    float acc[2][8][4];
    #pragma unroll
    for (int mt = 0; mt < 2; ++mt)
        #pragma unroll
        for (int nt = 0; nt < 8; ++nt)
            #pragma unroll
            for (int q = 0; q < 4; ++q) acc[mt][nt][q] = 0.f;

    uint4 afr[4][2];
    auto lda = [&](int ks) {
        afr[ks & 3][0] = *(const uint4*)(Aw + ks * 128);
        afr[ks & 3][1] = *(const uint4*)(Aw + 4096 + ks * 128);
    };
    auto bstage = [&](int s) {   // stage s covers k-steps 2s, 2s+1
        uint32_t dst = sb + (((s & 3) << 11) + tid * 4) * 4;
        cp16(dst,        Bg + (size_t)(2 * s) * 8192);
        cp16(dst + 4096, Bg + (size_t)(2 * s + 1) * 8192);
        CP_COMMIT();
    };

    bstage(0); bstage(1); bstage(2);
    lda(0); lda(1); lda(2); lda(3);
    CP_WAIT(2);
    __syncthreads();

    #pragma unroll 2
    for (int s = 0; s < 16; ++s) {
        #pragma unroll
        for (int kk = 0; kk < 2; ++kk) {
            const int ks = 2 * s + kk;
            uint2 bfr[8];
            #pragma unroll
            for (int nt = 0; nt < 8; ++nt)
                bfr[nt] = *(const uint2*)(bwarp + ((s & 3) << 11) + (kk << 10) + nt * 64);
            #pragma unroll
            for (int mt = 0; mt < 2; ++mt)
                #pragma unroll
                for (int nt = 0; nt < 8; ++nt)
                    mma_bf16(acc[mt][nt], (const uint32_t*)&afr[ks & 3][mt],
                             (const uint32_t*)&bfr[nt]);
            if (s + 2 < 16) lda(2 * s + 4 + kk);
        }
        if (s + 3 < 16) bstage(s + 3);
        else CP_COMMIT();
        CP_WAIT(2);
        __syncthreads();
    }

    if (qkvmode) {
        #pragma unroll
        for (int mt = 0; mt < 2; ++mt) {
            int o0 = ob + wm * 32 + mt * 16 + r;
            float b0 = __ldg(bias + o0);
            float b1 = __ldg(bias + o0 + 8);
            #pragma unroll
            for (int nt = 0; nt < 8; ++nt) {
                int n = nb + wn * 64 + nt * 8 + 2 * c;
                float v0 = acc[mt][nt][0] + b0, v1 = acc[mt][nt][1] + b0;
                float v2 = acc[mt][nt][2] + b1, v3 = acc[mt][nt][3] + b1;
                if (o0 < 1024) {   // Q or K: pairs along d -> butterfly
                    if (o0 < 512) { v0 *= QSCL; v1 *= QSCL; v2 *= QSCL; v3 *= QSCL; }
                    float u0 = __shfl_xor_sync(0xffffffffu, v0, 4);
                    float u1 = __shfl_xor_sync(0xffffffffu, v1, 4);
                    float u2 = __shfl_xor_sync(0xffffffffu, v2, 4);
                    float u3 = __shfl_xor_sync(0xffffffffu, v3, 4);
                    if (!(r & 1)) {
                        uint32_t w0 = pack2(v0, u0), w1 = pack2(v1, u1);
                        uint32_t w2 = pack2(v2, u2), w3 = pack2(v3, u3);
                        if (o0 < 512) {        // Q a-frag
                            int h = o0 >> 6, d0 = o0 & 63, q = n;
                            int qt = q >> 4, q_in = q & 15;
                            int ksd = d0 >> 4, tp = (d0 & 15) >> 1;
                            int lane0 = (q_in & 7) * 4 + tp;
                            int rb = (q_in >> 3) & 1;
                            uint32_t* dst = g_qa
                                + ((size_t)((b * 8 + h) * 64 + qt) * 4 + ksd) * 128;
                            dst[lane0 * 4 + rb]           = w0;
                            dst[(lane0 + 4) * 4 + rb]     = w1;
                            dst[lane0 * 4 + rb + 2]       = w2;
                            dst[(lane0 + 4) * 4 + rb + 2] = w3;
                        } else {               // K b-frag
                            int oh = o0 - 512;
                            int h = oh >> 6, d0 = oh & 63, m = n;
                            int kt = m >> 6, m_in = m & 63;
                            int ksd = d0 >> 4, t = (d0 & 15) >> 1;
                            uint32_t* dst = g_kb
                                + ((size_t)((b * 8 + h) * 16 + kt) * 4 + ksd) * 512;
                            dst[m_in * 8 + t * 2]           = w0;
                            dst[(m_in + 1) * 8 + t * 2]     = w1;
                            dst[m_in * 8 + t * 2 + 1]       = w2;
                            dst[(m_in + 1) * 8 + t * 2 + 1] = w3;
                        }
                    }
                } else {           // V: pairs along m -> in-thread
                    int oh = o0 - 1024;
                    int h = oh >> 6, d = oh & 63, m = n;
                    int kt = m >> 6;
                    int ksm = nt >> 1;
                    int tr = c * 2 + (nt & 1);
                    uint32_t w0 = pack2(v0, v1);
                    uint32_t w1 = pack2(v2, v3);
                    uint32_t* dst = g_vb
                        + ((size_t)((b * 8 + h) * 16 + kt) * 4 + ksm) * 512;
                    dst[d * 8 + tr]       = w0;
                    dst[(d + 8) * 8 + tr] = w1;
                }
            }
        }
    } else {
        #pragma unroll
        for (int mt = 0; mt < 2; ++mt) {
            int o = ob + wm * 32 + mt * 16 + r;
            float b0 = __ldg(bias + o);
            float b1 = __ldg(bias + o + 8);
            #pragma unroll
            for (int nt = 0; nt < 8; ++nt) {
                int n = nb + wn * 64 + nt * 8 + 2 * c;
                size_t i0 = ((size_t)b * M + o) * Nn + n;
                size_t i1 = i0 + (size_t)8 * Nn;
                float2 v0 = make_float2(acc[mt][nt][0] + b0, acc[mt][nt][1] + b0);
                float2 v1 = make_float2(acc[mt][nt][2] + b1, acc[mt][nt][3] + b1);
                if (resid) {
                    float2 r0 = *(const float2*)(resid + i0);
                    float2 r1 = *(const float2*)(resid + i1);
                    v0.x += r0.x; v0.y += r0.y;
                    v1.x += r1.x; v1.y += r1.y;
                }
                *(float2*)(out + i0) = v0;
                *(float2*)(out + i1) = v1;
            }
        }
    }
}

// ---------------- flash attention: P in registers, 3-stage cp.async ring ----------------
// smem words: kbuf[3] @0..6143, vbuf[3] @6144..12287; epilogue reuses as 64x132 floats
__global__ __launch_bounds__(256) void attn_mma() {
    const int b = blockIdx.z, h = blockIdx.y;
    const uint32_t* qa = g_qa + (size_t)(b * 8 + h) * 32768;
    const uint32_t* kb = g_kb + (size_t)(b * 8 + h) * 32768;
    const uint32_t* vb = g_vb + (size_t)(b * 8 + h) * 32768;

    extern __shared__ uint32_t smu[];
    const int tid = threadIdx.x, lane = tid & 31, w = tid >> 5;
    const int r = lane >> 2, c = lane & 3;
    const uint32_t sbase = smem_u32(smu);

    uint4 aq[4];
    {
        const uint32_t* qp = qa + (size_t)(blockIdx.x * 8 + w) * 512 + lane * 4;
        #pragma unroll
        for (int ks = 0; ks < 4; ++ks) aq[ks] = *(const uint4*)(qp + ks * 128);
    }

    auto stage = [&](int kt) {
        int buf = kt % 3;
        const uint32_t* kg = kb + (size_t)kt * 2048 + tid * 8;
        const uint32_t* vg = vb + (size_t)kt * 2048 + tid * 8;
        uint32_t ksm = sbase + (buf * 2048 + tid * 8) * 4;
        uint32_t vsm = sbase + (6144 + buf * 2048 + tid * 8) * 4;
        cp16(ksm,      kg);
        cp16(ksm + 16, kg + 4);
        cp16(vsm,      vg);
        cp16(vsm + 16, vg + 4);
        CP_COMMIT();
    };

    float oacc[8][4];
    #pragma unroll
    for (int j = 0; j < 8; ++j)
        #pragma unroll
        for (int i = 0; i < 4; ++i) oacc[j][i] = 0.f;
    float rm0 = -1e30f, rm1 = -1e30f, rs0 = 0.f, rs1 = 0.f;

    stage(0);
    stage(1);
    CP_WAIT(1);
    __syncthreads();

    for (int kt = 0; kt < 16; ++kt) {
        if (kt + 2 < 16) stage(kt + 2);

        const uint32_t* ksb = smu + (kt % 3) * 2048;
        const uint32_t* vsb = smu + 6144 + (kt % 3) * 2048;

        // S = Q K^T
        float sacc[8][4];
        #pragma unroll
        for (int j = 0; j < 8; ++j)
            #pragma unroll
            for (int i = 0; i < 4; ++i) sacc[j][i] = 0.f;
        #pragma unroll
        for (int ks = 0; ks < 4; ++ks) {
            uint2 bk[8];
            #pragma unroll
            for (int j = 0; j < 8; ++j)
                bk[j] = *(const uint2*)(ksb + ks * 512 + (j * 8 + r) * 8 + c * 2);
            #pragma unroll
            for (int j = 0; j < 8; ++j)
                mma_bf16(sacc[j], (const uint32_t*)&aq[ks], (const uint32_t*)&bk[j]);
        }

        // online softmax (rows r, r+8) — P packed into registers
        float tm0 = -1e30f, tm1 = -1e30f;
        #pragma unroll
        for (int j = 0; j < 8; ++j) {
            tm0 = fmaxf(tm0, fmaxf(sacc[j][0], sacc[j][1]));
            tm1 = fmaxf(tm1, fmaxf(sacc[j][2], sacc[j][3]));
        }
        tm0 = fmaxf(tm0, __shfl_xor_sync(0xffffffffu, tm0, 1));
        tm0 = fmaxf(tm0, __shfl_xor_sync(0xffffffffu, tm0, 2));
        tm1 = fmaxf(tm1, __shfl_xor_sync(0xffffffffu, tm1, 1));
        tm1 = fmaxf(tm1, __shfl_xor_sync(0xffffffffu, tm1, 2));
        float nm0 = fmaxf(rm0, tm0), nm1 = fmaxf(rm1, tm1);
        float cr0 = fexp2(rm0 - nm0), cr1 = fexp2(rm1 - nm1);
        rm0 = nm0; rm1 = nm1;
        float ts0 = 0.f, ts1 = 0.f;
        uint4 pa[4];
        #pragma unroll
        for (int t = 0; t < 4; ++t) {
            float e0 = fexp2(sacc[2*t][0] - nm0);
            float e1 = fexp2(sacc[2*t][1] - nm0);
            float e2 = fexp2(sacc[2*t][2] - nm1);
            float e3 = fexp2(sacc[2*t][3] - nm1);
            float f0 = fexp2(sacc[2*t+1][0] - nm0);
            float f1 = fexp2(sacc[2*t+1][1] - nm0);
            float f2 = fexp2(sacc[2*t+1][2] - nm1);
            float f3 = fexp2(sacc[2*t+1][3] - nm1);
            ts0 += e0 + e1 + f0 + f1;
            ts1 += e2 + e3 + f2 + f3;
            pa[t] = make_uint4(pack2(e0, e1), pack2(e2, e3),
                               pack2(f0, f1), pack2(f2, f3));
        }
        #pragma unroll
        for (int j = 0; j < 8; ++j) {
            oacc[j][0] *= cr0; oacc[j][1] *= cr0;
            oacc[j][2] *= cr1; oacc[j][3] *= cr1;
        }
        ts0 += __shfl_xor_sync(0xffffffffu, ts0, 1);
        ts0 += __shfl_xor_sync(0xffffffffu, ts0, 2);
        ts1 += __shfl_xor_sync(0xffffffffu, ts1, 1);
        ts1 += __shfl_xor_sync(0xffffffffu, ts1, 2);
        rs0 = rs0 * cr0 + ts0;
        rs1 = rs1 * cr1 + ts1;

        // O += P V
        #pragma unroll
        for (int ks = 0; ks < 4; ++ks) {
            #pragma unroll
            for (int j = 0; j < 8; ++j) {
                uint2 bv = *(const uint2*)(vsb + ks * 512 + (j * 8 + r) * 8 + c * 2);
                mma_bf16(oacc[j], (const uint32_t*)&pa[ks], (const uint32_t*)&bv);
            }
        }

        CP_WAIT(1);
        __syncthreads();
    }

    // normalize, transpose via smem (stride 132), write bf16 b-frag for proj
    float inv0 = 1.f / rs0, inv1 = 1.f / rs1;
    float* os = (float*)smu;   // 64 x 132 floats = 8448 words
    int q0 = w * 16 + r;
    #pragma unroll
    for (int j = 0; j < 8; ++j) {
        int d = j * 8 + 2 * c;
        os[d * 132 + q0]           = oacc[j][0] * inv0;
        os[(d + 1) * 132 + q0]     = oacc[j][1] * inv0;
        os[d * 132 + q0 + 8]       = oacc[j][2] * inv1;
        os[(d + 1) * 132 + q0 + 8] = oacc[j][3] * inv1;
    }
    __syncthreads();
    const int qbase = blockIdx.x * 128;
    #pragma unroll
    for (int rr = 0; rr < 8; ++rr) {
        int f = tid + rr * 256;
        int t = f & 3, nl = (f >> 2) & 127, ksl = f >> 9;
        int c0 = ksl * 16 + 2 * t;
        uint2 wv;
        wv.x = pack2(os[c0 * 132 + nl],       os[(c0 + 1) * 132 + nl]);
        wv.y = pack2(os[(c0 + 8) * 132 + nl], os[(c0 + 9) * 132 + nl]);
        *(uint2*)(g_atb + ((size_t)b * 32 + h * 4 + ksl) * 8192
                  + (size_t)(qbase + nl) * 8 + t * 2) = wv;
    }
}

// ---------------- launch ----------------
extern "C" void kernel_launch(void* const* d_in, const int* in_sizes, int n_in,
                              void* d_out, int out_size) {
    const float* x      = (const float*)d_in[0];
    const float* gamma  = (const float*)d_in[1];
    const float* beta   = (const float*)d_in[2];
    const float* w_qkv  = (const float*)d_in[3];
    const float* b_qkv  = (const float*)d_in[4];
    const float* w_proj = (const float*)d_in[5];
    const float* b_proj = (const float*)d_in[6];
    float* out = (float*)d_out;

    uint32_t *xb, *atb, *wA, *wP;
    cudaGetSymbolAddress((void**)&xb,  g_xb);
    cudaGetSymbolAddress((void**)&atb, g_atb);
    cudaGetSymbolAddress((void**)&wA,  g_wA);
    cudaGetSymbolAddress((void**)&wP,  g_wP);

    const int prep_smem = 16 * 1024 * sizeof(float);   // 64 KB (gn blocks)
    const int gemm_smem = 32768;                       // 4 stages x 8 KB
    const int attn_smem = 12288 * 4;                   // 49152 B (3-stage ring)
    cudaFuncSetAttribute(prep_kernel, cudaFuncAttributeMaxDynamicSharedMemorySize, prep_smem);
    cudaFuncSetAttribute(gemm_mma,    cudaFuncAttributeMaxDynamicSharedMemorySize, gemm_smem);
    cudaFuncSetAttribute(attn_mma,    cudaFuncAttributeMaxDynamicSharedMemorySize, attn_smem);

    prep_kernel<<<2304, 256, prep_smem>>>(w_qkv, w_proj, x, gamma, beta);
    gemm_mma<<<dim3(8, 12, 8), 256, gemm_smem>>>(wA, xb, b_qkv, nullptr, nullptr, 0, 1);
    attn_mma<<<dim3(8, NH, Bn), 256, attn_smem>>>();
    gemm_mma<<<dim3(8, 4, 8), 256, gemm_smem>>>(wP, atb, b_proj, x, out, Cc, 0);
}